// round 1
// baseline (speedup 1.0000x reference)
#include <cuda_runtime.h>
#include <math.h>

// ---- problem dims ----
#define BB 16
#define NCC 1024
#define NTT 2048
#define GAPD 128
#define CTRLD 8
#define RD 256
#define NHD 4
#define HDD 64
#define HIDD 128
#define LHD 192
#define CIN (CTRLD + GAPD)        // 136
#define DIN (2 * RD + GAPD + CTRLD) // 648

// ---- scratch (static device memory; allocation-free at runtime) ----
__device__ float g_comb [BB * NCC * CIN];
__device__ float g_h1   [BB * NCC * HIDD];
__device__ float g_rep  [BB * NCC * RD];
__device__ float g_hle  [BB * NCC * RD];
__device__ float g_hmean[BB * RD];
__device__ float g_z    [BB * RD];
__device__ float g_qkv  [BB * NCC * 3 * RD];
__device__ float g_sc   [(size_t)BB * NHD * NCC * NCC];   // 64M floats
__device__ float g_attno[BB * NCC * RD];
__device__ float g_oproj[BB * NCC * RD];
__device__ float g_rep2 [BB * NCC * RD];
__device__ float g_qt   [BB * NTT * RD];
__device__ float g_cs   [(size_t)BB * NTT * NCC];         // 33.5M floats
__device__ float g_det  [BB * NTT * RD];
__device__ float g_decin[(size_t)BB * NTT * DIN];
__device__ float g_dh   [BB * NTT * HIDD];
__device__ float g_dout [BB * NTT * 2 * CTRLD];

// ===================== generic tiled GEMM =====================
// C[m,n] = act( alpha * sum_k A[m,k] * B'[k,n] + bias[n] )
// TB=true : B is [N,K] row-major (C = A * B^T)
// TB=false: B is [K,N] row-major (C = A * B)
// Batched: z = blockIdx.z, offset = (z/nH)*s?b + (z%nH)*s?h
#define BM 64
#define BN 64
#define BKK 16
#define TM 4
#define TN 4

template<bool TB, int ACT>
__global__ void gemm_k(const float* __restrict__ A, const float* __restrict__ B,
                       const float* __restrict__ bias, float* __restrict__ C,
                       int M, int N, int K, int lda, int ldb, int ldc,
                       long sAb, long sAh, long sBb, long sBh, long sCb, long sCh,
                       int nH, float alpha)
{
    int z = blockIdx.z;
    int bb = z / nH, hh = z - bb * nH;
    A += bb * sAb + hh * sAh;
    B += bb * sBb + hh * sBh;
    C += bb * sCb + hh * sCh;

    __shared__ float As[BKK][BM + 4];
    __shared__ float Bs[BKK][BN + 4];

    int tid = threadIdx.x;           // 0..255
    int tx = tid & 15, ty = tid >> 4;
    int m0 = blockIdx.x * BM;
    int n0 = blockIdx.y * BN;

    float acc[TM][TN];
#pragma unroll
    for (int i = 0; i < TM; i++)
#pragma unroll
        for (int j = 0; j < TN; j++) acc[i][j] = 0.f;

    for (int k0 = 0; k0 < K; k0 += BKK) {
#pragma unroll
        for (int i = 0; i < (BM * BKK) / 256; i++) {
            int idx = tid + i * 256;
            int r = idx / BKK, c = idx % BKK;
            int gm = m0 + r, gk = k0 + c;
            As[c][r] = (gm < M && gk < K) ? A[(long)gm * lda + gk] : 0.f;
        }
#pragma unroll
        for (int i = 0; i < (BN * BKK) / 256; i++) {
            int idx = tid + i * 256;
            if (TB) {
                int r = idx / BKK, c = idx % BKK;   // r = n, c = k
                int gn = n0 + r, gk = k0 + c;
                Bs[c][r] = (gn < N && gk < K) ? B[(long)gn * ldb + gk] : 0.f;
            } else {
                int r = idx / BN, c = idx % BN;     // r = k, c = n
                int gk = k0 + r, gn = n0 + c;
                Bs[r][c] = (gk < K && gn < N) ? B[(long)gk * ldb + gn] : 0.f;
            }
        }
        __syncthreads();
#pragma unroll
        for (int kk = 0; kk < BKK; kk++) {
            float a[TM], b[TN];
#pragma unroll
            for (int i = 0; i < TM; i++) a[i] = As[kk][ty * TM + i];
#pragma unroll
            for (int j = 0; j < TN; j++) b[j] = Bs[kk][tx * TN + j];
#pragma unroll
            for (int i = 0; i < TM; i++)
#pragma unroll
                for (int j = 0; j < TN; j++) acc[i][j] += a[i] * b[j];
        }
        __syncthreads();
    }

#pragma unroll
    for (int i = 0; i < TM; i++) {
        int gm = m0 + ty * TM + i;
        if (gm >= M) continue;
#pragma unroll
        for (int j = 0; j < TN; j++) {
            int gn = n0 + tx * TN + j;
            if (gn >= N) continue;
            float v = acc[i][j] * alpha + (bias ? bias[gn] : 0.f);
            if (ACT == 1) v = fmaxf(v, 0.f);
            C[(long)gm * ldc + gn] = v;
        }
    }
}

// ===================== small kernels =====================

__global__ void concat_ctx_k(const float* __restrict__ cy, const float* __restrict__ cx,
                             float* __restrict__ out)
{
    int idx = blockIdx.x * 256 + threadIdx.x;
    int total = BB * NCC * CIN;
    if (idx >= total) return;
    int row = idx / CIN, c = idx - row * CIN;
    out[idx] = (c < CTRLD) ? cy[row * CTRLD + c] : cx[row * GAPD + (c - CTRLD)];
}

__global__ void mean_k(const float* __restrict__ h, float* __restrict__ out)
{
    int b = blockIdx.x, j = threadIdx.x; // 256 threads
    const float* p = h + (long)b * NCC * RD + j;
    float s = 0.f;
    for (int n = 0; n < NCC; n++) s += p[(long)n * RD];
    out[b * RD + j] = s * (1.f / NCC);
}

__global__ void latent_k(const float* __restrict__ hmean,
                         const float* __restrict__ pw, const float* __restrict__ pb,
                         const float* __restrict__ mw, const float* __restrict__ mb,
                         const float* __restrict__ sw, const float* __restrict__ sb,
                         const float* __restrict__ eps, float* __restrict__ z)
{
    __shared__ float h2[LHD];
    int b = blockIdx.x, tid = threadIdx.x; // 256 threads
    if (tid < LHD) {
        float s = pb[tid];
        const float* hm = hmean + b * RD;
        for (int k = 0; k < RD; k++) s += hm[k] * pw[k * LHD + tid];
        h2[tid] = s;
    }
    __syncthreads();
    float mu = mb[tid], ls = sb[tid];
    for (int k = 0; k < LHD; k++) {
        mu += h2[k] * mw[k * RD + tid];
        ls += h2[k] * sw[k * RD + tid];
    }
    float sig = 0.9f / (1.f + expf(-ls)) + 0.1f;
    z[b * RD + tid] = mu + sig * eps[b * RD + tid];
}

__global__ void softmax_k(float* __restrict__ x, int L)
{
    __shared__ float sh[256];
    long row = blockIdx.x;
    float* p = x + row * (long)L;
    int tid = threadIdx.x;
    float m = -1e30f;
    for (int i = tid; i < L; i += 256) m = fmaxf(m, p[i]);
    sh[tid] = m; __syncthreads();
    for (int s = 128; s; s >>= 1) { if (tid < s) sh[tid] = fmaxf(sh[tid], sh[tid + s]); __syncthreads(); }
    m = sh[0]; __syncthreads();
    float sum = 0.f;
    for (int i = tid; i < L; i += 256) { float e = expf(p[i] - m); p[i] = e; sum += e; }
    sh[tid] = sum; __syncthreads();
    for (int s = 128; s; s >>= 1) { if (tid < s) sh[tid] += sh[tid + s]; __syncthreads(); }
    float inv = 1.f / sh[0];
    for (int i = tid; i < L; i += 256) p[i] *= inv;
}

__global__ void ln_k(const float* __restrict__ x, const float* __restrict__ y,
                     const float* __restrict__ g, const float* __restrict__ b,
                     float* __restrict__ out)
{
    __shared__ float sh[256];
    long row = blockIdx.x; int tid = threadIdx.x; // dim == 256 threads
    float v = x[row * RD + tid] + y[row * RD + tid];
    sh[tid] = v; __syncthreads();
    for (int s = 128; s; s >>= 1) { if (tid < s) sh[tid] += sh[tid + s]; __syncthreads(); }
    float mean = sh[0] * (1.f / RD); __syncthreads();
    float d = v - mean;
    sh[tid] = d * d; __syncthreads();
    for (int s = 128; s; s >>= 1) { if (tid < s) sh[tid] += sh[tid + s]; __syncthreads(); }
    float var = sh[0] * (1.f / RD);
    out[row * RD + tid] = d * rsqrtf(var + 1e-5f) * g[tid] + b[tid];
}

__global__ void concat_dec_k(const float* __restrict__ det, const float* __restrict__ z,
                             const float* __restrict__ tx, const float* __restrict__ pc,
                             float* __restrict__ out)
{
    long idx = (long)blockIdx.x * 256 + threadIdx.x;
    long total = (long)BB * NTT * DIN;
    if (idx >= total) return;
    long row = idx / DIN; int c = (int)(idx - row * DIN);
    int b = (int)(row / NTT);
    float v;
    if (c < RD)            v = det[row * RD + c];
    else if (c < 2 * RD)   v = z[b * RD + (c - RD)];
    else if (c < 2 * RD + GAPD) v = tx[row * GAPD + (c - 2 * RD)];
    else                   v = pc[row * CTRLD + (c - 2 * RD - GAPD)];
    out[idx] = v;
}

__global__ void epi_k(const float* __restrict__ dout, float* __restrict__ out)
{
    int idx = blockIdx.x * 256 + threadIdx.x;
    int total = BB * NTT * CTRLD;
    if (idx >= total) return;
    int row = idx / CTRLD, j = idx - row * CTRLD;
    float mu = dout[row * 2 * CTRLD + j];
    float ls = dout[row * 2 * CTRLD + CTRLD + j];
    float sp = fmaxf(ls, 0.f) + log1pf(expf(-fabsf(ls)));
    out[idx] = mu;
    out[total + idx] = 0.9f * sp + 0.1f;
}

// ===================== host side =====================

static float* sym(const void* s) { void* p = nullptr; cudaGetSymbolAddress(&p, s); return (float*)p; }

static inline dim3 ggrid(int M, int N, int batches) {
    return dim3((M + BM - 1) / BM, (N + BN - 1) / BN, batches);
}

extern "C" void kernel_launch(void* const* d_in, const int* in_sizes, int n_in,
                              void* d_out, int out_size)
{
    const float* context_x   = (const float*)d_in[0];
    const float* context_y   = (const float*)d_in[1];
    const float* target_x    = (const float*)d_in[2];
    const float* pred_ctrl   = (const float*)d_in[3];
    const float* eps         = (const float*)d_in[4];
    const float* ce_w1 = (const float*)d_in[5];  const float* ce_b1 = (const float*)d_in[6];
    const float* ce_w2 = (const float*)d_in[7];  const float* ce_b2 = (const float*)d_in[8];
    const float* sa_in_w = (const float*)d_in[9];  const float* sa_in_b = (const float*)d_in[10];
    const float* sa_out_w = (const float*)d_in[11]; const float* sa_out_b = (const float*)d_in[12];
    const float* sa_ln_g = (const float*)d_in[13];  const float* sa_ln_b = (const float*)d_in[14];
    const float* qp_w = (const float*)d_in[15]; const float* qp_b = (const float*)d_in[16];
    const float* le_w1 = (const float*)d_in[17]; const float* le_b1 = (const float*)d_in[18];
    const float* le_w2 = (const float*)d_in[19]; const float* le_b2 = (const float*)d_in[20];
    const float* le_pw = (const float*)d_in[21]; const float* le_pb = (const float*)d_in[22];
    const float* le_mw = (const float*)d_in[23]; const float* le_mb = (const float*)d_in[24];
    const float* le_sw = (const float*)d_in[25]; const float* le_sb = (const float*)d_in[26];
    const float* dec_w1 = (const float*)d_in[27]; const float* dec_b1 = (const float*)d_in[28];
    const float* dec_w2 = (const float*)d_in[29]; const float* dec_b2 = (const float*)d_in[30];
    float* out = (float*)d_out;

    float* comb  = sym(g_comb);
    float* h1    = sym(g_h1);
    float* rep   = sym(g_rep);
    float* hle   = sym(g_hle);
    float* hmean = sym(g_hmean);
    float* z     = sym(g_z);
    float* qkv   = sym(g_qkv);
    float* sc    = sym(g_sc);
    float* attno = sym(g_attno);
    float* oproj = sym(g_oproj);
    float* rep2  = sym(g_rep2);
    float* qt    = sym(g_qt);
    float* cs    = sym(g_cs);
    float* det   = sym(g_det);
    float* decin = sym(g_decin);
    float* dh    = sym(g_dh);
    float* dout  = sym(g_dout);

    const int MC = BB * NCC;   // 16384
    const int MT = BB * NTT;   // 32768

    // 1. comb_ctx = concat(context_y, context_x)
    concat_ctx_k<<<(BB * NCC * CIN + 255) / 256, 256>>>(context_y, context_x, comb);

    // --- latent path ---
    // hle1 = relu(comb @ le_w1 + le_b1)  (reuse h1)
    gemm_k<false, 1><<<ggrid(MC, HIDD, 1), 256>>>(comb, le_w1, le_b1, h1,
        MC, HIDD, CIN, CIN, HIDD, HIDD, 0, 0, 0, 0, 0, 0, 1, 1.f);
    // hle = hle1 @ le_w2 + le_b2
    gemm_k<false, 0><<<ggrid(MC, RD, 1), 256>>>(h1, le_w2, le_b2, hle,
        MC, RD, HIDD, HIDD, RD, RD, 0, 0, 0, 0, 0, 0, 1, 1.f);
    mean_k<<<BB, 256>>>(hle, hmean);
    latent_k<<<BB, 256>>>(hmean, le_pw, le_pb, le_mw, le_mb, le_sw, le_sb, eps, z);

    // --- deterministic path ---
    gemm_k<false, 1><<<ggrid(MC, HIDD, 1), 256>>>(comb, ce_w1, ce_b1, h1,
        MC, HIDD, CIN, CIN, HIDD, HIDD, 0, 0, 0, 0, 0, 0, 1, 1.f);
    gemm_k<false, 0><<<ggrid(MC, RD, 1), 256>>>(h1, ce_w2, ce_b2, rep,
        MC, RD, HIDD, HIDD, RD, RD, 0, 0, 0, 0, 0, 0, 1, 1.f);

    // self-attention: qkv
    gemm_k<false, 0><<<ggrid(MC, 3 * RD, 1), 256>>>(rep, sa_in_w, sa_in_b, qkv,
        MC, 3 * RD, RD, RD, 3 * RD, 3 * RD, 0, 0, 0, 0, 0, 0, 1, 1.f);

    // scores[b,h] = (1/8) Q K^T ; batches = 64, Q off h*64, K off 256+h*64
    {
        long sQb = (long)NCC * 3 * RD, sQh = HDD;
        long sSb = (long)NHD * NCC * NCC, sSh = (long)NCC * NCC;
        gemm_k<true, 0><<<ggrid(NCC, NCC, BB * NHD), 256>>>(
            qkv, qkv + RD, nullptr, sc,
            NCC, NCC, HDD, 3 * RD, 3 * RD, NCC,
            sQb, sQh, sQb, sQh, sSb, sSh, NHD, 0.125f);
    }
    softmax_k<<<BB * NHD * NCC, 256>>>(sc, NCC);
    // attno[b,n,h*64+d] = P @ V
    {
        long sPb = (long)NHD * NCC * NCC, sPh = (long)NCC * NCC;
        long sVb = (long)NCC * 3 * RD, sVh = HDD;
        long sOb = (long)NCC * RD, sOh = HDD;
        gemm_k<false, 0><<<ggrid(NCC, HDD, BB * NHD), 256>>>(
            sc, qkv + 2 * RD, nullptr, attno,
            NCC, HDD, NCC, NCC, 3 * RD, RD,
            sPb, sPh, sVb, sVh, sOb, sOh, NHD, 1.f);
    }
    // out proj + residual LN
    gemm_k<false, 0><<<ggrid(MC, RD, 1), 256>>>(attno, sa_out_w, sa_out_b, oproj,
        MC, RD, RD, RD, RD, RD, 0, 0, 0, 0, 0, 0, 1, 1.f);
    ln_k<<<MC, 256>>>(rep, oproj, sa_ln_g, sa_ln_b, rep2);

    // cross attention
    gemm_k<false, 0><<<ggrid(MT, RD, 1), 256>>>(target_x, qp_w, qp_b, qt,
        MT, RD, GAPD, GAPD, RD, RD, 0, 0, 0, 0, 0, 0, 1, 1.f);
    gemm_k<true, 0><<<ggrid(NTT, NCC, BB), 256>>>(
        qt, rep2, nullptr, cs,
        NTT, NCC, RD, RD, RD, NCC,
        (long)NTT * RD, 0, (long)NCC * RD, 0, (long)NTT * NCC, 0, 1, 0.0625f);
    softmax_k<<<BB * NTT, 256>>>(cs, NCC);
    gemm_k<false, 0><<<ggrid(NTT, RD, BB), 256>>>(
        cs, rep2, nullptr, det,
        NTT, RD, NCC, NCC, RD, RD,
        (long)NTT * NCC, 0, (long)NCC * RD, 0, (long)NTT * RD, 0, 1, 1.f);

    // decoder
    concat_dec_k<<<(int)(((long)BB * NTT * DIN + 255) / 256), 256>>>(det, z, target_x, pred_ctrl, decin);
    gemm_k<false, 1><<<ggrid(MT, HIDD, 1), 256>>>(decin, dec_w1, dec_b1, dh,
        MT, HIDD, DIN, DIN, HIDD, HIDD, 0, 0, 0, 0, 0, 0, 1, 1.f);
    gemm_k<false, 0><<<ggrid(MT, 2 * CTRLD, 1), 256>>>(dh, dec_w2, dec_b2, dout,
        MT, 2 * CTRLD, HIDD, HIDD, 2 * CTRLD, 2 * CTRLD, 0, 0, 0, 0, 0, 0, 1, 1.f);
    epi_k<<<(BB * NTT * CTRLD + 255) / 256, 256>>>(dout, out);
}

// round 2
// speedup vs baseline: 2.3185x; 2.3185x over previous
#include <cuda_runtime.h>
#include <math.h>

// ---- problem dims ----
#define BB 16
#define NCC 1024
#define NTT 2048
#define GAPD 128
#define CTRLD 8
#define RD 256
#define NHD 4
#define HDD 64
#define HIDD 128
#define LHD 192
#define CIN (CTRLD + GAPD)          // 136
#define DIN (2 * RD + GAPD + CTRLD) // 648

// ---- scratch (static device memory; allocation-free at runtime) ----
__device__ float g_comb [BB * NCC * CIN];
__device__ float g_h1   [BB * NCC * HIDD];
__device__ float g_rep  [BB * NCC * RD];
__device__ float g_hle  [BB * NCC * RD];
__device__ float g_part [BB * 8 * RD];
__device__ float g_hmean[BB * RD];
__device__ float g_z    [BB * RD];
__device__ float g_qkv  [BB * NCC * 3 * RD];
__device__ float g_sc   [(size_t)BB * NHD * NCC * NCC];
__device__ float g_attno[BB * NCC * RD];
__device__ float g_oproj[BB * NCC * RD];
__device__ float g_rep2 [BB * NCC * RD];
__device__ float g_qt   [BB * NTT * RD];
__device__ float g_cs   [(size_t)BB * NTT * NCC];
__device__ float g_det  [BB * NTT * RD];
__device__ float g_decin[(size_t)BB * NTT * DIN];
__device__ float g_dh   [BB * NTT * HIDD];
__device__ float g_dout [BB * NTT * 2 * CTRLD];

// ===================== tf32 tensor-core GEMM =====================
// C[m,n] = act( alpha * sum_k A[m,k]*B'[k,n] + bias[n] )
// TB=true : B is [N,K] row-major (C = A*B^T); TB=false: B is [K,N] row-major.
// Batched via blockIdx.z: off = (z/nH)*s?b + (z%nH)*s?h
#define XBM 128
#define XBN 128
#define XBK 32

__device__ __forceinline__ float to_tf32(float x) {
    float r; asm("cvt.rna.tf32.f32 %0, %1;" : "=f"(r) : "f"(x)); return r;
}

__device__ __forceinline__ void mma8(float* d, const float* a, const float* b) {
    asm volatile(
        "mma.sync.aligned.m16n8k8.row.col.f32.tf32.tf32.f32 "
        "{%0,%1,%2,%3},{%4,%5,%6,%7},{%8,%9},{%0,%1,%2,%3};\n"
        : "+f"(d[0]), "+f"(d[1]), "+f"(d[2]), "+f"(d[3])
        : "r"(__float_as_uint(a[0])), "r"(__float_as_uint(a[1])),
          "r"(__float_as_uint(a[2])), "r"(__float_as_uint(a[3])),
          "r"(__float_as_uint(b[0])), "r"(__float_as_uint(b[1])));
}

template<bool TB, int ACT>
__global__ void __launch_bounds__(256) mma_gemm(
    const float* __restrict__ A, const float* __restrict__ B,
    const float* __restrict__ bias, float* __restrict__ C,
    int M, int N, int K, int lda, int ldb, int ldc,
    long sAb, long sAh, long sBb, long sBh, long sCb, long sCh,
    int nH, float alpha)
{
    int z = blockIdx.z;
    int bb = z / nH, hh = z - bb * nH;
    A += bb * sAb + hh * sAh;
    B += bb * sBb + hh * sBh;
    C += bb * sCb + hh * sCh;

    constexpr int BP = TB ? 9 : 8;
    __shared__ float As[XBM][XBK + 4];   // m-major
    __shared__ float Bs[XBK][XBN + BP];  // k-major

    int tid = threadIdx.x;
    int wid = tid >> 5, lane = tid & 31;
    int g = lane >> 2, t4 = lane & 3;
    int wm = wid & 1, wn = wid >> 1;     // warp grid 2(m) x 4(n), warp tile 64x32
    int m0 = blockIdx.x * XBM, n0 = blockIdx.y * XBN;

    float acc[4][4][4];
#pragma unroll
    for (int i = 0; i < 4; i++)
#pragma unroll
        for (int j = 0; j < 4; j++)
#pragma unroll
            for (int l = 0; l < 4; l++) acc[i][j][l] = 0.f;

    for (int k0 = 0; k0 < K; k0 += XBK) {
        // --- load A tile: [128][32], rows of A row-major ---
        {
            int c = (tid & 7) * 4;
            int gk = k0 + c;
#pragma unroll
            for (int p = 0; p < 4; p++) {
                int r = p * 32 + (tid >> 3);
                const float* src = A + (long)(m0 + r) * lda + gk;
                float4 v;
                if (gk + 4 <= K) v = *(const float4*)src;
                else {
                    v.x = (gk     < K) ? src[0] : 0.f;
                    v.y = (gk + 1 < K) ? src[1] : 0.f;
                    v.z = (gk + 2 < K) ? src[2] : 0.f;
                    v.w = (gk + 3 < K) ? src[3] : 0.f;
                }
                float4 w = make_float4(to_tf32(v.x), to_tf32(v.y), to_tf32(v.z), to_tf32(v.w));
                *(float4*)&As[r][c] = w;
            }
        }
        // --- load B tile -> Bs[k][n] ---
        if (!TB) {
            int gn = n0 + lane * 4;
#pragma unroll
            for (int p = 0; p < 4; p++) {
                int r = p * 8 + wid;
                int gk = k0 + r;
                float4 v = make_float4(0.f, 0.f, 0.f, 0.f);
                if (gk < K && gn + 3 < N)
                    v = *(const float4*)(B + (long)gk * ldb + gn);
                float4 w = make_float4(to_tf32(v.x), to_tf32(v.y), to_tf32(v.z), to_tf32(v.w));
                *(float4*)&Bs[r][lane * 4] = w;
            }
        } else {
            int c = (tid & 7) * 4;
            int gk = k0 + c;
#pragma unroll
            for (int p = 0; p < 4; p++) {
                int r = p * 32 + (tid >> 3);  // n index
                int gn = n0 + r;
                float4 v = make_float4(0.f, 0.f, 0.f, 0.f);
                if (gn < N) {
                    const float* src = B + (long)gn * ldb + gk;
                    if (gk + 4 <= K) v = *(const float4*)src;
                    else {
                        v.x = (gk     < K) ? src[0] : 0.f;
                        v.y = (gk + 1 < K) ? src[1] : 0.f;
                        v.z = (gk + 2 < K) ? src[2] : 0.f;
                        v.w = (gk + 3 < K) ? src[3] : 0.f;
                    }
                }
                Bs[c + 0][r] = to_tf32(v.x);
                Bs[c + 1][r] = to_tf32(v.y);
                Bs[c + 2][r] = to_tf32(v.z);
                Bs[c + 3][r] = to_tf32(v.w);
            }
        }
        __syncthreads();

#pragma unroll
        for (int ks = 0; ks < 4; ks++) {
            int kb = ks * 8;
            float af[4][4], bf[4][2];
#pragma unroll
            for (int mi = 0; mi < 4; mi++) {
                int ma = wm * 64 + mi * 16 + g;
                af[mi][0] = As[ma    ][kb + t4];
                af[mi][1] = As[ma + 8][kb + t4];
                af[mi][2] = As[ma    ][kb + t4 + 4];
                af[mi][3] = As[ma + 8][kb + t4 + 4];
            }
#pragma unroll
            for (int ni = 0; ni < 4; ni++) {
                int nb = wn * 32 + ni * 8 + g;
                bf[ni][0] = Bs[kb + t4    ][nb];
                bf[ni][1] = Bs[kb + t4 + 4][nb];
            }
#pragma unroll
            for (int mi = 0; mi < 4; mi++)
#pragma unroll
                for (int ni = 0; ni < 4; ni++)
                    mma8(acc[mi][ni], af[mi], bf[ni]);
        }
        __syncthreads();
    }

    // --- epilogue ---
#pragma unroll
    for (int mi = 0; mi < 4; mi++) {
        int gm = m0 + wm * 64 + mi * 16 + g;
#pragma unroll
        for (int ni = 0; ni < 4; ni++) {
            int gn = n0 + wn * 32 + ni * 8 + t4 * 2;
            if (gn >= N) continue;
            float b0 = bias ? bias[gn] : 0.f;
            float b1 = bias ? bias[gn + 1] : 0.f;
            float v0 = acc[mi][ni][0] * alpha + b0;
            float v1 = acc[mi][ni][1] * alpha + b1;
            float v2 = acc[mi][ni][2] * alpha + b0;
            float v3 = acc[mi][ni][3] * alpha + b1;
            if (ACT == 1) {
                v0 = fmaxf(v0, 0.f); v1 = fmaxf(v1, 0.f);
                v2 = fmaxf(v2, 0.f); v3 = fmaxf(v3, 0.f);
            }
            *(float2*)&C[(long)gm * ldc + gn]       = make_float2(v0, v1);
            *(float2*)&C[(long)(gm + 8) * ldc + gn] = make_float2(v2, v3);
        }
    }
}

// ===================== SIMT GEMM (kept for tiny-N dec2) =====================
#define BM 64
#define BN 64
#define BKK 16
#define TM 4
#define TN 4

template<bool TB, int ACT>
__global__ void gemm_k(const float* __restrict__ A, const float* __restrict__ B,
                       const float* __restrict__ bias, float* __restrict__ C,
                       int M, int N, int K, int lda, int ldb, int ldc,
                       long sAb, long sAh, long sBb, long sBh, long sCb, long sCh,
                       int nH, float alpha)
{
    int z = blockIdx.z;
    int bb = z / nH, hh = z - bb * nH;
    A += bb * sAb + hh * sAh;
    B += bb * sBb + hh * sBh;
    C += bb * sCb + hh * sCh;

    __shared__ float As[BKK][BM + 4];
    __shared__ float Bs[BKK][BN + 4];

    int tid = threadIdx.x;
    int tx = tid & 15, ty = tid >> 4;
    int m0 = blockIdx.x * BM;
    int n0 = blockIdx.y * BN;

    float acc[TM][TN];
#pragma unroll
    for (int i = 0; i < TM; i++)
#pragma unroll
        for (int j = 0; j < TN; j++) acc[i][j] = 0.f;

    for (int k0 = 0; k0 < K; k0 += BKK) {
#pragma unroll
        for (int i = 0; i < (BM * BKK) / 256; i++) {
            int idx = tid + i * 256;
            int r = idx / BKK, c = idx % BKK;
            int gm = m0 + r, gk = k0 + c;
            As[c][r] = (gm < M && gk < K) ? A[(long)gm * lda + gk] : 0.f;
        }
#pragma unroll
        for (int i = 0; i < (BN * BKK) / 256; i++) {
            int idx = tid + i * 256;
            if (TB) {
                int r = idx / BKK, c = idx % BKK;
                int gn = n0 + r, gk = k0 + c;
                Bs[c][r] = (gn < N && gk < K) ? B[(long)gn * ldb + gk] : 0.f;
            } else {
                int r = idx / BN, c = idx % BN;
                int gk = k0 + r, gn = n0 + c;
                Bs[r][c] = (gk < K && gn < N) ? B[(long)gk * ldb + gn] : 0.f;
            }
        }
        __syncthreads();
#pragma unroll
        for (int kk = 0; kk < BKK; kk++) {
            float a[TM], b[TN];
#pragma unroll
            for (int i = 0; i < TM; i++) a[i] = As[kk][ty * TM + i];
#pragma unroll
            for (int j = 0; j < TN; j++) b[j] = Bs[kk][tx * TN + j];
#pragma unroll
            for (int i = 0; i < TM; i++)
#pragma unroll
                for (int j = 0; j < TN; j++) acc[i][j] += a[i] * b[j];
        }
        __syncthreads();
    }

#pragma unroll
    for (int i = 0; i < TM; i++) {
        int gm = m0 + ty * TM + i;
        if (gm >= M) continue;
#pragma unroll
        for (int j = 0; j < TN; j++) {
            int gn = n0 + tx * TN + j;
            if (gn >= N) continue;
            float v = acc[i][j] * alpha + (bias ? bias[gn] : 0.f);
            if (ACT == 1) v = fmaxf(v, 0.f);
            C[(long)gm * ldc + gn] = v;
        }
    }
}

// ===================== small kernels =====================

__global__ void concat_ctx_k(const float* __restrict__ cy, const float* __restrict__ cx,
                             float* __restrict__ out)
{
    int idx = blockIdx.x * 256 + threadIdx.x;
    int total = BB * NCC * CIN;
    if (idx >= total) return;
    int row = idx / CIN, c = idx - row * CIN;
    out[idx] = (c < CTRLD) ? cy[row * CTRLD + c] : cx[row * GAPD + (c - CTRLD)];
}

__global__ void mean1_k(const float* __restrict__ h, float* __restrict__ part)
{
    int b = blockIdx.x, ch = blockIdx.y, j = threadIdx.x;
    const float* p = h + (long)b * NCC * RD + (long)ch * 128 * RD + j;
    float s = 0.f;
#pragma unroll 4
    for (int n = 0; n < 128; n++) s += p[(long)n * RD];
    part[(b * 8 + ch) * RD + j] = s;
}

__global__ void mean2_k(const float* __restrict__ part, float* __restrict__ out)
{
    int b = blockIdx.x, j = threadIdx.x;
    float s = 0.f;
#pragma unroll
    for (int c = 0; c < 8; c++) s += part[(b * 8 + c) * RD + j];
    out[b * RD + j] = s * (1.f / NCC);
}

__global__ void latent_k(const float* __restrict__ hmean,
                         const float* __restrict__ pw, const float* __restrict__ pb,
                         const float* __restrict__ mw, const float* __restrict__ mb,
                         const float* __restrict__ sw, const float* __restrict__ sb,
                         const float* __restrict__ eps, float* __restrict__ z)
{
    __shared__ float h2[LHD];
    int b = blockIdx.x, tid = threadIdx.x;
    if (tid < LHD) {
        float s = pb[tid];
        const float* hm = hmean + b * RD;
        for (int k = 0; k < RD; k++) s += hm[k] * pw[k * LHD + tid];
        h2[tid] = s;
    }
    __syncthreads();
    float mu = mb[tid], ls = sb[tid];
    for (int k = 0; k < LHD; k++) {
        mu += h2[k] * mw[k * RD + tid];
        ls += h2[k] * sw[k * RD + tid];
    }
    float sig = 0.9f / (1.f + expf(-ls)) + 0.1f;
    z[b * RD + tid] = mu + sig * eps[b * RD + tid];
}

// single-pass register softmax for rows of exactly 1024 floats, 256 threads
__global__ void softmax1024_k(float* __restrict__ x)
{
    __shared__ float sh[8];
    long row = blockIdx.x;
    float4* p = (float4*)(x + row * 1024);
    int tid = threadIdx.x;
    float4 v = p[tid];

    float m = fmaxf(fmaxf(v.x, v.y), fmaxf(v.z, v.w));
#pragma unroll
    for (int o = 16; o; o >>= 1) m = fmaxf(m, __shfl_xor_sync(0xffffffffu, m, o));
    if ((tid & 31) == 0) sh[tid >> 5] = m;
    __syncthreads();
    m = sh[0];
#pragma unroll
    for (int i = 1; i < 8; i++) m = fmaxf(m, sh[i]);
    __syncthreads();

    v.x = __expf(v.x - m); v.y = __expf(v.y - m);
    v.z = __expf(v.z - m); v.w = __expf(v.w - m);
    float s = v.x + v.y + v.z + v.w;
#pragma unroll
    for (int o = 16; o; o >>= 1) s += __shfl_xor_sync(0xffffffffu, s, o);
    if ((tid & 31) == 0) sh[tid >> 5] = s;
    __syncthreads();
    s = sh[0];
#pragma unroll
    for (int i = 1; i < 8; i++) s += sh[i];
    float inv = 1.f / s;
    v.x *= inv; v.y *= inv; v.z *= inv; v.w *= inv;
    p[tid] = v;
}

__global__ void ln_k(const float* __restrict__ x, const float* __restrict__ y,
                     const float* __restrict__ g, const float* __restrict__ b,
                     float* __restrict__ out)
{
    __shared__ float sh[256];
    long row = blockIdx.x; int tid = threadIdx.x;
    float v = x[row * RD + tid] + y[row * RD + tid];
    sh[tid] = v; __syncthreads();
    for (int s = 128; s; s >>= 1) { if (tid < s) sh[tid] += sh[tid + s]; __syncthreads(); }
    float mean = sh[0] * (1.f / RD); __syncthreads();
    float d = v - mean;
    sh[tid] = d * d; __syncthreads();
    for (int s = 128; s; s >>= 1) { if (tid < s) sh[tid] += sh[tid + s]; __syncthreads(); }
    float var = sh[0] * (1.f / RD);
    out[row * RD + tid] = d * rsqrtf(var + 1e-5f) * g[tid] + b[tid];
}

__global__ void concat_dec_k(const float* __restrict__ det, const float* __restrict__ z,
                             const float* __restrict__ tx, const float* __restrict__ pc,
                             float* __restrict__ out)
{
    long idx = (long)blockIdx.x * 256 + threadIdx.x;
    long total = (long)BB * NTT * DIN;
    if (idx >= total) return;
    long row = idx / DIN; int c = (int)(idx - row * DIN);
    int b = (int)(row / NTT);
    float v;
    if (c < RD)                 v = det[row * RD + c];
    else if (c < 2 * RD)        v = z[b * RD + (c - RD)];
    else if (c < 2 * RD + GAPD) v = tx[row * GAPD + (c - 2 * RD)];
    else                        v = pc[row * CTRLD + (c - 2 * RD - GAPD)];
    out[idx] = v;
}

__global__ void epi_k(const float* __restrict__ dout, float* __restrict__ out)
{
    int idx = blockIdx.x * 256 + threadIdx.x;
    int total = BB * NTT * CTRLD;
    if (idx >= total) return;
    int row = idx / CTRLD, j = idx - row * CTRLD;
    float mu = dout[row * 2 * CTRLD + j];
    float ls = dout[row * 2 * CTRLD + CTRLD + j];
    float sp = fmaxf(ls, 0.f) + log1pf(expf(-fabsf(ls)));
    out[idx] = mu;
    out[total + idx] = 0.9f * sp + 0.1f;
}

// ===================== host side =====================

static float* sym(const void* s) { void* p = nullptr; cudaGetSymbolAddress(&p, s); return (float*)p; }

static inline dim3 xgrid(int M, int N, int batches) {
    return dim3((M + XBM - 1) / XBM, (N + XBN - 1) / XBN, batches);
}
static inline dim3 ggrid(int M, int N, int batches) {
    return dim3((M + BM - 1) / BM, (N + BN - 1) / BN, batches);
}

extern "C" void kernel_launch(void* const* d_in, const int* in_sizes, int n_in,
                              void* d_out, int out_size)
{
    const float* context_x   = (const float*)d_in[0];
    const float* context_y   = (const float*)d_in[1];
    const float* target_x    = (const float*)d_in[2];
    const float* pred_ctrl   = (const float*)d_in[3];
    const float* eps         = (const float*)d_in[4];
    const float* ce_w1 = (const float*)d_in[5];  const float* ce_b1 = (const float*)d_in[6];
    const float* ce_w2 = (const float*)d_in[7];  const float* ce_b2 = (const float*)d_in[8];
    const float* sa_in_w = (const float*)d_in[9];  const float* sa_in_b = (const float*)d_in[10];
    const float* sa_out_w = (const float*)d_in[11]; const float* sa_out_b = (const float*)d_in[12];
    const float* sa_ln_g = (const float*)d_in[13];  const float* sa_ln_b = (const float*)d_in[14];
    const float* qp_w = (const float*)d_in[15]; const float* qp_b = (const float*)d_in[16];
    const float* le_w1 = (const float*)d_in[17]; const float* le_b1 = (const float*)d_in[18];
    const float* le_w2 = (const float*)d_in[19]; const float* le_b2 = (const float*)d_in[20];
    const float* le_pw = (const float*)d_in[21]; const float* le_pb = (const float*)d_in[22];
    const float* le_mw = (const float*)d_in[23]; const float* le_mb = (const float*)d_in[24];
    const float* le_sw = (const float*)d_in[25]; const float* le_sb = (const float*)d_in[26];
    const float* dec_w1 = (const float*)d_in[27]; const float* dec_b1 = (const float*)d_in[28];
    const float* dec_w2 = (const float*)d_in[29]; const float* dec_b2 = (const float*)d_in[30];
    float* out = (float*)d_out;

    float* comb  = sym(g_comb);
    float* h1    = sym(g_h1);
    float* rep   = sym(g_rep);
    float* hle   = sym(g_hle);
    float* part  = sym(g_part);
    float* hmean = sym(g_hmean);
    float* z     = sym(g_z);
    float* qkv   = sym(g_qkv);
    float* sc    = sym(g_sc);
    float* attno = sym(g_attno);
    float* oproj = sym(g_oproj);
    float* rep2  = sym(g_rep2);
    float* qt    = sym(g_qt);
    float* cs    = sym(g_cs);
    float* det   = sym(g_det);
    float* decin = sym(g_decin);
    float* dh    = sym(g_dh);
    float* dout  = sym(g_dout);

    const int MC = BB * NCC;   // 16384
    const int MT = BB * NTT;   // 32768

    concat_ctx_k<<<(BB * NCC * CIN + 255) / 256, 256>>>(context_y, context_x, comb);

    // --- latent path ---
    mma_gemm<false, 1><<<xgrid(MC, HIDD, 1), 256>>>(comb, le_w1, le_b1, h1,
        MC, HIDD, CIN, CIN, HIDD, HIDD, 0, 0, 0, 0, 0, 0, 1, 1.f);
    mma_gemm<false, 0><<<xgrid(MC, RD, 1), 256>>>(h1, le_w2, le_b2, hle,
        MC, RD, HIDD, HIDD, RD, RD, 0, 0, 0, 0, 0, 0, 1, 1.f);
    mean1_k<<<dim3(BB, 8), 256>>>(hle, part);
    mean2_k<<<BB, 256>>>(part, hmean);
    latent_k<<<BB, 256>>>(hmean, le_pw, le_pb, le_mw, le_mb, le_sw, le_sb, eps, z);

    // --- deterministic path ---
    mma_gemm<false, 1><<<xgrid(MC, HIDD, 1), 256>>>(comb, ce_w1, ce_b1, h1,
        MC, HIDD, CIN, CIN, HIDD, HIDD, 0, 0, 0, 0, 0, 0, 1, 1.f);
    mma_gemm<false, 0><<<xgrid(MC, RD, 1), 256>>>(h1, ce_w2, ce_b2, rep,
        MC, RD, HIDD, HIDD, RD, RD, 0, 0, 0, 0, 0, 0, 1, 1.f);

    mma_gemm<false, 0><<<xgrid(MC, 3 * RD, 1), 256>>>(rep, sa_in_w, sa_in_b, qkv,
        MC, 3 * RD, RD, RD, 3 * RD, 3 * RD, 0, 0, 0, 0, 0, 0, 1, 1.f);

    {   // self-attn scores: (1/8) Q K^T, batched over (b, h)
        long sQb = (long)NCC * 3 * RD, sQh = HDD;
        long sSb = (long)NHD * NCC * NCC, sSh = (long)NCC * NCC;
        mma_gemm<true, 0><<<xgrid(NCC, NCC, BB * NHD), 256>>>(
            qkv, qkv + RD, nullptr, sc,
            NCC, NCC, HDD, 3 * RD, 3 * RD, NCC,
            sQb, sQh, sQb, sQh, sSb, sSh, NHD, 0.125f);
    }
    softmax1024_k<<<BB * NHD * NCC, 256>>>(sc);
    {   // P @ V
        long sPb = (long)NHD * NCC * NCC, sPh = (long)NCC * NCC;
        long sVb = (long)NCC * 3 * RD, sVh = HDD;
        long sOb = (long)NCC * RD, sOh = HDD;
        mma_gemm<false, 0><<<xgrid(NCC, HDD, BB * NHD), 256>>>(
            sc, qkv + 2 * RD, nullptr, attno,
            NCC, HDD, NCC, NCC, 3 * RD, RD,
            sPb, sPh, sVb, sVh, sOb, sOh, NHD, 1.f);
    }
    mma_gemm<false, 0><<<xgrid(MC, RD, 1), 256>>>(attno, sa_out_w, sa_out_b, oproj,
        MC, RD, RD, RD, RD, RD, 0, 0, 0, 0, 0, 0, 1, 1.f);
    ln_k<<<MC, 256>>>(rep, oproj, sa_ln_g, sa_ln_b, rep2);

    // --- cross attention ---
    mma_gemm<false, 0><<<xgrid(MT, RD, 1), 256>>>(target_x, qp_w, qp_b, qt,
        MT, RD, GAPD, GAPD, RD, RD, 0, 0, 0, 0, 0, 0, 1, 1.f);
    mma_gemm<true, 0><<<xgrid(NTT, NCC, BB), 256>>>(
        qt, rep2, nullptr, cs,
        NTT, NCC, RD, RD, RD, NCC,
        (long)NTT * RD, 0, (long)NCC * RD, 0, (long)NTT * NCC, 0, 1, 0.0625f);
    softmax1024_k<<<BB * NTT, 256>>>(cs);
    mma_gemm<false, 0><<<xgrid(NTT, RD, BB), 256>>>(
        cs, rep2, nullptr, det,
        NTT, RD, NCC, NCC, RD, RD,
        (long)NTT * NCC, 0, (long)NCC * RD, 0, (long)NTT * RD, 0, 1, 1.f);

    // --- decoder ---
    concat_dec_k<<<(int)(((long)BB * NTT * DIN + 255) / 256), 256>>>(det, z, target_x, pred_ctrl, decin);
    mma_gemm<false, 1><<<xgrid(MT, HIDD, 1), 256>>>(decin, dec_w1, dec_b1, dh,
        MT, HIDD, DIN, DIN, HIDD, HIDD, 0, 0, 0, 0, 0, 0, 1, 1.f);
    gemm_k<false, 0><<<ggrid(MT, 2 * CTRLD, 1), 256>>>(dh, dec_w2, dec_b2, dout,
        MT, 2 * CTRLD, HIDD, HIDD, 2 * CTRLD, 2 * CTRLD, 0, 0, 0, 0, 0, 0, 1, 1.f);
    epi_k<<<(BB * NTT * CTRLD + 255) / 256, 256>>>(dout, out);
}

// round 3
// speedup vs baseline: 2.8406x; 1.2252x over previous
#include <cuda_runtime.h>
#include <math.h>

// ---- problem dims ----
#define BB 16
#define NCC 1024
#define NTT 2048
#define GAPD 128
#define CTRLD 8
#define RD 256
#define NHD 4
#define HDD 64
#define HIDD 128
#define LHD 192
#define CIN (CTRLD + GAPD)          // 136
#define DIN (2 * RD + GAPD + CTRLD) // 648

// ---- scratch ----
__device__ float g_comb [BB * NCC * CIN];
__device__ float g_h1   [BB * NCC * HIDD];
__device__ float g_rep  [BB * NCC * RD];
__device__ float g_hle  [BB * NCC * RD];
__device__ float g_part [BB * 32 * RD];
__device__ float g_hmean[BB * RD];
__device__ float g_z    [BB * RD];
__device__ float g_qkv  [BB * NCC * 3 * RD];
__device__ float g_sc   [(size_t)BB * NHD * NCC * NCC];
__device__ float g_attno[BB * NCC * RD];
__device__ float g_oproj[BB * NCC * RD];
__device__ float g_rep2 [BB * NCC * RD];
__device__ float g_qt   [BB * NTT * RD];
__device__ float g_cs   [(size_t)BB * NTT * NCC];
__device__ float g_det  [BB * NTT * RD];
__device__ float g_dh   [BB * NTT * HIDD];

// ===================== tf32 tensor-core GEMM (reg-pipelined) =====================
#define XBM 128
#define XBK 32

__device__ __forceinline__ float to_tf32(float x) {
    float r; asm("cvt.rna.tf32.f32 %0, %1;" : "=f"(r) : "f"(x)); return r;
}
__device__ __forceinline__ float4 cvt4(float4 v) {
    return make_float4(to_tf32(v.x), to_tf32(v.y), to_tf32(v.z), to_tf32(v.w));
}
__device__ __forceinline__ void mma8(float* d, const float* a, const float* b) {
    asm volatile(
        "mma.sync.aligned.m16n8k8.row.col.f32.tf32.tf32.f32 "
        "{%0,%1,%2,%3},{%4,%5,%6,%7},{%8,%9},{%0,%1,%2,%3};\n"
        : "+f"(d[0]), "+f"(d[1]), "+f"(d[2]), "+f"(d[3])
        : "r"(__float_as_uint(a[0])), "r"(__float_as_uint(a[1])),
          "r"(__float_as_uint(a[2])), "r"(__float_as_uint(a[3])),
          "r"(__float_as_uint(b[0])), "r"(__float_as_uint(b[1])));
}

__device__ __forceinline__ float4 ld_guard(const float* src, int gk, int K) {
    if (gk + 4 <= K) return *(const float4*)src;
    float4 v = make_float4(0.f, 0.f, 0.f, 0.f);
    if (gk     < K) v.x = src[0];
    if (gk + 1 < K) v.y = src[1];
    if (gk + 2 < K) v.z = src[2];
    if (gk + 3 < K) v.w = src[3];
    return v;
}

// TB=true : B is [N,K] row-major (C = A*B^T) — requires WNT==32 (XBN=128)
// TB=false: B is [K,N] row-major.
// WNT: warp n-tile (16 or 32) -> block N = 4*WNT.
// DEC: A gathered from [det | z(bcast) | tx | pc] with K=DIN.
template<bool TB, int WNT, int ACT, bool DEC>
__global__ void __launch_bounds__(256) mma_gemm(
    const float* __restrict__ A, const float* __restrict__ B,
    const float* __restrict__ bias, float* __restrict__ C,
    int M, int N, int K, int lda, int ldb, int ldc,
    long sAb, long sAh, long sBb, long sBh, long sCb, long sCh,
    int nH, float alpha,
    const float* __restrict__ zt, const float* __restrict__ txt,
    const float* __restrict__ pct)
{
    constexpr int XBN_ = WNT * 4;
    constexpr int NI = WNT / 8;
    constexpr int AST = XBK + 4;                 // 36
    constexpr int BST = XBN_ + (TB ? 9 : 8);

    int z = blockIdx.z;
    int bb = z / nH, hh = z - bb * nH;
    A += bb * sAb + hh * sAh;
    B += bb * sBb + hh * sBh;
    C += bb * sCb + hh * sCh;

    __shared__ float As[XBM][AST];
    __shared__ float Bs[XBK][BST];

    int tid = threadIdx.x;
    int wid = tid >> 5, lane = tid & 31;
    int g = lane >> 2, t4 = lane & 3;
    int wm = wid & 1, wn = wid >> 1;             // 2(m) x 4(n) warps
    int m0 = blockIdx.x * XBM, n0 = blockIdx.y * XBN_;

    float acc[4][NI][4];
#pragma unroll
    for (int i = 0; i < 4; i++)
#pragma unroll
        for (int j = 0; j < NI; j++)
#pragma unroll
            for (int l = 0; l < 4; l++) acc[i][j][l] = 0.f;

    // ---- register staging ----
    float4 ra[4], rb[4];
    constexpr int C4  = XBN_ / 4;        // float4 cols in B tile (!TB)
    constexpr int RPI = 256 / C4;        // rows per 256-thread pass
    constexpr int ITS = TB ? 4 : (XBK / RPI);

    const int ac = (tid & 7) * 4;        // A k-chunk
    const int ar = tid >> 3;             // A row base (0..31)
    const int bc4 = tid % C4;            // !TB col
    const int brb = tid / C4;            // !TB row base

    auto loadA = [&](int k0) {
        int gk = k0 + ac;
#pragma unroll
        for (int p = 0; p < 4; p++) {
            int gm = m0 + p * 32 + ar;
            if (DEC) {
                const float* s;
                if (gk < RD)                 s = A   + (long)gm * RD   + gk;
                else if (gk < 2 * RD)        s = zt  + (long)(gm >> 11) * RD + (gk - RD);
                else if (gk < 2 * RD + GAPD) s = txt + (long)gm * GAPD + (gk - 2 * RD);
                else if (gk < DIN)           s = pct + (long)gm * CTRLD + (gk - 2 * RD - GAPD);
                else                         s = nullptr;
                ra[p] = s ? *(const float4*)s : make_float4(0.f, 0.f, 0.f, 0.f);
            } else {
                ra[p] = ld_guard(A + (long)gm * lda + gk, gk, K);
            }
        }
    };
    auto loadB = [&](int k0) {
        if (TB) {
            int gk = k0 + ac;
#pragma unroll
            for (int p = 0; p < 4; p++) {
                int gn = n0 + p * 32 + ar;
                rb[p] = (gn < N) ? ld_guard(B + (long)gn * ldb + gk, gk, K)
                                 : make_float4(0.f, 0.f, 0.f, 0.f);
            }
        } else {
            int gn = n0 + bc4 * 4;
#pragma unroll
            for (int it = 0; it < ITS; it++) {
                int gk = k0 + it * RPI + brb;
                rb[it] = (gk < K && gn + 3 < N) ? *(const float4*)(B + (long)gk * ldb + gn)
                                                : make_float4(0.f, 0.f, 0.f, 0.f);
            }
        }
    };
    auto stsAB = [&]() {
#pragma unroll
        for (int p = 0; p < 4; p++)
            *(float4*)&As[p * 32 + ar][ac] = cvt4(ra[p]);
        if (TB) {
#pragma unroll
            for (int p = 0; p < 4; p++) {
                int r = p * 32 + ar;
                float4 w = cvt4(rb[p]);
                Bs[ac + 0][r] = w.x; Bs[ac + 1][r] = w.y;
                Bs[ac + 2][r] = w.z; Bs[ac + 3][r] = w.w;
            }
        } else {
#pragma unroll
            for (int it = 0; it < ITS; it++)
                *(float4*)&Bs[it * RPI + brb][bc4 * 4] = cvt4(rb[it]);
        }
    };

    int kT = (K + XBK - 1) / XBK;
    loadA(0); loadB(0);

    for (int t = 0; t < kT; t++) {
        stsAB();
        __syncthreads();
        if (t + 1 < kT) { loadA((t + 1) * XBK); loadB((t + 1) * XBK); }
#pragma unroll
        for (int ks = 0; ks < 4; ks++) {
            int kb = ks * 8;
            float af[4][4], bf[NI][2];
#pragma unroll
            for (int mi = 0; mi < 4; mi++) {
                int ma = wm * 64 + mi * 16 + g;
                af[mi][0] = As[ma    ][kb + t4];
                af[mi][1] = As[ma + 8][kb + t4];
                af[mi][2] = As[ma    ][kb + t4 + 4];
                af[mi][3] = As[ma + 8][kb + t4 + 4];
            }
#pragma unroll
            for (int ni = 0; ni < NI; ni++) {
                int nb = wn * WNT + ni * 8 + g;
                bf[ni][0] = Bs[kb + t4    ][nb];
                bf[ni][1] = Bs[kb + t4 + 4][nb];
            }
#pragma unroll
            for (int mi = 0; mi < 4; mi++)
#pragma unroll
                for (int ni = 0; ni < NI; ni++)
                    mma8(acc[mi][ni], af[mi], bf[ni]);
        }
        __syncthreads();
    }

#pragma unroll
    for (int mi = 0; mi < 4; mi++) {
        int gm = m0 + wm * 64 + mi * 16 + g;
#pragma unroll
        for (int ni = 0; ni < NI; ni++) {
            int gn = n0 + wn * WNT + ni * 8 + t4 * 2;
            if (gn >= N) continue;
            float b0 = bias ? bias[gn] : 0.f;
            float b1 = bias ? bias[gn + 1] : 0.f;
            float v0 = acc[mi][ni][0] * alpha + b0;
            float v1 = acc[mi][ni][1] * alpha + b1;
            float v2 = acc[mi][ni][2] * alpha + b0;
            float v3 = acc[mi][ni][3] * alpha + b1;
            if (ACT == 1) {
                v0 = fmaxf(v0, 0.f); v1 = fmaxf(v1, 0.f);
                v2 = fmaxf(v2, 0.f); v3 = fmaxf(v3, 0.f);
            }
            *(float2*)&C[(long)gm * ldc + gn]       = make_float2(v0, v1);
            *(float2*)&C[(long)(gm + 8) * ldc + gn] = make_float2(v2, v3);
        }
    }
}

// ===================== small kernels =====================

__global__ void concat_ctx_k(const float* __restrict__ cy, const float* __restrict__ cx,
                             float* __restrict__ out)
{
    int idx = blockIdx.x * 256 + threadIdx.x;
    int total = BB * NCC * CIN;
    if (idx >= total) return;
    int row = idx / CIN, c = idx - row * CIN;
    out[idx] = (c < CTRLD) ? cy[row * CTRLD + c] : cx[row * GAPD + (c - CTRLD)];
}

__global__ void mean1_k(const float* __restrict__ h, float* __restrict__ part)
{
    int b = blockIdx.x, ch = blockIdx.y, j = threadIdx.x * 4; // 64 threads
    const float* p = h + (long)b * NCC * RD + (long)ch * 32 * RD + j;
    float4 s = make_float4(0.f, 0.f, 0.f, 0.f);
#pragma unroll 4
    for (int n = 0; n < 32; n++) {
        float4 v = *(const float4*)(p + (long)n * RD);
        s.x += v.x; s.y += v.y; s.z += v.z; s.w += v.w;
    }
    *(float4*)&part[(long)(b * 32 + ch) * RD + j] = s;
}

__global__ void mean2_k(const float* __restrict__ part, float* __restrict__ out)
{
    int b = blockIdx.x, j = threadIdx.x;
    float s = 0.f;
#pragma unroll
    for (int c = 0; c < 32; c++) s += part[(long)(b * 32 + c) * RD + j];
    out[b * RD + j] = s * (1.f / NCC);
}

__global__ void latent_k(const float* __restrict__ hmean,
                         const float* __restrict__ pw, const float* __restrict__ pb,
                         const float* __restrict__ mw, const float* __restrict__ mb,
                         const float* __restrict__ sw, const float* __restrict__ sb,
                         const float* __restrict__ eps, float* __restrict__ z)
{
    __shared__ float h2[LHD];
    int b = blockIdx.x, tid = threadIdx.x;
    if (tid < LHD) {
        float s = pb[tid];
        const float* hm = hmean + b * RD;
        for (int k = 0; k < RD; k++) s += hm[k] * pw[k * LHD + tid];
        h2[tid] = s;
    }
    __syncthreads();
    float mu = mb[tid], ls = sb[tid];
    for (int k = 0; k < LHD; k++) {
        mu += h2[k] * mw[k * RD + tid];
        ls += h2[k] * sw[k * RD + tid];
    }
    float sig = 0.9f / (1.f + expf(-ls)) + 0.1f;
    z[b * RD + tid] = mu + sig * eps[b * RD + tid];
}

// single-pass register softmax for rows of exactly 1024 floats, 256 threads
__global__ void softmax1024_k(float* __restrict__ x)
{
    __shared__ float sh[8];
    long row = blockIdx.x;
    float4* p = (float4*)(x + row * 1024);
    int tid = threadIdx.x;
    float4 v = p[tid];

    float m = fmaxf(fmaxf(v.x, v.y), fmaxf(v.z, v.w));
#pragma unroll
    for (int o = 16; o; o >>= 1) m = fmaxf(m, __shfl_xor_sync(0xffffffffu, m, o));
    if ((tid & 31) == 0) sh[tid >> 5] = m;
    __syncthreads();
    m = sh[0];
#pragma unroll
    for (int i = 1; i < 8; i++) m = fmaxf(m, sh[i]);
    __syncthreads();

    v.x = __expf(v.x - m); v.y = __expf(v.y - m);
    v.z = __expf(v.z - m); v.w = __expf(v.w - m);
    float s = v.x + v.y + v.z + v.w;
#pragma unroll
    for (int o = 16; o; o >>= 1) s += __shfl_xor_sync(0xffffffffu, s, o);
    if ((tid & 31) == 0) sh[tid >> 5] = s;
    __syncthreads();
    s = sh[0];
#pragma unroll
    for (int i = 1; i < 8; i++) s += sh[i];
    float inv = 1.f / s;
    v.x *= inv; v.y *= inv; v.z *= inv; v.w *= inv;
    p[tid] = v;
}

__global__ void ln_k(const float* __restrict__ x, const float* __restrict__ y,
                     const float* __restrict__ g, const float* __restrict__ b,
                     float* __restrict__ out)
{
    __shared__ float sh[256];
    long row = blockIdx.x; int tid = threadIdx.x;
    float v = x[row * RD + tid] + y[row * RD + tid];
    sh[tid] = v; __syncthreads();
    for (int s = 128; s; s >>= 1) { if (tid < s) sh[tid] += sh[tid + s]; __syncthreads(); }
    float mean = sh[0] * (1.f / RD); __syncthreads();
    float d = v - mean;
    sh[tid] = d * d; __syncthreads();
    for (int s = 128; s; s >>= 1) { if (tid < s) sh[tid] += sh[tid + s]; __syncthreads(); }
    float var = sh[0] * (1.f / RD);
    out[row * RD + tid] = d * rsqrtf(var + 1e-5f) * g[tid] + b[tid];
}

// dec2 (K=128, N=16) fused with mu/sigma epilogue, writes final out
__global__ void __launch_bounds__(256) dec2_k(
    const float* __restrict__ dh, const float* __restrict__ w2,
    const float* __restrict__ b2, float* __restrict__ out)
{
    __shared__ float w[128][17];
    __shared__ float a[16][132];
    int tid = threadIdx.x;
    for (int i = tid; i < 128 * 16; i += 256) { int k = i >> 4, c = i & 15; w[k][c] = w2[i]; }
    long row0 = (long)blockIdx.x * 16;
    for (int i = tid; i < 512; i += 256) {
        int r = i >> 5, c4 = (i & 31) * 4;
        *(float4*)&a[r][c4] = *(const float4*)&dh[(row0 + r) * 128 + c4];
    }
    __syncthreads();
    int r = tid >> 4, c = tid & 15;
    float s = b2[c];
#pragma unroll
    for (int k = 0; k < 128; k++) s += a[r][k] * w[k][c];
    long row = row0 + r;
    const long TOT = (long)BB * NTT * CTRLD;
    if (c < CTRLD) out[row * CTRLD + c] = s;
    else {
        float sp = fmaxf(s, 0.f) + log1pf(expf(-fabsf(s)));
        out[TOT + row * CTRLD + (c - CTRLD)] = 0.9f * sp + 0.1f;
    }
}

// ===================== host side =====================

static float* sym(const void* s) { void* p = nullptr; cudaGetSymbolAddress(&p, s); return (float*)p; }

extern "C" void kernel_launch(void* const* d_in, const int* in_sizes, int n_in,
                              void* d_out, int out_size)
{
    const float* context_x = (const float*)d_in[0];
    const float* context_y = (const float*)d_in[1];
    const float* target_x  = (const float*)d_in[2];
    const float* pred_ctrl = (const float*)d_in[3];
    const float* eps       = (const float*)d_in[4];
    const float* ce_w1 = (const float*)d_in[5];  const float* ce_b1 = (const float*)d_in[6];
    const float* ce_w2 = (const float*)d_in[7];  const float* ce_b2 = (const float*)d_in[8];
    const float* sa_in_w = (const float*)d_in[9];  const float* sa_in_b = (const float*)d_in[10];
    const float* sa_out_w = (const float*)d_in[11]; const float* sa_out_b = (const float*)d_in[12];
    const float* sa_ln_g = (const float*)d_in[13];  const float* sa_ln_b = (const float*)d_in[14];
    const float* qp_w = (const float*)d_in[15]; const float* qp_b = (const float*)d_in[16];
    const float* le_w1 = (const float*)d_in[17]; const float* le_b1 = (const float*)d_in[18];
    const float* le_w2 = (const float*)d_in[19]; const float* le_b2 = (const float*)d_in[20];
    const float* le_pw = (const float*)d_in[21]; const float* le_pb = (const float*)d_in[22];
    const float* le_mw = (const float*)d_in[23]; const float* le_mb = (const float*)d_in[24];
    const float* le_sw = (const float*)d_in[25]; const float* le_sb = (const float*)d_in[26];
    const float* dec_w1 = (const float*)d_in[27]; const float* dec_b1 = (const float*)d_in[28];
    const float* dec_w2 = (const float*)d_in[29]; const float* dec_b2 = (const float*)d_in[30];
    float* out = (float*)d_out;

    float* comb  = sym(g_comb);
    float* h1    = sym(g_h1);
    float* rep   = sym(g_rep);
    float* hle   = sym(g_hle);
    float* part  = sym(g_part);
    float* hmean = sym(g_hmean);
    float* z     = sym(g_z);
    float* qkv   = sym(g_qkv);
    float* sc    = sym(g_sc);
    float* attno = sym(g_attno);
    float* oproj = sym(g_oproj);
    float* rep2  = sym(g_rep2);
    float* qt    = sym(g_qt);
    float* cs    = sym(g_cs);
    float* det   = sym(g_det);
    float* dh    = sym(g_dh);

    const int MC = BB * NCC;   // 16384
    const int MT = BB * NTT;   // 32768

    concat_ctx_k<<<(BB * NCC * CIN + 255) / 256, 256>>>(context_y, context_x, comb);

    // --- latent path ---
    mma_gemm<false, 32, 1, false><<<dim3(MC / 128, 1, 1), 256>>>(comb, le_w1, le_b1, h1,
        MC, HIDD, CIN, CIN, HIDD, HIDD, 0, 0, 0, 0, 0, 0, 1, 1.f, 0, 0, 0);
    mma_gemm<false, 32, 0, false><<<dim3(MC / 128, 2, 1), 256>>>(h1, le_w2, le_b2, hle,
        MC, RD, HIDD, HIDD, RD, RD, 0, 0, 0, 0, 0, 0, 1, 1.f, 0, 0, 0);
    mean1_k<<<dim3(BB, 32), 64>>>(hle, part);
    mean2_k<<<BB, 256>>>(part, hmean);
    latent_k<<<BB, 256>>>(hmean, le_pw, le_pb, le_mw, le_mb, le_sw, le_sb, eps, z);

    // --- deterministic path ---
    mma_gemm<false, 32, 1, false><<<dim3(MC / 128, 1, 1), 256>>>(comb, ce_w1, ce_b1, h1,
        MC, HIDD, CIN, CIN, HIDD, HIDD, 0, 0, 0, 0, 0, 0, 1, 1.f, 0, 0, 0);
    mma_gemm<false, 32, 0, false><<<dim3(MC / 128, 2, 1), 256>>>(h1, ce_w2, ce_b2, rep,
        MC, RD, HIDD, HIDD, RD, RD, 0, 0, 0, 0, 0, 0, 1, 1.f, 0, 0, 0);

    mma_gemm<false, 32, 0, false><<<dim3(MC / 128, 6, 1), 256>>>(rep, sa_in_w, sa_in_b, qkv,
        MC, 3 * RD, RD, RD, 3 * RD, 3 * RD, 0, 0, 0, 0, 0, 0, 1, 1.f, 0, 0, 0);

    {   // self-attn scores: (1/8) Q K^T, batched over (b, h)
        long sQb = (long)NCC * 3 * RD, sQh = HDD;
        long sSb = (long)NHD * NCC * NCC, sSh = (long)NCC * NCC;
        mma_gemm<true, 32, 0, false><<<dim3(NCC / 128, NCC / 128, BB * NHD), 256>>>(
            qkv, qkv + RD, nullptr, sc,
            NCC, NCC, HDD, 3 * RD, 3 * RD, NCC,
            sQb, sQh, sQb, sQh, sSb, sSh, NHD, 0.125f, 0, 0, 0);
    }
    softmax1024_k<<<BB * NHD * NCC, 256>>>(sc);
    {   // P @ V   (N=64 -> 128x64 tiles)
        long sPb = (long)NHD * NCC * NCC, sPh = (long)NCC * NCC;
        long sVb = (long)NCC * 3 * RD, sVh = HDD;
        long sOb = (long)NCC * RD, sOh = HDD;
        mma_gemm<false, 16, 0, false><<<dim3(NCC / 128, 1, BB * NHD), 256>>>(
            sc, qkv + 2 * RD, nullptr, attno,
            NCC, HDD, NCC, NCC, 3 * RD, RD,
            sPb, sPh, sVb, sVh, sOb, sOh, NHD, 1.f, 0, 0, 0);
    }
    mma_gemm<false, 32, 0, false><<<dim3(MC / 128, 2, 1), 256>>>(attno, sa_out_w, sa_out_b, oproj,
        MC, RD, RD, RD, RD, RD, 0, 0, 0, 0, 0, 0, 1, 1.f, 0, 0, 0);
    ln_k<<<MC, 256>>>(rep, oproj, sa_ln_g, sa_ln_b, rep2);

    // --- cross attention ---
    mma_gemm<false, 32, 0, false><<<dim3(MT / 128, 2, 1), 256>>>(target_x, qp_w, qp_b, qt,
        MT, RD, GAPD, GAPD, RD, RD, 0, 0, 0, 0, 0, 0, 1, 1.f, 0, 0, 0);
    mma_gemm<true, 32, 0, false><<<dim3(NTT / 128, NCC / 128, BB), 256>>>(
        qt, rep2, nullptr, cs,
        NTT, NCC, RD, RD, RD, NCC,
        (long)NTT * RD, 0, (long)NCC * RD, 0, (long)NTT * NCC, 0, 1, 0.0625f, 0, 0, 0);
    softmax1024_k<<<BB * NTT, 256>>>(cs);
    mma_gemm<false, 32, 0, false><<<dim3(NTT / 128, 2, BB), 256>>>(
        cs, rep2, nullptr, det,
        NTT, RD, NCC, NCC, RD, RD,
        (long)NTT * NCC, 0, (long)NCC * RD, 0, (long)NTT * RD, 0, 1, 1.f, 0, 0, 0);

    // --- decoder: dec1 gathers A from [det | z | target_x | pred_control] ---
    mma_gemm<false, 32, 1, true><<<dim3(MT / 128, 1, 1), 256>>>(det, dec_w1, dec_b1, dh,
        MT, HIDD, DIN, DIN, HIDD, HIDD, 0, 0, 0, 0, 0, 0, 1, 1.f,
        z, target_x, pred_ctrl);
    dec2_k<<<MT / 16, 256>>>(dh, dec_w2, dec_b2, out);
}

// round 4
// speedup vs baseline: 3.5447x; 1.2479x over previous
#include <cuda_runtime.h>
#include <math.h>

// ---- problem dims ----
#define BB 16
#define NCC 1024
#define NTT 2048
#define GAPD 128
#define CTRLD 8
#define RD 256
#define NHD 4
#define HDD 64
#define HIDD 128
#define LHD 192
#define CIN (CTRLD + GAPD)          // 136
#define DIN (2 * RD + GAPD + CTRLD) // 648

// ---- scratch ----
__device__ float g_comb [BB * NCC * CIN];
__device__ float g_h1   [BB * NCC * HIDD];
__device__ float g_rep  [BB * NCC * RD];
__device__ float g_hle  [BB * NCC * RD];
__device__ float g_part [BB * 32 * RD];
__device__ float g_hmean[BB * RD];
__device__ float g_z    [BB * RD];
__device__ float g_qkv  [BB * NCC * 3 * RD];
__device__ float g_attno[BB * NCC * RD];
__device__ float g_oproj[BB * NCC * RD];
__device__ float g_rep2 [BB * NCC * RD];
__device__ float g_qt   [BB * NTT * RD];
__device__ float g_det  [BB * NTT * RD];
__device__ float g_dh   [BB * NTT * HIDD];

// ===================== common mma helpers =====================
__device__ __forceinline__ float to_tf32(float x) {
    float r; asm("cvt.rna.tf32.f32 %0, %1;" : "=f"(r) : "f"(x)); return r;
}
__device__ __forceinline__ float4 cvt4(float4 v) {
    return make_float4(to_tf32(v.x), to_tf32(v.y), to_tf32(v.z), to_tf32(v.w));
}
__device__ __forceinline__ void mma8(float* d, const float* a, const float* b) {
    asm volatile(
        "mma.sync.aligned.m16n8k8.row.col.f32.tf32.tf32.f32 "
        "{%0,%1,%2,%3},{%4,%5,%6,%7},{%8,%9},{%0,%1,%2,%3};\n"
        : "+f"(d[0]), "+f"(d[1]), "+f"(d[2]), "+f"(d[3])
        : "r"(__float_as_uint(a[0])), "r"(__float_as_uint(a[1])),
          "r"(__float_as_uint(a[2])), "r"(__float_as_uint(a[3])),
          "r"(__float_as_uint(b[0])), "r"(__float_as_uint(b[1])));
}
__device__ __forceinline__ float4 ld_guard(const float* src, int gk, int K) {
    if (gk + 4 <= K) return *(const float4*)src;
    float4 v = make_float4(0.f, 0.f, 0.f, 0.f);
    if (gk     < K) v.x = src[0];
    if (gk + 1 < K) v.y = src[1];
    if (gk + 2 < K) v.z = src[2];
    if (gk + 3 < K) v.w = src[3];
    return v;
}

// ===================== tf32 GEMM (reg-pipelined), B = [K,N] row-major ====
#define XBM 128
#define XBK 32

// WNT: warp n-tile (16 or 32) -> block N = 4*WNT.
// DEC: A gathered from [det | z(bcast) | tx | pc] with K=DIN.
template<int WNT, int ACT, bool DEC>
__global__ void __launch_bounds__(256) mma_gemm(
    const float* __restrict__ A, const float* __restrict__ B,
    const float* __restrict__ bias, float* __restrict__ C,
    int M, int N, int K, int lda, int ldb, int ldc,
    float alpha,
    const float* __restrict__ zt, const float* __restrict__ txt,
    const float* __restrict__ pct)
{
    constexpr int XBN_ = WNT * 4;
    constexpr int NI = WNT / 8;
    constexpr int AST = XBK + 4;
    constexpr int BST = XBN_ + 8;

    __shared__ float As[XBM][AST];
    __shared__ float Bs[XBK][BST];

    int tid = threadIdx.x;
    int wid = tid >> 5, lane = tid & 31;
    int g = lane >> 2, t4 = lane & 3;
    int wm = wid & 1, wn = wid >> 1;
    int m0 = blockIdx.x * XBM, n0 = blockIdx.y * XBN_;

    float acc[4][NI][4];
#pragma unroll
    for (int i = 0; i < 4; i++)
#pragma unroll
        for (int j = 0; j < NI; j++)
#pragma unroll
            for (int l = 0; l < 4; l++) acc[i][j][l] = 0.f;

    float4 ra[4], rb[4];
    constexpr int C4  = XBN_ / 4;
    constexpr int RPI = 256 / C4;
    constexpr int ITS = XBK / RPI;

    const int ac = (tid & 7) * 4;
    const int ar = tid >> 3;
    const int bc4 = tid % C4;
    const int brb = tid / C4;

    auto loadA = [&](int k0) {
        int gk = k0 + ac;
#pragma unroll
        for (int p = 0; p < 4; p++) {
            int gm = m0 + p * 32 + ar;
            if (DEC) {
                const float* s;
                if (gk < RD)                 s = A   + (long)gm * RD   + gk;
                else if (gk < 2 * RD)        s = zt  + (long)(gm >> 11) * RD + (gk - RD);
                else if (gk < 2 * RD + GAPD) s = txt + (long)gm * GAPD + (gk - 2 * RD);
                else if (gk < DIN)           s = pct + (long)gm * CTRLD + (gk - 2 * RD - GAPD);
                else                         s = nullptr;
                ra[p] = s ? *(const float4*)s : make_float4(0.f, 0.f, 0.f, 0.f);
            } else {
                ra[p] = ld_guard(A + (long)gm * lda + gk, gk, K);
            }
        }
    };
    auto loadB = [&](int k0) {
        int gn = n0 + bc4 * 4;
#pragma unroll
        for (int it = 0; it < ITS; it++) {
            int gk = k0 + it * RPI + brb;
            rb[it] = (gk < K && gn + 3 < N) ? *(const float4*)(B + (long)gk * ldb + gn)
                                            : make_float4(0.f, 0.f, 0.f, 0.f);
        }
    };
    auto stsAB = [&]() {
#pragma unroll
        for (int p = 0; p < 4; p++)
            *(float4*)&As[p * 32 + ar][ac] = cvt4(ra[p]);
#pragma unroll
        for (int it = 0; it < ITS; it++)
            *(float4*)&Bs[it * RPI + brb][bc4 * 4] = cvt4(rb[it]);
    };

    int kT = (K + XBK - 1) / XBK;
    loadA(0); loadB(0);

    for (int t = 0; t < kT; t++) {
        stsAB();
        __syncthreads();
        if (t + 1 < kT) { loadA((t + 1) * XBK); loadB((t + 1) * XBK); }
#pragma unroll
        for (int ks = 0; ks < 4; ks++) {
            int kb = ks * 8;
            float af[4][4], bf[NI][2];
#pragma unroll
            for (int mi = 0; mi < 4; mi++) {
                int ma = wm * 64 + mi * 16 + g;
                af[mi][0] = As[ma    ][kb + t4];
                af[mi][1] = As[ma + 8][kb + t4];
                af[mi][2] = As[ma    ][kb + t4 + 4];
                af[mi][3] = As[ma + 8][kb + t4 + 4];
            }
#pragma unroll
            for (int ni = 0; ni < NI; ni++) {
                int nb = wn * WNT + ni * 8 + g;
                bf[ni][0] = Bs[kb + t4    ][nb];
                bf[ni][1] = Bs[kb + t4 + 4][nb];
            }
#pragma unroll
            for (int mi = 0; mi < 4; mi++)
#pragma unroll
                for (int ni = 0; ni < NI; ni++)
                    mma8(acc[mi][ni], af[mi], bf[ni]);
        }
        __syncthreads();
    }

#pragma unroll
    for (int mi = 0; mi < 4; mi++) {
        int gm = m0 + wm * 64 + mi * 16 + g;
#pragma unroll
        for (int ni = 0; ni < NI; ni++) {
            int gn = n0 + wn * WNT + ni * 8 + t4 * 2;
            if (gn >= N) continue;
            float b0 = bias ? bias[gn] : 0.f;
            float b1 = bias ? bias[gn + 1] : 0.f;
            float v0 = acc[mi][ni][0] * alpha + b0;
            float v1 = acc[mi][ni][1] * alpha + b1;
            float v2 = acc[mi][ni][2] * alpha + b0;
            float v3 = acc[mi][ni][3] * alpha + b1;
            if (ACT == 1) {
                v0 = fmaxf(v0, 0.f); v1 = fmaxf(v1, 0.f);
                v2 = fmaxf(v2, 0.f); v3 = fmaxf(v3, 0.f);
            }
            *(float2*)&C[(long)gm * ldc + gn]       = make_float2(v0, v1);
            *(float2*)&C[(long)(gm + 8) * ldc + gn] = make_float2(v2, v3);
        }
    }
}

// ===================== flash self-attention =====================
// grid (8, 4, 16): (q-tile, head, batch). 256 threads.
// Q tile 128x64, KV tiles 128x64. Smem: Q[128][68] K[128][68] V[128][68] P[128][132] red[4][128]
#define SELF_SMEM ((3 * 128 * 68 + 128 * 132 + 512) * 4)

__global__ void __launch_bounds__(256) flash_self_k(
    const float* __restrict__ qkv, float* __restrict__ attno)
{
    extern __shared__ float sm[];
    float* Qs  = sm;
    float* Ks  = sm + 128 * 68;
    float* Vs  = sm + 2 * 128 * 68;
    float* Ps  = sm + 3 * 128 * 68;
    float* red = sm + 3 * 128 * 68 + 128 * 132;

    const int b = blockIdx.z, h = blockIdx.y;
    const int m0 = blockIdx.x * 128;
    const float* base = qkv + (long)b * NCC * 768;
    const float* qp = base + h * 64;
    const float* kp = base + 256 + h * 64;
    const float* vp = base + 512 + h * 64;

    const int tid = threadIdx.x, wid = tid >> 5, lane = tid & 31;
    const int g = lane >> 2, t4 = lane & 3;
    const int wm = wid & 1, wn = wid >> 1;
    const int c4 = (tid & 15) * 4, r0 = tid >> 4;

    // load Q tile once
#pragma unroll
    for (int p = 0; p < 8; p++) {
        int r = p * 16 + r0;
        float4 v = *(const float4*)(qp + (long)(m0 + r) * 768 + c4);
        *(float4*)&Qs[r * 68 + c4] = cvt4(v);
    }

    float m_run[4][2], l_run[4][2], acc_o[4][2][4];
#pragma unroll
    for (int mi = 0; mi < 4; mi++)
#pragma unroll
        for (int hf = 0; hf < 2; hf++) { m_run[mi][hf] = -1e30f; l_run[mi][hf] = 0.f; }
#pragma unroll
    for (int mi = 0; mi < 4; mi++)
#pragma unroll
        for (int ni = 0; ni < 2; ni++)
#pragma unroll
            for (int c = 0; c < 4; c++) acc_o[mi][ni][c] = 0.f;

    for (int tk = 0; tk < 8; tk++) {
        __syncthreads();   // protect K/V/red from previous iteration's readers
#pragma unroll
        for (int p = 0; p < 8; p++) {
            int r = p * 16 + r0;
            float4 kv = *(const float4*)(kp + (long)(tk * 128 + r) * 768 + c4);
            float4 vv = *(const float4*)(vp + (long)(tk * 128 + r) * 768 + c4);
            *(float4*)&Ks[r * 68 + c4] = cvt4(kv);
            *(float4*)&Vs[r * 68 + c4] = cvt4(vv);
        }
        __syncthreads();

        // ---- S = (1/8) Q K^T ----
        float s[4][4][4];
#pragma unroll
        for (int mi = 0; mi < 4; mi++)
#pragma unroll
            for (int ni = 0; ni < 4; ni++)
#pragma unroll
                for (int c = 0; c < 4; c++) s[mi][ni][c] = 0.f;
#pragma unroll
        for (int ks = 0; ks < 8; ks++) {
            int kb = ks * 8;
            float af[4][4], bf[4][2];
#pragma unroll
            for (int mi = 0; mi < 4; mi++) {
                int ma = wm * 64 + mi * 16 + g;
                af[mi][0] = Qs[ma * 68 + kb + t4];
                af[mi][1] = Qs[(ma + 8) * 68 + kb + t4];
                af[mi][2] = Qs[ma * 68 + kb + t4 + 4];
                af[mi][3] = Qs[(ma + 8) * 68 + kb + t4 + 4];
            }
#pragma unroll
            for (int ni = 0; ni < 4; ni++) {
                int nb = wn * 32 + ni * 8 + g;
                bf[ni][0] = Ks[nb * 68 + kb + t4];
                bf[ni][1] = Ks[nb * 68 + kb + t4 + 4];
            }
#pragma unroll
            for (int mi = 0; mi < 4; mi++)
#pragma unroll
                for (int ni = 0; ni < 4; ni++)
                    mma8(s[mi][ni], af[mi], bf[ni]);
        }
#pragma unroll
        for (int mi = 0; mi < 4; mi++)
#pragma unroll
            for (int ni = 0; ni < 4; ni++)
#pragma unroll
                for (int c = 0; c < 4; c++) s[mi][ni][c] *= 0.125f;

        // ---- row max ----
#pragma unroll
        for (int mi = 0; mi < 4; mi++)
#pragma unroll
            for (int hf = 0; hf < 2; hf++) {
                float lm = -1e30f;
#pragma unroll
                for (int ni = 0; ni < 4; ni++)
                    lm = fmaxf(lm, fmaxf(s[mi][ni][hf * 2], s[mi][ni][hf * 2 + 1]));
                lm = fmaxf(lm, __shfl_xor_sync(0xffffffffu, lm, 1));
                lm = fmaxf(lm, __shfl_xor_sync(0xffffffffu, lm, 2));
                if (t4 == 0) red[wn * 128 + wm * 64 + mi * 16 + hf * 8 + g] = lm;
            }
        __syncthreads();

        float fac[4][2], lsum[4][2];
#pragma unroll
        for (int mi = 0; mi < 4; mi++)
#pragma unroll
            for (int hf = 0; hf < 2; hf++) {
                int r = wm * 64 + mi * 16 + hf * 8 + g;
                float tm = fmaxf(fmaxf(red[r], red[128 + r]), fmaxf(red[256 + r], red[384 + r]));
                float mnew = fmaxf(m_run[mi][hf], tm);
                fac[mi][hf] = __expf(m_run[mi][hf] - mnew);
                m_run[mi][hf] = mnew;
                float ls = 0.f;
#pragma unroll
                for (int ni = 0; ni < 4; ni++) {
                    float p0 = __expf(s[mi][ni][hf * 2] - mnew);
                    float p1 = __expf(s[mi][ni][hf * 2 + 1] - mnew);
                    s[mi][ni][hf * 2] = p0; s[mi][ni][hf * 2 + 1] = p1;
                    ls += p0 + p1;
                }
                ls += __shfl_xor_sync(0xffffffffu, ls, 1);
                ls += __shfl_xor_sync(0xffffffffu, ls, 2);
                lsum[mi][hf] = ls;
            }
        __syncthreads();
#pragma unroll
        for (int mi = 0; mi < 4; mi++)
#pragma unroll
            for (int hf = 0; hf < 2; hf++)
                if (t4 == 0) red[wn * 128 + wm * 64 + mi * 16 + hf * 8 + g] = lsum[mi][hf];
        __syncthreads();
#pragma unroll
        for (int mi = 0; mi < 4; mi++)
#pragma unroll
            for (int hf = 0; hf < 2; hf++) {
                int r = wm * 64 + mi * 16 + hf * 8 + g;
                float ts = red[r] + red[128 + r] + red[256 + r] + red[384 + r];
                l_run[mi][hf] = l_run[mi][hf] * fac[mi][hf] + ts;
            }
        // rescale O
#pragma unroll
        for (int mi = 0; mi < 4; mi++)
#pragma unroll
            for (int ni = 0; ni < 2; ni++) {
                acc_o[mi][ni][0] *= fac[mi][0]; acc_o[mi][ni][1] *= fac[mi][0];
                acc_o[mi][ni][2] *= fac[mi][1]; acc_o[mi][ni][3] *= fac[mi][1];
            }
        // write P (tf32)
#pragma unroll
        for (int mi = 0; mi < 4; mi++) {
            int r = wm * 64 + mi * 16 + g;
#pragma unroll
            for (int ni = 0; ni < 4; ni++) {
                int c = wn * 32 + ni * 8 + t4 * 2;
                Ps[r * 132 + c]           = to_tf32(s[mi][ni][0]);
                Ps[r * 132 + c + 1]       = to_tf32(s[mi][ni][1]);
                Ps[(r + 8) * 132 + c]     = to_tf32(s[mi][ni][2]);
                Ps[(r + 8) * 132 + c + 1] = to_tf32(s[mi][ni][3]);
            }
        }
        __syncthreads();

        // ---- O += P V ----
#pragma unroll
        for (int ks = 0; ks < 16; ks++) {
            int kb = ks * 8;
            float af[4][4], bf[2][2];
#pragma unroll
            for (int mi = 0; mi < 4; mi++) {
                int ma = wm * 64 + mi * 16 + g;
                af[mi][0] = Ps[ma * 132 + kb + t4];
                af[mi][1] = Ps[(ma + 8) * 132 + kb + t4];
                af[mi][2] = Ps[ma * 132 + kb + t4 + 4];
                af[mi][3] = Ps[(ma + 8) * 132 + kb + t4 + 4];
            }
#pragma unroll
            for (int ni = 0; ni < 2; ni++) {
                int nb = wn * 16 + ni * 8 + g;
                bf[ni][0] = Vs[(kb + t4) * 68 + nb];
                bf[ni][1] = Vs[(kb + t4 + 4) * 68 + nb];
            }
#pragma unroll
            for (int mi = 0; mi < 4; mi++)
#pragma unroll
                for (int ni = 0; ni < 2; ni++)
                    mma8(acc_o[mi][ni], af[mi], bf[ni]);
        }
    }

    // epilogue
#pragma unroll
    for (int mi = 0; mi < 4; mi++) {
        int row = m0 + wm * 64 + mi * 16 + g;
        float inv0 = 1.f / l_run[mi][0], inv1 = 1.f / l_run[mi][1];
#pragma unroll
        for (int ni = 0; ni < 2; ni++) {
            int col = h * 64 + wn * 16 + ni * 8 + t4 * 2;
            long o0 = ((long)b * NCC + row) * 256 + col;
            long o1 = ((long)b * NCC + row + 8) * 256 + col;
            *(float2*)&attno[o0] = make_float2(acc_o[mi][ni][0] * inv0, acc_o[mi][ni][1] * inv0);
            *(float2*)&attno[o1] = make_float2(acc_o[mi][ni][2] * inv1, acc_o[mi][ni][3] * inv1);
        }
    }
}

// ===================== flash cross-attention =====================
// grid (32, 1, 16). Q tile 64x256, KV tiles 64x256 (K == V == rep2).
// Smem: Q[64][260] KV[64][260] P[64][68] red[4][64]
#define CROSS_SMEM ((2 * 64 * 260 + 64 * 68 + 256) * 4)

__global__ void __launch_bounds__(256) flash_cross_k(
    const float* __restrict__ qt, const float* __restrict__ rep2,
    float* __restrict__ det)
{
    extern __shared__ float sm[];
    float* Qs  = sm;
    float* KVs = sm + 64 * 260;
    float* Ps  = sm + 2 * 64 * 260;
    float* red = sm + 2 * 64 * 260 + 64 * 68;

    const int b = blockIdx.z;
    const int m0 = blockIdx.x * 64;
    const float* qb  = qt   + (long)b * NTT * 256;
    const float* kvb = rep2 + (long)b * NCC * 256;

    const int tid = threadIdx.x, wid = tid >> 5, lane = tid & 31;
    const int g = lane >> 2, t4 = lane & 3;
    const int wm = wid & 1, wn = wid >> 1;
    const int c4 = (tid & 63) * 4, r0 = tid >> 6;

#pragma unroll
    for (int p = 0; p < 16; p++) {
        int r = p * 4 + r0;
        float4 v = *(const float4*)(qb + (long)(m0 + r) * 256 + c4);
        *(float4*)&Qs[r * 260 + c4] = cvt4(v);
    }

    float m_run[2][2], l_run[2][2], acc_o[2][8][4];
#pragma unroll
    for (int mi = 0; mi < 2; mi++)
#pragma unroll
        for (int hf = 0; hf < 2; hf++) { m_run[mi][hf] = -1e30f; l_run[mi][hf] = 0.f; }
#pragma unroll
    for (int mi = 0; mi < 2; mi++)
#pragma unroll
        for (int ni = 0; ni < 8; ni++)
#pragma unroll
            for (int c = 0; c < 4; c++) acc_o[mi][ni][c] = 0.f;

    for (int tk = 0; tk < 16; tk++) {
        __syncthreads();
#pragma unroll
        for (int p = 0; p < 16; p++) {
            int r = p * 4 + r0;
            float4 v = *(const float4*)(kvb + (long)(tk * 64 + r) * 256 + c4);
            *(float4*)&KVs[r * 260 + c4] = cvt4(v);
        }
        __syncthreads();

        // ---- S = (1/16) Q KV^T ----
        float s[2][2][4];
#pragma unroll
        for (int mi = 0; mi < 2; mi++)
#pragma unroll
            for (int ni = 0; ni < 2; ni++)
#pragma unroll
                for (int c = 0; c < 4; c++) s[mi][ni][c] = 0.f;
#pragma unroll
        for (int ks = 0; ks < 32; ks++) {
            int kb = ks * 8;
            float af[2][4], bf[2][2];
#pragma unroll
            for (int mi = 0; mi < 2; mi++) {
                int ma = wm * 32 + mi * 16 + g;
                af[mi][0] = Qs[ma * 260 + kb + t4];
                af[mi][1] = Qs[(ma + 8) * 260 + kb + t4];
                af[mi][2] = Qs[ma * 260 + kb + t4 + 4];
                af[mi][3] = Qs[(ma + 8) * 260 + kb + t4 + 4];
            }
#pragma unroll
            for (int ni = 0; ni < 2; ni++) {
                int nb = wn * 16 + ni * 8 + g;
                bf[ni][0] = KVs[nb * 260 + kb + t4];
                bf[ni][1] = KVs[nb * 260 + kb + t4 + 4];
            }
#pragma unroll
            for (int mi = 0; mi < 2; mi++)
#pragma unroll
                for (int ni = 0; ni < 2; ni++)
                    mma8(s[mi][ni], af[mi], bf[ni]);
        }
#pragma unroll
        for (int mi = 0; mi < 2; mi++)
#pragma unroll
            for (int ni = 0; ni < 2; ni++)
#pragma unroll
                for (int c = 0; c < 4; c++) s[mi][ni][c] *= 0.0625f;

#pragma unroll
        for (int mi = 0; mi < 2; mi++)
#pragma unroll
            for (int hf = 0; hf < 2; hf++) {
                float lm = -1e30f;
#pragma unroll
                for (int ni = 0; ni < 2; ni++)
                    lm = fmaxf(lm, fmaxf(s[mi][ni][hf * 2], s[mi][ni][hf * 2 + 1]));
                lm = fmaxf(lm, __shfl_xor_sync(0xffffffffu, lm, 1));
                lm = fmaxf(lm, __shfl_xor_sync(0xffffffffu, lm, 2));
                if (t4 == 0) red[wn * 64 + wm * 32 + mi * 16 + hf * 8 + g] = lm;
            }
        __syncthreads();

        float fac[2][2], lsum[2][2];
#pragma unroll
        for (int mi = 0; mi < 2; mi++)
#pragma unroll
            for (int hf = 0; hf < 2; hf++) {
                int r = wm * 32 + mi * 16 + hf * 8 + g;
                float tm = fmaxf(fmaxf(red[r], red[64 + r]), fmaxf(red[128 + r], red[192 + r]));
                float mnew = fmaxf(m_run[mi][hf], tm);
                fac[mi][hf] = __expf(m_run[mi][hf] - mnew);
                m_run[mi][hf] = mnew;
                float ls = 0.f;
#pragma unroll
                for (int ni = 0; ni < 2; ni++) {
                    float p0 = __expf(s[mi][ni][hf * 2] - mnew);
                    float p1 = __expf(s[mi][ni][hf * 2 + 1] - mnew);
                    s[mi][ni][hf * 2] = p0; s[mi][ni][hf * 2 + 1] = p1;
                    ls += p0 + p1;
                }
                ls += __shfl_xor_sync(0xffffffffu, ls, 1);
                ls += __shfl_xor_sync(0xffffffffu, ls, 2);
                lsum[mi][hf] = ls;
            }
        __syncthreads();
#pragma unroll
        for (int mi = 0; mi < 2; mi++)
#pragma unroll
            for (int hf = 0; hf < 2; hf++)
                if (t4 == 0) red[wn * 64 + wm * 32 + mi * 16 + hf * 8 + g] = lsum[mi][hf];
        __syncthreads();
#pragma unroll
        for (int mi = 0; mi < 2; mi++)
#pragma unroll
            for (int hf = 0; hf < 2; hf++) {
                int r = wm * 32 + mi * 16 + hf * 8 + g;
                float ts = red[r] + red[64 + r] + red[128 + r] + red[192 + r];
                l_run[mi][hf] = l_run[mi][hf] * fac[mi][hf] + ts;
            }
#pragma unroll
        for (int mi = 0; mi < 2; mi++)
#pragma unroll
            for (int ni = 0; ni < 8; ni++) {
                acc_o[mi][ni][0] *= fac[mi][0]; acc_o[mi][ni][1] *= fac[mi][0];
                acc_o[mi][ni][2] *= fac[mi][1]; acc_o[mi][ni][3] *= fac[mi][1];
            }
#pragma unroll
        for (int mi = 0; mi < 2; mi++) {
            int r = wm * 32 + mi * 16 + g;
#pragma unroll
            for (int ni = 0; ni < 2; ni++) {
                int c = wn * 16 + ni * 8 + t4 * 2;
                Ps[r * 68 + c]           = to_tf32(s[mi][ni][0]);
                Ps[r * 68 + c + 1]       = to_tf32(s[mi][ni][1]);
                Ps[(r + 8) * 68 + c]     = to_tf32(s[mi][ni][2]);
                Ps[(r + 8) * 68 + c + 1] = to_tf32(s[mi][ni][3]);
            }
        }
        __syncthreads();

        // ---- O += P KV ----
#pragma unroll
        for (int ks = 0; ks < 8; ks++) {
            int kb = ks * 8;
            float af[2][4], bf[8][2];
#pragma unroll
            for (int mi = 0; mi < 2; mi++) {
                int ma = wm * 32 + mi * 16 + g;
                af[mi][0] = Ps[ma * 68 + kb + t4];
                af[mi][1] = Ps[(ma + 8) * 68 + kb + t4];
                af[mi][2] = Ps[ma * 68 + kb + t4 + 4];
                af[mi][3] = Ps[(ma + 8) * 68 + kb + t4 + 4];
            }
#pragma unroll
            for (int ni = 0; ni < 8; ni++) {
                int nb = wn * 64 + ni * 8 + g;
                bf[ni][0] = KVs[(kb + t4) * 260 + nb];
                bf[ni][1] = KVs[(kb + t4 + 4) * 260 + nb];
            }
#pragma unroll
            for (int mi = 0; mi < 2; mi++)
#pragma unroll
                for (int ni = 0; ni < 8; ni++)
                    mma8(acc_o[mi][ni], af[mi], bf[ni]);
        }
    }

#pragma unroll
    for (int mi = 0; mi < 2; mi++) {
        int row = m0 + wm * 32 + mi * 16 + g;
        float inv0 = 1.f / l_run[mi][0], inv1 = 1.f / l_run[mi][1];
#pragma unroll
        for (int ni = 0; ni < 8; ni++) {
            int col = wn * 64 + ni * 8 + t4 * 2;
            long o0 = ((long)b * NTT + row) * 256 + col;
            long o1 = ((long)b * NTT + row + 8) * 256 + col;
            *(float2*)&det[o0] = make_float2(acc_o[mi][ni][0] * inv0, acc_o[mi][ni][1] * inv0);
            *(float2*)&det[o1] = make_float2(acc_o[mi][ni][2] * inv1, acc_o[mi][ni][3] * inv1);
        }
    }
}

// ===================== small kernels =====================

__global__ void concat_ctx_k(const float* __restrict__ cy, const float* __restrict__ cx,
                             float* __restrict__ out)
{
    int idx = blockIdx.x * 256 + threadIdx.x;
    int total = BB * NCC * CIN;
    if (idx >= total) return;
    int row = idx / CIN, c = idx - row * CIN;
    out[idx] = (c < CTRLD) ? cy[row * CTRLD + c] : cx[row * GAPD + (c - CTRLD)];
}

__global__ void mean1_k(const float* __restrict__ h, float* __restrict__ part)
{
    int b = blockIdx.x, ch = blockIdx.y, j = threadIdx.x * 4; // 64 threads
    const float* p = h + (long)b * NCC * RD + (long)ch * 32 * RD + j;
    float4 s = make_float4(0.f, 0.f, 0.f, 0.f);
#pragma unroll 4
    for (int n = 0; n < 32; n++) {
        float4 v = *(const float4*)(p + (long)n * RD);
        s.x += v.x; s.y += v.y; s.z += v.z; s.w += v.w;
    }
    *(float4*)&part[(long)(b * 32 + ch) * RD + j] = s;
}

__global__ void mean2_k(const float* __restrict__ part, float* __restrict__ out)
{
    int b = blockIdx.x, j = threadIdx.x;
    float s = 0.f;
#pragma unroll
    for (int c = 0; c < 32; c++) s += part[(long)(b * 32 + c) * RD + j];
    out[b * RD + j] = s * (1.f / NCC);
}

__global__ void latent_k(const float* __restrict__ hmean,
                         const float* __restrict__ pw, const float* __restrict__ pb,
                         const float* __restrict__ mw, const float* __restrict__ mb,
                         const float* __restrict__ sw, const float* __restrict__ sb,
                         const float* __restrict__ eps, float* __restrict__ z)
{
    __shared__ float h2[LHD];
    int b = blockIdx.x, tid = threadIdx.x;
    if (tid < LHD) {
        float s = pb[tid];
        const float* hm = hmean + b * RD;
        for (int k = 0; k < RD; k++) s += hm[k] * pw[k * LHD + tid];
        h2[tid] = s;
    }
    __syncthreads();
    float mu = mb[tid], ls = sb[tid];
    for (int k = 0; k < LHD; k++) {
        mu += h2[k] * mw[k * RD + tid];
        ls += h2[k] * sw[k * RD + tid];
    }
    float sig = 0.9f / (1.f + expf(-ls)) + 0.1f;
    z[b * RD + tid] = mu + sig * eps[b * RD + tid];
}

__global__ void ln_k(const float* __restrict__ x, const float* __restrict__ y,
                     const float* __restrict__ g, const float* __restrict__ b,
                     float* __restrict__ out)
{
    __shared__ float sh[256];
    long row = blockIdx.x; int tid = threadIdx.x;
    float v = x[row * RD + tid] + y[row * RD + tid];
    sh[tid] = v; __syncthreads();
    for (int s = 128; s; s >>= 1) { if (tid < s) sh[tid] += sh[tid + s]; __syncthreads(); }
    float mean = sh[0] * (1.f / RD); __syncthreads();
    float d = v - mean;
    sh[tid] = d * d; __syncthreads();
    for (int s = 128; s; s >>= 1) { if (tid < s) sh[tid] += sh[tid + s]; __syncthreads(); }
    float var = sh[0] * (1.f / RD);
    out[row * RD + tid] = d * rsqrtf(var + 1e-5f) * g[tid] + b[tid];
}

// dec2 (K=128, N=16) fused with mu/sigma epilogue, writes final out
__global__ void __launch_bounds__(256) dec2_k(
    const float* __restrict__ dh, const float* __restrict__ w2,
    const float* __restrict__ b2, float* __restrict__ out)
{
    __shared__ float w[128][17];
    __shared__ float a[16][132];
    int tid = threadIdx.x;
    for (int i = tid; i < 128 * 16; i += 256) { int k = i >> 4, c = i & 15; w[k][c] = w2[i]; }
    long row0 = (long)blockIdx.x * 16;
    for (int i = tid; i < 512; i += 256) {
        int r = i >> 5, c4 = (i & 31) * 4;
        *(float4*)&a[r][c4] = *(const float4*)&dh[(row0 + r) * 128 + c4];
    }
    __syncthreads();
    int r = tid >> 4, c = tid & 15;
    float s = b2[c];
#pragma unroll
    for (int k = 0; k < 128; k++) s += a[r][k] * w[k][c];
    long row = row0 + r;
    const long TOT = (long)BB * NTT * CTRLD;
    if (c < CTRLD) out[row * CTRLD + c] = s;
    else {
        float sp = fmaxf(s, 0.f) + log1pf(expf(-fabsf(s)));
        out[TOT + row * CTRLD + (c - CTRLD)] = 0.9f * sp + 0.1f;
    }
}

// ===================== host side =====================

static float* sym(const void* s) { void* p = nullptr; cudaGetSymbolAddress(&p, s); return (float*)p; }

extern "C" void kernel_launch(void* const* d_in, const int* in_sizes, int n_in,
                              void* d_out, int out_size)
{
    const float* context_x = (const float*)d_in[0];
    const float* context_y = (const float*)d_in[1];
    const float* target_x  = (const float*)d_in[2];
    const float* pred_ctrl = (const float*)d_in[3];
    const float* eps       = (const float*)d_in[4];
    const float* ce_w1 = (const float*)d_in[5];  const float* ce_b1 = (const float*)d_in[6];
    const float* ce_w2 = (const float*)d_in[7];  const float* ce_b2 = (const float*)d_in[8];
    const float* sa_in_w = (const float*)d_in[9];  const float* sa_in_b = (const float*)d_in[10];
    const float* sa_out_w = (const float*)d_in[11]; const float* sa_out_b = (const float*)d_in[12];
    const float* sa_ln_g = (const float*)d_in[13];  const float* sa_ln_b = (const float*)d_in[14];
    const float* qp_w = (const float*)d_in[15]; const float* qp_b = (const float*)d_in[16];
    const float* le_w1 = (const float*)d_in[17]; const float* le_b1 = (const float*)d_in[18];
    const float* le_w2 = (const float*)d_in[19]; const float* le_b2 = (const float*)d_in[20];
    const float* le_pw = (const float*)d_in[21]; const float* le_pb = (const float*)d_in[22];
    const float* le_mw = (const float*)d_in[23]; const float* le_mb = (const float*)d_in[24];
    const float* le_sw = (const float*)d_in[25]; const float* le_sb = (const float*)d_in[26];
    const float* dec_w1 = (const float*)d_in[27]; const float* dec_b1 = (const float*)d_in[28];
    const float* dec_w2 = (const float*)d_in[29]; const float* dec_b2 = (const float*)d_in[30];
    float* out = (float*)d_out;

    float* comb  = sym(g_comb);
    float* h1    = sym(g_h1);
    float* rep   = sym(g_rep);
    float* hle   = sym(g_hle);
    float* part  = sym(g_part);
    float* hmean = sym(g_hmean);
    float* z     = sym(g_z);
    float* qkv   = sym(g_qkv);
    float* attno = sym(g_attno);
    float* oproj = sym(g_oproj);
    float* rep2  = sym(g_rep2);
    float* qt    = sym(g_qt);
    float* det   = sym(g_det);
    float* dh    = sym(g_dh);

    const int MC = BB * NCC;   // 16384
    const int MT = BB * NTT;   // 32768

    cudaFuncSetAttribute(flash_self_k,  cudaFuncAttributeMaxDynamicSharedMemorySize, SELF_SMEM);
    cudaFuncSetAttribute(flash_cross_k, cudaFuncAttributeMaxDynamicSharedMemorySize, CROSS_SMEM);

    concat_ctx_k<<<(BB * NCC * CIN + 255) / 256, 256>>>(context_y, context_x, comb);

    // --- latent path ---
    mma_gemm<32, 1, false><<<dim3(MC / 128, 1, 1), 256>>>(comb, le_w1, le_b1, h1,
        MC, HIDD, CIN, CIN, HIDD, HIDD, 1.f, 0, 0, 0);
    mma_gemm<32, 0, false><<<dim3(MC / 128, 2, 1), 256>>>(h1, le_w2, le_b2, hle,
        MC, RD, HIDD, HIDD, RD, RD, 1.f, 0, 0, 0);
    mean1_k<<<dim3(BB, 32), 64>>>(hle, part);
    mean2_k<<<BB, 256>>>(part, hmean);
    latent_k<<<BB, 256>>>(hmean, le_pw, le_pb, le_mw, le_mb, le_sw, le_sb, eps, z);

    // --- deterministic path ---
    mma_gemm<32, 1, false><<<dim3(MC / 128, 1, 1), 256>>>(comb, ce_w1, ce_b1, h1,
        MC, HIDD, CIN, CIN, HIDD, HIDD, 1.f, 0, 0, 0);
    mma_gemm<32, 0, false><<<dim3(MC / 128, 2, 1), 256>>>(h1, ce_w2, ce_b2, rep,
        MC, RD, HIDD, HIDD, RD, RD, 1.f, 0, 0, 0);

    mma_gemm<32, 0, false><<<dim3(MC / 128, 6, 1), 256>>>(rep, sa_in_w, sa_in_b, qkv,
        MC, 3 * RD, RD, RD, 3 * RD, 3 * RD, 1.f, 0, 0, 0);

    // fused self-attention
    flash_self_k<<<dim3(NCC / 128, NHD, BB), 256, SELF_SMEM>>>(qkv, attno);

    mma_gemm<32, 0, false><<<dim3(MC / 128, 2, 1), 256>>>(attno, sa_out_w, sa_out_b, oproj,
        MC, RD, RD, RD, RD, RD, 1.f, 0, 0, 0);
    ln_k<<<MC, 256>>>(rep, oproj, sa_ln_g, sa_ln_b, rep2);

    // --- cross attention (fused) ---
    mma_gemm<32, 0, false><<<dim3(MT / 128, 2, 1), 256>>>(target_x, qp_w, qp_b, qt,
        MT, RD, GAPD, GAPD, RD, RD, 1.f, 0, 0, 0);
    flash_cross_k<<<dim3(NTT / 64, 1, BB), 256, CROSS_SMEM>>>(qt, rep2, det);

    // --- decoder: dec1 gathers A from [det | z | target_x | pred_control] ---
    mma_gemm<32, 1, true><<<dim3(MT / 128, 1, 1), 256>>>(det, dec_w1, dec_b1, dh,
        MT, HIDD, DIN, DIN, HIDD, HIDD, 1.f,
        z, target_x, pred_ctrl);
    dec2_k<<<MT / 16, 256>>>(dh, dec_w2, dec_b2, out);
}

// round 5
// speedup vs baseline: 3.7070x; 1.0458x over previous
#include <cuda_runtime.h>
#include <math.h>

// ---- problem dims ----
#define BB 16
#define NCC 1024
#define NTT 2048
#define GAPD 128
#define CTRLD 8
#define RD 256
#define NHD 4
#define HDD 64
#define HIDD 128
#define LHD 192
#define CIN (CTRLD + GAPD)          // 136
#define DIN (2 * RD + GAPD + CTRLD) // 648

// ---- scratch ----
__device__ float g_h1   [BB * NCC * HIDD];
__device__ float g_rep  [BB * NCC * RD];
__device__ float g_hle  [BB * NCC * RD];
__device__ float g_part [BB * 32 * RD];
__device__ float g_hmean[BB * RD];
__device__ float g_z    [BB * RD];
__device__ float g_qkv  [BB * NCC * 3 * RD];
__device__ float g_attno[BB * NCC * RD];
__device__ float g_oproj[BB * NCC * RD];
__device__ float g_rep2 [BB * NCC * RD];
__device__ float g_qt   [BB * NTT * RD];
__device__ float g_det  [BB * NTT * RD];
__device__ float g_dh   [BB * NTT * HIDD];

// ===================== common mma helpers =====================
__device__ __forceinline__ float to_tf32(float x) {
    float r; asm("cvt.rna.tf32.f32 %0, %1;" : "=f"(r) : "f"(x)); return r;
}
__device__ __forceinline__ float4 cvt4(float4 v) {
    return make_float4(to_tf32(v.x), to_tf32(v.y), to_tf32(v.z), to_tf32(v.w));
}
__device__ __forceinline__ void mma8(float* d, const float* a, const float* b) {
    asm volatile(
        "mma.sync.aligned.m16n8k8.row.col.f32.tf32.tf32.f32 "
        "{%0,%1,%2,%3},{%4,%5,%6,%7},{%8,%9},{%0,%1,%2,%3};\n"
        : "+f"(d[0]), "+f"(d[1]), "+f"(d[2]), "+f"(d[3])
        : "r"(__float_as_uint(a[0])), "r"(__float_as_uint(a[1])),
          "r"(__float_as_uint(a[2])), "r"(__float_as_uint(a[3])),
          "r"(__float_as_uint(b[0])), "r"(__float_as_uint(b[1])));
}
__device__ __forceinline__ float4 ld_guard(const float* src, int gk, int K) {
    if (gk + 4 <= K) return *(const float4*)src;
    float4 v = make_float4(0.f, 0.f, 0.f, 0.f);
    if (gk     < K) v.x = src[0];
    if (gk + 1 < K) v.y = src[1];
    if (gk + 2 < K) v.z = src[2];
    if (gk + 3 < K) v.w = src[3];
    return v;
}

// ===================== tf32 GEMM (reg-pipelined), B = [K,N] row-major ====
#define XBM 128
#define XBK 32

// WNT: warp n-tile (16 or 32) -> block N = 4*WNT.
// MODE 0: plain A.  MODE 1: A gathered from [det | z(bcast) | tx | pc], K=DIN.
// MODE 2: A gathered from [cy | cx], K=CIN (zt=cy, txt=cx).
template<int WNT, int ACT, int MODE>
__global__ void __launch_bounds__(256) mma_gemm(
    const float* __restrict__ A, const float* __restrict__ B,
    const float* __restrict__ bias, float* __restrict__ C,
    int M, int N, int K, int lda, int ldb, int ldc,
    float alpha,
    const float* __restrict__ zt, const float* __restrict__ txt,
    const float* __restrict__ pct)
{
    constexpr int XBN_ = WNT * 4;
    constexpr int NI = WNT / 8;
    constexpr int AST = XBK + 4;
    constexpr int BST = XBN_ + 8;

    __shared__ float As[XBM][AST];
    __shared__ float Bs[XBK][BST];

    int tid = threadIdx.x;
    int wid = tid >> 5, lane = tid & 31;
    int g = lane >> 2, t4 = lane & 3;
    int wm = wid & 1, wn = wid >> 1;
    int m0 = blockIdx.x * XBM, n0 = blockIdx.y * XBN_;

    float acc[4][NI][4];
#pragma unroll
    for (int i = 0; i < 4; i++)
#pragma unroll
        for (int j = 0; j < NI; j++)
#pragma unroll
            for (int l = 0; l < 4; l++) acc[i][j][l] = 0.f;

    float4 ra[4], rb[4];
    constexpr int C4  = XBN_ / 4;
    constexpr int RPI = 256 / C4;
    constexpr int ITS = XBK / RPI;

    const int ac = (tid & 7) * 4;
    const int ar = tid >> 3;
    const int bc4 = tid % C4;
    const int brb = tid / C4;

    auto loadA = [&](int k0) {
        int gk = k0 + ac;
#pragma unroll
        for (int p = 0; p < 4; p++) {
            int gm = m0 + p * 32 + ar;
            if (MODE == 1) {
                const float* s;
                if (gk < RD)                 s = A   + (long)gm * RD   + gk;
                else if (gk < 2 * RD)        s = zt  + (long)(gm >> 11) * RD + (gk - RD);
                else if (gk < 2 * RD + GAPD) s = txt + (long)gm * GAPD + (gk - 2 * RD);
                else if (gk < DIN)           s = pct + (long)gm * CTRLD + (gk - 2 * RD - GAPD);
                else                         s = nullptr;
                ra[p] = s ? *(const float4*)s : make_float4(0.f, 0.f, 0.f, 0.f);
            } else if (MODE == 2) {
                const float* s;
                if (gk < CTRLD)    s = zt  + (long)gm * CTRLD + gk;        // context_y
                else if (gk < CIN) s = txt + (long)gm * GAPD + (gk - CTRLD); // context_x
                else               s = nullptr;
                ra[p] = s ? *(const float4*)s : make_float4(0.f, 0.f, 0.f, 0.f);
            } else {
                ra[p] = ld_guard(A + (long)gm * lda + gk, gk, K);
            }
        }
    };
    auto loadB = [&](int k0) {
        int gn = n0 + bc4 * 4;
#pragma unroll
        for (int it = 0; it < ITS; it++) {
            int gk = k0 + it * RPI + brb;
            rb[it] = (gk < K && gn + 3 < N) ? *(const float4*)(B + (long)gk * ldb + gn)
                                            : make_float4(0.f, 0.f, 0.f, 0.f);
        }
    };
    auto stsAB = [&]() {
#pragma unroll
        for (int p = 0; p < 4; p++)
            *(float4*)&As[p * 32 + ar][ac] = cvt4(ra[p]);
#pragma unroll
        for (int it = 0; it < ITS; it++)
            *(float4*)&Bs[it * RPI + brb][bc4 * 4] = cvt4(rb[it]);
    };

    int kT = (K + XBK - 1) / XBK;
    loadA(0); loadB(0);

    for (int t = 0; t < kT; t++) {
        stsAB();
        __syncthreads();
        if (t + 1 < kT) { loadA((t + 1) * XBK); loadB((t + 1) * XBK); }
#pragma unroll
        for (int ks = 0; ks < 4; ks++) {
            int kb = ks * 8;
            float af[4][4], bf[NI][2];
#pragma unroll
            for (int mi = 0; mi < 4; mi++) {
                int ma = wm * 64 + mi * 16 + g;
                af[mi][0] = As[ma    ][kb + t4];
                af[mi][1] = As[ma + 8][kb + t4];
                af[mi][2] = As[ma    ][kb + t4 + 4];
                af[mi][3] = As[ma + 8][kb + t4 + 4];
            }
#pragma unroll
            for (int ni = 0; ni < NI; ni++) {
                int nb = wn * WNT + ni * 8 + g;
                bf[ni][0] = Bs[kb + t4    ][nb];
                bf[ni][1] = Bs[kb + t4 + 4][nb];
            }
#pragma unroll
            for (int mi = 0; mi < 4; mi++)
#pragma unroll
                for (int ni = 0; ni < NI; ni++)
                    mma8(acc[mi][ni], af[mi], bf[ni]);
        }
        __syncthreads();
    }

#pragma unroll
    for (int mi = 0; mi < 4; mi++) {
        int gm = m0 + wm * 64 + mi * 16 + g;
#pragma unroll
        for (int ni = 0; ni < NI; ni++) {
            int gn = n0 + wn * WNT + ni * 8 + t4 * 2;
            if (gn >= N) continue;
            float b0 = bias ? bias[gn] : 0.f;
            float b1 = bias ? bias[gn + 1] : 0.f;
            float v0 = acc[mi][ni][0] * alpha + b0;
            float v1 = acc[mi][ni][1] * alpha + b1;
            float v2 = acc[mi][ni][2] * alpha + b0;
            float v3 = acc[mi][ni][3] * alpha + b1;
            if (ACT == 1) {
                v0 = fmaxf(v0, 0.f); v1 = fmaxf(v1, 0.f);
                v2 = fmaxf(v2, 0.f); v3 = fmaxf(v3, 0.f);
            }
            *(float2*)&C[(long)gm * ldc + gn]       = make_float2(v0, v1);
            *(float2*)&C[(long)(gm + 8) * ldc + gn] = make_float2(v2, v3);
        }
    }
}

// ===================== flash self-attention (reg-prefetch KV) =====================
// grid (8, 4, 16). Q tile 128x64, KV tiles 128x64.
#define SELF_SMEM ((3 * 128 * 68 + 128 * 132 + 512) * 4)

__global__ void __launch_bounds__(256) flash_self_k(
    const float* __restrict__ qkv, float* __restrict__ attno)
{
    extern __shared__ float sm[];
    float* Qs  = sm;
    float* Ks  = sm + 128 * 68;
    float* Vs  = sm + 2 * 128 * 68;
    float* Ps  = sm + 3 * 128 * 68;
    float* red = sm + 3 * 128 * 68 + 128 * 132;

    const int b = blockIdx.z, h = blockIdx.y;
    const int m0 = blockIdx.x * 128;
    const float* base = qkv + (long)b * NCC * 768;
    const float* qp = base + h * 64;
    const float* kp = base + 256 + h * 64;
    const float* vp = base + 512 + h * 64;

    const int tid = threadIdx.x, wid = tid >> 5, lane = tid & 31;
    const int g = lane >> 2, t4 = lane & 3;
    const int wm = wid & 1, wn = wid >> 1;
    const int c4 = (tid & 15) * 4, r0 = tid >> 4;

    // load Q tile once
#pragma unroll
    for (int p = 0; p < 8; p++) {
        int r = p * 16 + r0;
        float4 v = *(const float4*)(qp + (long)(m0 + r) * 768 + c4);
        *(float4*)&Qs[r * 68 + c4] = cvt4(v);
    }

    float4 rk[8], rv[8];
    auto loadKV = [&](int tk) {
#pragma unroll
        for (int p = 0; p < 8; p++) {
            int r = tk * 128 + p * 16 + r0;
            rk[p] = *(const float4*)(kp + (long)r * 768 + c4);
            rv[p] = *(const float4*)(vp + (long)r * 768 + c4);
        }
    };
    auto stsKV = [&]() {
#pragma unroll
        for (int p = 0; p < 8; p++) {
            int r = p * 16 + r0;
            *(float4*)&Ks[r * 68 + c4] = cvt4(rk[p]);
            *(float4*)&Vs[r * 68 + c4] = cvt4(rv[p]);
        }
    };

    float m_run[4][2], l_run[4][2], acc_o[4][2][4];
#pragma unroll
    for (int mi = 0; mi < 4; mi++)
#pragma unroll
        for (int hf = 0; hf < 2; hf++) { m_run[mi][hf] = -1e30f; l_run[mi][hf] = 0.f; }
#pragma unroll
    for (int mi = 0; mi < 4; mi++)
#pragma unroll
        for (int ni = 0; ni < 2; ni++)
#pragma unroll
            for (int c = 0; c < 4; c++) acc_o[mi][ni][c] = 0.f;

    loadKV(0);

    for (int tk = 0; tk < 8; tk++) {
        __syncthreads();   // WAR: previous iteration readers of Ks/Vs done
        stsKV();
        __syncthreads();
        if (tk + 1 < 8) loadKV(tk + 1);   // overlap with compute below

        // ---- S = (1/8) Q K^T ----
        float s[4][4][4];
#pragma unroll
        for (int mi = 0; mi < 4; mi++)
#pragma unroll
            for (int ni = 0; ni < 4; ni++)
#pragma unroll
                for (int c = 0; c < 4; c++) s[mi][ni][c] = 0.f;
#pragma unroll
        for (int ks = 0; ks < 8; ks++) {
            int kb = ks * 8;
            float af[4][4], bf[4][2];
#pragma unroll
            for (int mi = 0; mi < 4; mi++) {
                int ma = wm * 64 + mi * 16 + g;
                af[mi][0] = Qs[ma * 68 + kb + t4];
                af[mi][1] = Qs[(ma + 8) * 68 + kb + t4];
                af[mi][2] = Qs[ma * 68 + kb + t4 + 4];
                af[mi][3] = Qs[(ma + 8) * 68 + kb + t4 + 4];
            }
#pragma unroll
            for (int ni = 0; ni < 4; ni++) {
                int nb = wn * 32 + ni * 8 + g;
                bf[ni][0] = Ks[nb * 68 + kb + t4];
                bf[ni][1] = Ks[nb * 68 + kb + t4 + 4];
            }
#pragma unroll
            for (int mi = 0; mi < 4; mi++)
#pragma unroll
                for (int ni = 0; ni < 4; ni++)
                    mma8(s[mi][ni], af[mi], bf[ni]);
        }
#pragma unroll
        for (int mi = 0; mi < 4; mi++)
#pragma unroll
            for (int ni = 0; ni < 4; ni++)
#pragma unroll
                for (int c = 0; c < 4; c++) s[mi][ni][c] *= 0.125f;

        // ---- row max ----
#pragma unroll
        for (int mi = 0; mi < 4; mi++)
#pragma unroll
            for (int hf = 0; hf < 2; hf++) {
                float lm = -1e30f;
#pragma unroll
                for (int ni = 0; ni < 4; ni++)
                    lm = fmaxf(lm, fmaxf(s[mi][ni][hf * 2], s[mi][ni][hf * 2 + 1]));
                lm = fmaxf(lm, __shfl_xor_sync(0xffffffffu, lm, 1));
                lm = fmaxf(lm, __shfl_xor_sync(0xffffffffu, lm, 2));
                if (t4 == 0) red[wn * 128 + wm * 64 + mi * 16 + hf * 8 + g] = lm;
            }
        __syncthreads();

        float fac[4][2], lsum[4][2];
#pragma unroll
        for (int mi = 0; mi < 4; mi++)
#pragma unroll
            for (int hf = 0; hf < 2; hf++) {
                int r = wm * 64 + mi * 16 + hf * 8 + g;
                float tm = fmaxf(fmaxf(red[r], red[128 + r]), fmaxf(red[256 + r], red[384 + r]));
                float mnew = fmaxf(m_run[mi][hf], tm);
                fac[mi][hf] = __expf(m_run[mi][hf] - mnew);
                m_run[mi][hf] = mnew;
                float ls = 0.f;
#pragma unroll
                for (int ni = 0; ni < 4; ni++) {
                    float p0 = __expf(s[mi][ni][hf * 2] - mnew);
                    float p1 = __expf(s[mi][ni][hf * 2 + 1] - mnew);
                    s[mi][ni][hf * 2] = p0; s[mi][ni][hf * 2 + 1] = p1;
                    ls += p0 + p1;
                }
                ls += __shfl_xor_sync(0xffffffffu, ls, 1);
                ls += __shfl_xor_sync(0xffffffffu, ls, 2);
                lsum[mi][hf] = ls;
            }
        __syncthreads();
#pragma unroll
        for (int mi = 0; mi < 4; mi++)
#pragma unroll
            for (int hf = 0; hf < 2; hf++)
                if (t4 == 0) red[wn * 128 + wm * 64 + mi * 16 + hf * 8 + g] = lsum[mi][hf];
        __syncthreads();
#pragma unroll
        for (int mi = 0; mi < 4; mi++)
#pragma unroll
            for (int hf = 0; hf < 2; hf++) {
                int r = wm * 64 + mi * 16 + hf * 8 + g;
                float ts = red[r] + red[128 + r] + red[256 + r] + red[384 + r];
                l_run[mi][hf] = l_run[mi][hf] * fac[mi][hf] + ts;
            }
#pragma unroll
        for (int mi = 0; mi < 4; mi++)
#pragma unroll
            for (int ni = 0; ni < 2; ni++) {
                acc_o[mi][ni][0] *= fac[mi][0]; acc_o[mi][ni][1] *= fac[mi][0];
                acc_o[mi][ni][2] *= fac[mi][1]; acc_o[mi][ni][3] *= fac[mi][1];
            }
#pragma unroll
        for (int mi = 0; mi < 4; mi++) {
            int r = wm * 64 + mi * 16 + g;
#pragma unroll
            for (int ni = 0; ni < 4; ni++) {
                int c = wn * 32 + ni * 8 + t4 * 2;
                Ps[r * 132 + c]           = to_tf32(s[mi][ni][0]);
                Ps[r * 132 + c + 1]       = to_tf32(s[mi][ni][1]);
                Ps[(r + 8) * 132 + c]     = to_tf32(s[mi][ni][2]);
                Ps[(r + 8) * 132 + c + 1] = to_tf32(s[mi][ni][3]);
            }
        }
        __syncthreads();

        // ---- O += P V ----
#pragma unroll
        for (int ks = 0; ks < 16; ks++) {
            int kb = ks * 8;
            float af[4][4], bf[2][2];
#pragma unroll
            for (int mi = 0; mi < 4; mi++) {
                int ma = wm * 64 + mi * 16 + g;
                af[mi][0] = Ps[ma * 132 + kb + t4];
                af[mi][1] = Ps[(ma + 8) * 132 + kb + t4];
                af[mi][2] = Ps[ma * 132 + kb + t4 + 4];
                af[mi][3] = Ps[(ma + 8) * 132 + kb + t4 + 4];
            }
#pragma unroll
            for (int ni = 0; ni < 2; ni++) {
                int nb = wn * 16 + ni * 8 + g;
                bf[ni][0] = Vs[(kb + t4) * 68 + nb];
                bf[ni][1] = Vs[(kb + t4 + 4) * 68 + nb];
            }
#pragma unroll
            for (int mi = 0; mi < 4; mi++)
#pragma unroll
                for (int ni = 0; ni < 2; ni++)
                    mma8(acc_o[mi][ni], af[mi], bf[ni]);
        }
    }

#pragma unroll
    for (int mi = 0; mi < 4; mi++) {
        int row = m0 + wm * 64 + mi * 16 + g;
        float inv0 = 1.f / l_run[mi][0], inv1 = 1.f / l_run[mi][1];
#pragma unroll
        for (int ni = 0; ni < 2; ni++) {
            int col = h * 64 + wn * 16 + ni * 8 + t4 * 2;
            long o0 = ((long)b * NCC + row) * 256 + col;
            long o1 = ((long)b * NCC + row + 8) * 256 + col;
            *(float2*)&attno[o0] = make_float2(acc_o[mi][ni][0] * inv0, acc_o[mi][ni][1] * inv0);
            *(float2*)&attno[o1] = make_float2(acc_o[mi][ni][2] * inv1, acc_o[mi][ni][3] * inv1);
        }
    }
}

// ===================== flash cross-attention (reg-prefetch KV) =====================
// grid (32, 1, 16). Q tile 64x256, KV tiles 64x256 (K == V == rep2).
#define CROSS_SMEM ((2 * 64 * 260 + 64 * 68 + 256) * 4)

__global__ void __launch_bounds__(256) flash_cross_k(
    const float* __restrict__ qt, const float* __restrict__ rep2,
    float* __restrict__ det)
{
    extern __shared__ float sm[];
    float* Qs  = sm;
    float* KVs = sm + 64 * 260;
    float* Ps  = sm + 2 * 64 * 260;
    float* red = sm + 2 * 64 * 260 + 64 * 68;

    const int b = blockIdx.z;
    const int m0 = blockIdx.x * 64;
    const float* qb  = qt   + (long)b * NTT * 256;
    const float* kvb = rep2 + (long)b * NCC * 256;

    const int tid = threadIdx.x, wid = tid >> 5, lane = tid & 31;
    const int g = lane >> 2, t4 = lane & 3;
    const int wm = wid & 1, wn = wid >> 1;
    const int c4 = (tid & 63) * 4, r0 = tid >> 6;

#pragma unroll
    for (int p = 0; p < 16; p++) {
        int r = p * 4 + r0;
        float4 v = *(const float4*)(qb + (long)(m0 + r) * 256 + c4);
        *(float4*)&Qs[r * 260 + c4] = cvt4(v);
    }

    float4 rkv[16];
    auto loadKV = [&](int tk) {
#pragma unroll
        for (int p = 0; p < 16; p++) {
            int r = tk * 64 + p * 4 + r0;
            rkv[p] = *(const float4*)(kvb + (long)r * 256 + c4);
        }
    };
    auto stsKV = [&]() {
#pragma unroll
        for (int p = 0; p < 16; p++) {
            int r = p * 4 + r0;
            *(float4*)&KVs[r * 260 + c4] = cvt4(rkv[p]);
        }
    };

    float m_run[2][2], l_run[2][2], acc_o[2][8][4];
#pragma unroll
    for (int mi = 0; mi < 2; mi++)
#pragma unroll
        for (int hf = 0; hf < 2; hf++) { m_run[mi][hf] = -1e30f; l_run[mi][hf] = 0.f; }
#pragma unroll
    for (int mi = 0; mi < 2; mi++)
#pragma unroll
        for (int ni = 0; ni < 8; ni++)
#pragma unroll
            for (int c = 0; c < 4; c++) acc_o[mi][ni][c] = 0.f;

    loadKV(0);

    for (int tk = 0; tk < 16; tk++) {
        __syncthreads();
        stsKV();
        __syncthreads();
        if (tk + 1 < 16) loadKV(tk + 1);

        // ---- S = (1/16) Q KV^T ----
        float s[2][2][4];
#pragma unroll
        for (int mi = 0; mi < 2; mi++)
#pragma unroll
            for (int ni = 0; ni < 2; ni++)
#pragma unroll
                for (int c = 0; c < 4; c++) s[mi][ni][c] = 0.f;
#pragma unroll
        for (int ks = 0; ks < 32; ks++) {
            int kb = ks * 8;
            float af[2][4], bf[2][2];
#pragma unroll
            for (int mi = 0; mi < 2; mi++) {
                int ma = wm * 32 + mi * 16 + g;
                af[mi][0] = Qs[ma * 260 + kb + t4];
                af[mi][1] = Qs[(ma + 8) * 260 + kb + t4];
                af[mi][2] = Qs[ma * 260 + kb + t4 + 4];
                af[mi][3] = Qs[(ma + 8) * 260 + kb + t4 + 4];
            }
#pragma unroll
            for (int ni = 0; ni < 2; ni++) {
                int nb = wn * 16 + ni * 8 + g;
                bf[ni][0] = KVs[nb * 260 + kb + t4];
                bf[ni][1] = KVs[nb * 260 + kb + t4 + 4];
            }
#pragma unroll
            for (int mi = 0; mi < 2; mi++)
#pragma unroll
                for (int ni = 0; ni < 2; ni++)
                    mma8(s[mi][ni], af[mi], bf[ni]);
        }
#pragma unroll
        for (int mi = 0; mi < 2; mi++)
#pragma unroll
            for (int ni = 0; ni < 2; ni++)
#pragma unroll
                for (int c = 0; c < 4; c++) s[mi][ni][c] *= 0.0625f;

#pragma unroll
        for (int mi = 0; mi < 2; mi++)
#pragma unroll
            for (int hf = 0; hf < 2; hf++) {
                float lm = -1e30f;
#pragma unroll
                for (int ni = 0; ni < 2; ni++)
                    lm = fmaxf(lm, fmaxf(s[mi][ni][hf * 2], s[mi][ni][hf * 2 + 1]));
                lm = fmaxf(lm, __shfl_xor_sync(0xffffffffu, lm, 1));
                lm = fmaxf(lm, __shfl_xor_sync(0xffffffffu, lm, 2));
                if (t4 == 0) red[wn * 64 + wm * 32 + mi * 16 + hf * 8 + g] = lm;
            }
        __syncthreads();

        float fac[2][2], lsum[2][2];
#pragma unroll
        for (int mi = 0; mi < 2; mi++)
#pragma unroll
            for (int hf = 0; hf < 2; hf++) {
                int r = wm * 32 + mi * 16 + hf * 8 + g;
                float tm = fmaxf(fmaxf(red[r], red[64 + r]), fmaxf(red[128 + r], red[192 + r]));
                float mnew = fmaxf(m_run[mi][hf], tm);
                fac[mi][hf] = __expf(m_run[mi][hf] - mnew);
                m_run[mi][hf] = mnew;
                float ls = 0.f;
#pragma unroll
                for (int ni = 0; ni < 2; ni++) {
                    float p0 = __expf(s[mi][ni][hf * 2] - mnew);
                    float p1 = __expf(s[mi][ni][hf * 2 + 1] - mnew);
                    s[mi][ni][hf * 2] = p0; s[mi][ni][hf * 2 + 1] = p1;
                    ls += p0 + p1;
                }
                ls += __shfl_xor_sync(0xffffffffu, ls, 1);
                ls += __shfl_xor_sync(0xffffffffu, ls, 2);
                lsum[mi][hf] = ls;
            }
        __syncthreads();
#pragma unroll
        for (int mi = 0; mi < 2; mi++)
#pragma unroll
            for (int hf = 0; hf < 2; hf++)
                if (t4 == 0) red[wn * 64 + wm * 32 + mi * 16 + hf * 8 + g] = lsum[mi][hf];
        __syncthreads();
#pragma unroll
        for (int mi = 0; mi < 2; mi++)
#pragma unroll
            for (int hf = 0; hf < 2; hf++) {
                int r = wm * 32 + mi * 16 + hf * 8 + g;
                float ts = red[r] + red[64 + r] + red[128 + r] + red[192 + r];
                l_run[mi][hf] = l_run[mi][hf] * fac[mi][hf] + ts;
            }
#pragma unroll
        for (int mi = 0; mi < 2; mi++)
#pragma unroll
            for (int ni = 0; ni < 8; ni++) {
                acc_o[mi][ni][0] *= fac[mi][0]; acc_o[mi][ni][1] *= fac[mi][0];
                acc_o[mi][ni][2] *= fac[mi][1]; acc_o[mi][ni][3] *= fac[mi][1];
            }
#pragma unroll
        for (int mi = 0; mi < 2; mi++) {
            int r = wm * 32 + mi * 16 + g;
#pragma unroll
            for (int ni = 0; ni < 2; ni++) {
                int c = wn * 16 + ni * 8 + t4 * 2;
                Ps[r * 68 + c]           = to_tf32(s[mi][ni][0]);
                Ps[r * 68 + c + 1]       = to_tf32(s[mi][ni][1]);
                Ps[(r + 8) * 68 + c]     = to_tf32(s[mi][ni][2]);
                Ps[(r + 8) * 68 + c + 1] = to_tf32(s[mi][ni][3]);
            }
        }
        __syncthreads();

        // ---- O += P KV ----
#pragma unroll
        for (int ks = 0; ks < 8; ks++) {
            int kb = ks * 8;
            float af[2][4], bf[8][2];
#pragma unroll
            for (int mi = 0; mi < 2; mi++) {
                int ma = wm * 32 + mi * 16 + g;
                af[mi][0] = Ps[ma * 68 + kb + t4];
                af[mi][1] = Ps[(ma + 8) * 68 + kb + t4];
                af[mi][2] = Ps[ma * 68 + kb + t4 + 4];
                af[mi][3] = Ps[(ma + 8) * 68 + kb + t4 + 4];
            }
#pragma unroll
            for (int ni = 0; ni < 8; ni++) {
                int nb = wn * 64 + ni * 8 + g;
                bf[ni][0] = KVs[(kb + t4) * 260 + nb];
                bf[ni][1] = KVs[(kb + t4 + 4) * 260 + nb];
            }
#pragma unroll
            for (int mi = 0; mi < 2; mi++)
#pragma unroll
                for (int ni = 0; ni < 8; ni++)
                    mma8(acc_o[mi][ni], af[mi], bf[ni]);
        }
    }

#pragma unroll
    for (int mi = 0; mi < 2; mi++) {
        int row = m0 + wm * 32 + mi * 16 + g;
        float inv0 = 1.f / l_run[mi][0], inv1 = 1.f / l_run[mi][1];
#pragma unroll
        for (int ni = 0; ni < 8; ni++) {
            int col = wn * 64 + ni * 8 + t4 * 2;
            long o0 = ((long)b * NTT + row) * 256 + col;
            long o1 = ((long)b * NTT + row + 8) * 256 + col;
            *(float2*)&det[o0] = make_float2(acc_o[mi][ni][0] * inv0, acc_o[mi][ni][1] * inv0);
            *(float2*)&det[o1] = make_float2(acc_o[mi][ni][2] * inv1, acc_o[mi][ni][3] * inv1);
        }
    }
}

// ===================== small kernels =====================

__global__ void mean1_k(const float* __restrict__ h, float* __restrict__ part)
{
    int b = blockIdx.x, ch = blockIdx.y, j = threadIdx.x * 4;
    const float* p = h + (long)b * NCC * RD + (long)ch * 32 * RD + j;
    float4 s = make_float4(0.f, 0.f, 0.f, 0.f);
#pragma unroll 4
    for (int n = 0; n < 32; n++) {
        float4 v = *(const float4*)(p + (long)n * RD);
        s.x += v.x; s.y += v.y; s.z += v.z; s.w += v.w;
    }
    *(float4*)&part[(long)(b * 32 + ch) * RD + j] = s;
}

__global__ void mean2_k(const float* __restrict__ part, float* __restrict__ out)
{
    int b = blockIdx.x, j = threadIdx.x;
    float s = 0.f;
#pragma unroll
    for (int c = 0; c < 32; c++) s += part[(long)(b * 32 + c) * RD + j];
    out[b * RD + j] = s * (1.f / NCC);
}

__global__ void latent_k(const float* __restrict__ hmean,
                         const float* __restrict__ pw, const float* __restrict__ pb,
                         const float* __restrict__ mw, const float* __restrict__ mb,
                         const float* __restrict__ sw, const float* __restrict__ sb,
                         const float* __restrict__ eps, float* __restrict__ z)
{
    __shared__ float h2[LHD];
    int b = blockIdx.x, tid = threadIdx.x;
    if (tid < LHD) {
        float s = pb[tid];
        const float* hm = hmean + b * RD;
        for (int k = 0; k < RD; k++) s += hm[k] * pw[k * LHD + tid];
        h2[tid] = s;
    }
    __syncthreads();
    float mu = mb[tid], ls = sb[tid];
    for (int k = 0; k < LHD; k++) {
        mu += h2[k] * mw[k * RD + tid];
        ls += h2[k] * sw[k * RD + tid];
    }
    float sig = 0.9f / (1.f + expf(-ls)) + 0.1f;
    z[b * RD + tid] = mu + sig * eps[b * RD + tid];
}

__global__ void ln_k(const float* __restrict__ x, const float* __restrict__ y,
                     const float* __restrict__ g, const float* __restrict__ b,
                     float* __restrict__ out)
{
    __shared__ float sh[256];
    long row = blockIdx.x; int tid = threadIdx.x;
    float v = x[row * RD + tid] + y[row * RD + tid];
    sh[tid] = v; __syncthreads();
    for (int s = 128; s; s >>= 1) { if (tid < s) sh[tid] += sh[tid + s]; __syncthreads(); }
    float mean = sh[0] * (1.f / RD); __syncthreads();
    float d = v - mean;
    sh[tid] = d * d; __syncthreads();
    for (int s = 128; s; s >>= 1) { if (tid < s) sh[tid] += sh[tid + s]; __syncthreads(); }
    float var = sh[0] * (1.f / RD);
    out[row * RD + tid] = d * rsqrtf(var + 1e-5f) * g[tid] + b[tid];
}

// dec2 (K=128, N=16) fused with mu/sigma epilogue, writes final out
__global__ void __launch_bounds__(256) dec2_k(
    const float* __restrict__ dh, const float* __restrict__ w2,
    const float* __restrict__ b2, float* __restrict__ out)
{
    __shared__ float w[128][17];
    __shared__ float a[16][132];
    int tid = threadIdx.x;
    for (int i = tid; i < 128 * 16; i += 256) { int k = i >> 4, c = i & 15; w[k][c] = w2[i]; }
    long row0 = (long)blockIdx.x * 16;
    for (int i = tid; i < 512; i += 256) {
        int r = i >> 5, c4 = (i & 31) * 4;
        *(float4*)&a[r][c4] = *(const float4*)&dh[(row0 + r) * 128 + c4];
    }
    __syncthreads();
    int r = tid >> 4, c = tid & 15;
    float s = b2[c];
#pragma unroll
    for (int k = 0; k < 128; k++) s += a[r][k] * w[k][c];
    long row = row0 + r;
    const long TOT = (long)BB * NTT * CTRLD;
    if (c < CTRLD) out[row * CTRLD + c] = s;
    else {
        float sp = fmaxf(s, 0.f) + log1pf(expf(-fabsf(s)));
        out[TOT + row * CTRLD + (c - CTRLD)] = 0.9f * sp + 0.1f;
    }
}

// ===================== host side =====================

static float* sym(const void* s) { void* p = nullptr; cudaGetSymbolAddress(&p, s); return (float*)p; }

extern "C" void kernel_launch(void* const* d_in, const int* in_sizes, int n_in,
                              void* d_out, int out_size)
{
    const float* context_x = (const float*)d_in[0];
    const float* context_y = (const float*)d_in[1];
    const float* target_x  = (const float*)d_in[2];
    const float* pred_ctrl = (const float*)d_in[3];
    const float* eps       = (const float*)d_in[4];
    const float* ce_w1 = (const float*)d_in[5];  const float* ce_b1 = (const float*)d_in[6];
    const float* ce_w2 = (const float*)d_in[7];  const float* ce_b2 = (const float*)d_in[8];
    const float* sa_in_w = (const float*)d_in[9];  const float* sa_in_b = (const float*)d_in[10];
    const float* sa_out_w = (const float*)d_in[11]; const float* sa_out_b = (const float*)d_in[12];
    const float* sa_ln_g = (const float*)d_in[13];  const float* sa_ln_b = (const float*)d_in[14];
    const float* qp_w = (const float*)d_in[15]; const float* qp_b = (const float*)d_in[16];
    const float* le_w1 = (const float*)d_in[17]; const float* le_b1 = (const float*)d_in[18];
    const float* le_w2 = (const float*)d_in[19]; const float* le_b2 = (const float*)d_in[20];
    const float* le_pw = (const float*)d_in[21]; const float* le_pb = (const float*)d_in[22];
    const float* le_mw = (const float*)d_in[23]; const float* le_mb = (const float*)d_in[24];
    const float* le_sw = (const float*)d_in[25]; const float* le_sb = (const float*)d_in[26];
    const float* dec_w1 = (const float*)d_in[27]; const float* dec_b1 = (const float*)d_in[28];
    const float* dec_w2 = (const float*)d_in[29]; const float* dec_b2 = (const float*)d_in[30];
    float* out = (float*)d_out;

    float* h1    = sym(g_h1);
    float* rep   = sym(g_rep);
    float* hle   = sym(g_hle);
    float* part  = sym(g_part);
    float* hmean = sym(g_hmean);
    float* z     = sym(g_z);
    float* qkv   = sym(g_qkv);
    float* attno = sym(g_attno);
    float* oproj = sym(g_oproj);
    float* rep2  = sym(g_rep2);
    float* qt    = sym(g_qt);
    float* det   = sym(g_det);
    float* dh    = sym(g_dh);

    const int MC = BB * NCC;   // 16384
    const int MT = BB * NTT;   // 32768

    cudaFuncSetAttribute(flash_self_k,  cudaFuncAttributeMaxDynamicSharedMemorySize, SELF_SMEM);
    cudaFuncSetAttribute(flash_cross_k, cudaFuncAttributeMaxDynamicSharedMemorySize, CROSS_SMEM);

    // --- latent path (MLP1 gathers concat(cy,cx) directly) ---
    mma_gemm<32, 1, 2><<<dim3(MC / 128, 1, 1), 256>>>(nullptr, le_w1, le_b1, h1,
        MC, HIDD, CIN, CIN, HIDD, HIDD, 1.f, context_y, context_x, 0);
    mma_gemm<32, 0, 0><<<dim3(MC / 128, 2, 1), 256>>>(h1, le_w2, le_b2, hle,
        MC, RD, HIDD, HIDD, RD, RD, 1.f, 0, 0, 0);
    mean1_k<<<dim3(BB, 32), 64>>>(hle, part);
    mean2_k<<<BB, 256>>>(part, hmean);
    latent_k<<<BB, 256>>>(hmean, le_pw, le_pb, le_mw, le_mb, le_sw, le_sb, eps, z);

    // --- deterministic path ---
    mma_gemm<32, 1, 2><<<dim3(MC / 128, 1, 1), 256>>>(nullptr, ce_w1, ce_b1, h1,
        MC, HIDD, CIN, CIN, HIDD, HIDD, 1.f, context_y, context_x, 0);
    mma_gemm<32, 0, 0><<<dim3(MC / 128, 2, 1), 256>>>(h1, ce_w2, ce_b2, rep,
        MC, RD, HIDD, HIDD, RD, RD, 1.f, 0, 0, 0);

    mma_gemm<32, 0, 0><<<dim3(MC / 128, 6, 1), 256>>>(rep, sa_in_w, sa_in_b, qkv,
        MC, 3 * RD, RD, RD, 3 * RD, 3 * RD, 1.f, 0, 0, 0);

    flash_self_k<<<dim3(NCC / 128, NHD, BB), 256, SELF_SMEM>>>(qkv, attno);

    mma_gemm<32, 0, 0><<<dim3(MC / 128, 2, 1), 256>>>(attno, sa_out_w, sa_out_b, oproj,
        MC, RD, RD, RD, RD, RD, 1.f, 0, 0, 0);
    ln_k<<<MC, 256>>>(rep, oproj, sa_ln_g, sa_ln_b, rep2);

    // --- cross attention (fused) ---
    mma_gemm<32, 0, 0><<<dim3(MT / 128, 2, 1), 256>>>(target_x, qp_w, qp_b, qt,
        MT, RD, GAPD, GAPD, RD, RD, 1.f, 0, 0, 0);
    flash_cross_k<<<dim3(NTT / 64, 1, BB), 256, CROSS_SMEM>>>(qt, rep2, det);

    // --- decoder ---
    mma_gemm<32, 1, 1><<<dim3(MT / 128, 1, 1), 256>>>(det, dec_w1, dec_b1, dh,
        MT, HIDD, DIN, DIN, HIDD, HIDD, 1.f,
        z, target_x, pred_ctrl);
    dec2_k<<<MT / 16, 256>>>(dh, dec_w2, dec_b2, out);
}

// round 6
// speedup vs baseline: 4.1793x; 1.1274x over previous
#include <cuda_runtime.h>
#include <math.h>

// ---- problem dims ----
#define BB 16
#define NCC 1024
#define NTT 2048
#define GAPD 128
#define CTRLD 8
#define RD 256
#define NHD 4
#define HDD 64
#define HIDD 128
#define LHD 192
#define CIN (CTRLD + GAPD)          // 136
#define DIN (2 * RD + GAPD + CTRLD) // 648

// ---- scratch ----
__device__ float g_h12  [BB * NCC * 2 * HIDD];   // [le-h1 | ce-h1] cols 0..127 | 128..255
__device__ float g_rep  [BB * NCC * RD];
__device__ float g_hle  [BB * NCC * RD];
__device__ float g_part [BB * 32 * RD];
__device__ float g_hmean[BB * RD];
__device__ float g_z    [BB * RD];
__device__ float g_qkv  [BB * NCC * 3 * RD];
__device__ float g_attno[BB * NCC * RD];
__device__ float g_oproj[BB * NCC * RD];
__device__ float g_rep2 [BB * NCC * RD];
__device__ float g_qt   [BB * NTT * RD];
__device__ float g_det  [BB * NTT * RD];
__device__ float g_dh   [BB * NTT * HIDD];

// ===================== common mma helpers =====================
__device__ __forceinline__ float to_tf32(float x) {
    float r; asm("cvt.rna.tf32.f32 %0, %1;" : "=f"(r) : "f"(x)); return r;
}
__device__ __forceinline__ float4 cvt4(float4 v) {
    return make_float4(to_tf32(v.x), to_tf32(v.y), to_tf32(v.z), to_tf32(v.w));
}
__device__ __forceinline__ void mma8(float* d, const float* a, const float* b) {
    asm volatile(
        "mma.sync.aligned.m16n8k8.row.col.f32.tf32.tf32.f32 "
        "{%0,%1,%2,%3},{%4,%5,%6,%7},{%8,%9},{%0,%1,%2,%3};\n"
        : "+f"(d[0]), "+f"(d[1]), "+f"(d[2]), "+f"(d[3])
        : "r"(__float_as_uint(a[0])), "r"(__float_as_uint(a[1])),
          "r"(__float_as_uint(a[2])), "r"(__float_as_uint(a[3])),
          "r"(__float_as_uint(b[0])), "r"(__float_as_uint(b[1])));
}
__device__ __forceinline__ float4 ld_guard(const float* src, int gk, int K) {
    if (gk + 4 <= K) return *(const float4*)src;
    float4 v = make_float4(0.f, 0.f, 0.f, 0.f);
    if (gk     < K) v.x = src[0];
    if (gk + 1 < K) v.y = src[1];
    if (gk + 2 < K) v.z = src[2];
    if (gk + 3 < K) v.w = src[3];
    return v;
}

// ===================== tf32 GEMM (reg-pipelined), B = [K,N] row-major ====
#define XBM 128
#define XBK 32

// WNT: warp n-tile -> block N = 4*WNT.
// MODE 0: plain A.  MODE 1: A gathered from [det | z(bcast) | tx | pc], K=DIN.
// MODE 2: A gathered from [cy | cx], K=CIN (zt=cy, txt=cx).
// BMODE 1: B cols [0,128) from B, [128,256) from B2 (both ldb=128), biases likewise.
template<int WNT, int ACT, int MODE, int BMODE>
__global__ void __launch_bounds__(256) mma_gemm(
    const float* __restrict__ A, const float* __restrict__ B,
    const float* __restrict__ bias, float* __restrict__ C,
    int M, int N, int K, int lda, int ldb, int ldc,
    float alpha,
    const float* __restrict__ zt, const float* __restrict__ txt,
    const float* __restrict__ pct,
    const float* __restrict__ B2, const float* __restrict__ bias2)
{
    constexpr int XBN_ = WNT * 4;
    constexpr int NI = WNT / 8;
    constexpr int AST = XBK + 4;
    constexpr int BST = XBN_ + 8;

    __shared__ float As[XBM][AST];
    __shared__ float Bs[XBK][BST];

    int tid = threadIdx.x;
    int wid = tid >> 5, lane = tid & 31;
    int g = lane >> 2, t4 = lane & 3;
    int wm = wid & 1, wn = wid >> 1;
    int m0 = blockIdx.x * XBM, n0 = blockIdx.y * XBN_;

    float acc[4][NI][4];
#pragma unroll
    for (int i = 0; i < 4; i++)
#pragma unroll
        for (int j = 0; j < NI; j++)
#pragma unroll
            for (int l = 0; l < 4; l++) acc[i][j][l] = 0.f;

    float4 ra[4], rb[4];
    constexpr int C4  = XBN_ / 4;
    constexpr int RPI = 256 / C4;
    constexpr int ITS = XBK / RPI;

    const int ac = (tid & 7) * 4;
    const int ar = tid >> 3;
    const int bc4 = tid % C4;
    const int brb = tid / C4;

    auto loadA = [&](int k0) {
        int gk = k0 + ac;
#pragma unroll
        for (int p = 0; p < 4; p++) {
            int gm = m0 + p * 32 + ar;
            if (MODE == 1) {
                const float* s;
                if (gk < RD)                 s = A   + (long)gm * RD   + gk;
                else if (gk < 2 * RD)        s = zt  + (long)(gm >> 11) * RD + (gk - RD);
                else if (gk < 2 * RD + GAPD) s = txt + (long)gm * GAPD + (gk - 2 * RD);
                else if (gk < DIN)           s = pct + (long)gm * CTRLD + (gk - 2 * RD - GAPD);
                else                         s = nullptr;
                ra[p] = s ? *(const float4*)s : make_float4(0.f, 0.f, 0.f, 0.f);
            } else if (MODE == 2) {
                const float* s;
                if (gk < CTRLD)    s = zt  + (long)gm * CTRLD + gk;          // context_y
                else if (gk < CIN) s = txt + (long)gm * GAPD + (gk - CTRLD); // context_x
                else               s = nullptr;
                ra[p] = s ? *(const float4*)s : make_float4(0.f, 0.f, 0.f, 0.f);
            } else {
                ra[p] = ld_guard(A + (long)gm * lda + gk, gk, K);
            }
        }
    };
    auto loadB = [&](int k0) {
        int gn = n0 + bc4 * 4;
#pragma unroll
        for (int it = 0; it < ITS; it++) {
            int gk = k0 + it * RPI + brb;
            if (BMODE == 1) {
                const float* src = (gn < HIDD) ? (B  + (long)gk * ldb + gn)
                                               : (B2 + (long)gk * ldb + (gn - HIDD));
                rb[it] = (gk < K) ? *(const float4*)src : make_float4(0.f, 0.f, 0.f, 0.f);
            } else {
                rb[it] = (gk < K && gn + 3 < N) ? *(const float4*)(B + (long)gk * ldb + gn)
                                                : make_float4(0.f, 0.f, 0.f, 0.f);
            }
        }
    };
    auto stsAB = [&]() {
#pragma unroll
        for (int p = 0; p < 4; p++)
            *(float4*)&As[p * 32 + ar][ac] = cvt4(ra[p]);
#pragma unroll
        for (int it = 0; it < ITS; it++)
            *(float4*)&Bs[it * RPI + brb][bc4 * 4] = cvt4(rb[it]);
    };

    int kT = (K + XBK - 1) / XBK;
    loadA(0); loadB(0);

    for (int t = 0; t < kT; t++) {
        stsAB();
        __syncthreads();
        if (t + 1 < kT) { loadA((t + 1) * XBK); loadB((t + 1) * XBK); }
#pragma unroll
        for (int ks = 0; ks < 4; ks++) {
            int kb = ks * 8;
            float af[4][4], bf[NI][2];
#pragma unroll
            for (int mi = 0; mi < 4; mi++) {
                int ma = wm * 64 + mi * 16 + g;
                af[mi][0] = As[ma    ][kb + t4];
                af[mi][1] = As[ma + 8][kb + t4];
                af[mi][2] = As[ma    ][kb + t4 + 4];
                af[mi][3] = As[ma + 8][kb + t4 + 4];
            }
#pragma unroll
            for (int ni = 0; ni < NI; ni++) {
                int nb = wn * WNT + ni * 8 + g;
                bf[ni][0] = Bs[kb + t4    ][nb];
                bf[ni][1] = Bs[kb + t4 + 4][nb];
            }
#pragma unroll
            for (int mi = 0; mi < 4; mi++)
#pragma unroll
                for (int ni = 0; ni < NI; ni++)
                    mma8(acc[mi][ni], af[mi], bf[ni]);
        }
        __syncthreads();
    }

#pragma unroll
    for (int mi = 0; mi < 4; mi++) {
        int gm = m0 + wm * 64 + mi * 16 + g;
#pragma unroll
        for (int ni = 0; ni < NI; ni++) {
            int gn = n0 + wn * WNT + ni * 8 + t4 * 2;
            if (gn >= N) continue;
            float b0, b1;
            if (BMODE == 1) {
                const float* bp = (gn < HIDD) ? bias : bias2;
                int gq = (gn < HIDD) ? gn : gn - HIDD;
                b0 = bp[gq]; b1 = bp[gq + 1];
            } else {
                b0 = bias ? bias[gn] : 0.f;
                b1 = bias ? bias[gn + 1] : 0.f;
            }
            float v0 = acc[mi][ni][0] * alpha + b0;
            float v1 = acc[mi][ni][1] * alpha + b1;
            float v2 = acc[mi][ni][2] * alpha + b0;
            float v3 = acc[mi][ni][3] * alpha + b1;
            if (ACT == 1) {
                v0 = fmaxf(v0, 0.f); v1 = fmaxf(v1, 0.f);
                v2 = fmaxf(v2, 0.f); v3 = fmaxf(v3, 0.f);
            }
            *(float2*)&C[(long)gm * ldc + gn]       = make_float2(v0, v1);
            *(float2*)&C[(long)(gm + 8) * ldc + gn] = make_float2(v2, v3);
        }
    }
}

// ===================== flash self-attention (max-free softmax) =====================
// grid (8, 4, 16). Q tile 128x64, KV tiles 128x64.
// Scores here are tiny (|s|<~1): softmax without max-subtraction is exact and safe.
#define SELF_SMEM ((3 * 128 * 68 + 128 * 132 + 512) * 4)

__global__ void __launch_bounds__(256) flash_self_k(
    const float* __restrict__ qkv, float* __restrict__ attno)
{
    extern __shared__ float sm[];
    float* Qs  = sm;
    float* Ks  = sm + 128 * 68;
    float* Vs  = sm + 2 * 128 * 68;
    float* Ps  = sm + 3 * 128 * 68;
    float* red = sm + 3 * 128 * 68 + 128 * 132;

    const int b = blockIdx.z, h = blockIdx.y;
    const int m0 = blockIdx.x * 128;
    const float* base = qkv + (long)b * NCC * 768;
    const float* qp = base + h * 64;
    const float* kp = base + 256 + h * 64;
    const float* vp = base + 512 + h * 64;

    const int tid = threadIdx.x, wid = tid >> 5, lane = tid & 31;
    const int g = lane >> 2, t4 = lane & 3;
    const int wm = wid & 1, wn = wid >> 1;
    const int c4 = (tid & 15) * 4, r0 = tid >> 4;

#pragma unroll
    for (int p = 0; p < 8; p++) {
        int r = p * 16 + r0;
        float4 v = *(const float4*)(qp + (long)(m0 + r) * 768 + c4);
        *(float4*)&Qs[r * 68 + c4] = cvt4(v);
    }

    float4 rk[8], rv[8];
    auto loadKV = [&](int tk) {
#pragma unroll
        for (int p = 0; p < 8; p++) {
            int r = tk * 128 + p * 16 + r0;
            rk[p] = *(const float4*)(kp + (long)r * 768 + c4);
            rv[p] = *(const float4*)(vp + (long)r * 768 + c4);
        }
    };
    auto stsKV = [&]() {
#pragma unroll
        for (int p = 0; p < 8; p++) {
            int r = p * 16 + r0;
            *(float4*)&Ks[r * 68 + c4] = cvt4(rk[p]);
            *(float4*)&Vs[r * 68 + c4] = cvt4(rv[p]);
        }
    };

    float l_run[4][2], acc_o[4][2][4];
#pragma unroll
    for (int mi = 0; mi < 4; mi++)
#pragma unroll
        for (int hf = 0; hf < 2; hf++) l_run[mi][hf] = 0.f;
#pragma unroll
    for (int mi = 0; mi < 4; mi++)
#pragma unroll
        for (int ni = 0; ni < 2; ni++)
#pragma unroll
            for (int c = 0; c < 4; c++) acc_o[mi][ni][c] = 0.f;

    loadKV(0);

    for (int tk = 0; tk < 8; tk++) {
        __syncthreads();
        stsKV();
        __syncthreads();
        if (tk + 1 < 8) loadKV(tk + 1);

        // ---- S = Q K^T (scale folded into exp) ----
        float s[4][4][4];
#pragma unroll
        for (int mi = 0; mi < 4; mi++)
#pragma unroll
            for (int ni = 0; ni < 4; ni++)
#pragma unroll
                for (int c = 0; c < 4; c++) s[mi][ni][c] = 0.f;
#pragma unroll
        for (int ks = 0; ks < 8; ks++) {
            int kb = ks * 8;
            float af[4][4], bf[4][2];
#pragma unroll
            for (int mi = 0; mi < 4; mi++) {
                int ma = wm * 64 + mi * 16 + g;
                af[mi][0] = Qs[ma * 68 + kb + t4];
                af[mi][1] = Qs[(ma + 8) * 68 + kb + t4];
                af[mi][2] = Qs[ma * 68 + kb + t4 + 4];
                af[mi][3] = Qs[(ma + 8) * 68 + kb + t4 + 4];
            }
#pragma unroll
            for (int ni = 0; ni < 4; ni++) {
                int nb = wn * 32 + ni * 8 + g;
                bf[ni][0] = Ks[nb * 68 + kb + t4];
                bf[ni][1] = Ks[nb * 68 + kb + t4 + 4];
            }
#pragma unroll
            for (int mi = 0; mi < 4; mi++)
#pragma unroll
                for (int ni = 0; ni < 4; ni++)
                    mma8(s[mi][ni], af[mi], bf[ni]);
        }

        // ---- p = exp(s/8); row-sum only ----
#pragma unroll
        for (int mi = 0; mi < 4; mi++)
#pragma unroll
            for (int hf = 0; hf < 2; hf++) {
                float ls = 0.f;
#pragma unroll
                for (int ni = 0; ni < 4; ni++) {
                    float p0 = __expf(s[mi][ni][hf * 2]     * 0.125f);
                    float p1 = __expf(s[mi][ni][hf * 2 + 1] * 0.125f);
                    s[mi][ni][hf * 2] = p0; s[mi][ni][hf * 2 + 1] = p1;
                    ls += p0 + p1;
                }
                ls += __shfl_xor_sync(0xffffffffu, ls, 1);
                ls += __shfl_xor_sync(0xffffffffu, ls, 2);
                if (t4 == 0) red[wn * 128 + wm * 64 + mi * 16 + hf * 8 + g] = ls;
            }
        __syncthreads();
#pragma unroll
        for (int mi = 0; mi < 4; mi++)
#pragma unroll
            for (int hf = 0; hf < 2; hf++) {
                int r = wm * 64 + mi * 16 + hf * 8 + g;
                l_run[mi][hf] += red[r] + red[128 + r] + red[256 + r] + red[384 + r];
            }
        // write P (tf32)
#pragma unroll
        for (int mi = 0; mi < 4; mi++) {
            int r = wm * 64 + mi * 16 + g;
#pragma unroll
            for (int ni = 0; ni < 4; ni++) {
                int c = wn * 32 + ni * 8 + t4 * 2;
                Ps[r * 132 + c]           = to_tf32(s[mi][ni][0]);
                Ps[r * 132 + c + 1]       = to_tf32(s[mi][ni][1]);
                Ps[(r + 8) * 132 + c]     = to_tf32(s[mi][ni][2]);
                Ps[(r + 8) * 132 + c + 1] = to_tf32(s[mi][ni][3]);
            }
        }
        __syncthreads();

        // ---- O += P V ----
#pragma unroll
        for (int ks = 0; ks < 16; ks++) {
            int kb = ks * 8;
            float af[4][4], bf[2][2];
#pragma unroll
            for (int mi = 0; mi < 4; mi++) {
                int ma = wm * 64 + mi * 16 + g;
                af[mi][0] = Ps[ma * 132 + kb + t4];
                af[mi][1] = Ps[(ma + 8) * 132 + kb + t4];
                af[mi][2] = Ps[ma * 132 + kb + t4 + 4];
                af[mi][3] = Ps[(ma + 8) * 132 + kb + t4 + 4];
            }
#pragma unroll
            for (int ni = 0; ni < 2; ni++) {
                int nb = wn * 16 + ni * 8 + g;
                bf[ni][0] = Vs[(kb + t4) * 68 + nb];
                bf[ni][1] = Vs[(kb + t4 + 4) * 68 + nb];
            }
#pragma unroll
            for (int mi = 0; mi < 4; mi++)
#pragma unroll
                for (int ni = 0; ni < 2; ni++)
                    mma8(acc_o[mi][ni], af[mi], bf[ni]);
        }
    }

#pragma unroll
    for (int mi = 0; mi < 4; mi++) {
        int row = m0 + wm * 64 + mi * 16 + g;
        float inv0 = 1.f / l_run[mi][0], inv1 = 1.f / l_run[mi][1];
#pragma unroll
        for (int ni = 0; ni < 2; ni++) {
            int col = h * 64 + wn * 16 + ni * 8 + t4 * 2;
            long o0 = ((long)b * NCC + row) * 256 + col;
            long o1 = ((long)b * NCC + row + 8) * 256 + col;
            *(float2*)&attno[o0] = make_float2(acc_o[mi][ni][0] * inv0, acc_o[mi][ni][1] * inv0);
            *(float2*)&attno[o1] = make_float2(acc_o[mi][ni][2] * inv1, acc_o[mi][ni][3] * inv1);
        }
    }
}

// ===================== flash cross-attention (max-free softmax) =====================
// grid (32, 1, 16). Q tile 64x256, KV tiles 64x256 (K == V == rep2).
#define CROSS_SMEM ((2 * 64 * 260 + 64 * 68 + 256) * 4)

__global__ void __launch_bounds__(256) flash_cross_k(
    const float* __restrict__ qt, const float* __restrict__ rep2,
    float* __restrict__ det)
{
    extern __shared__ float sm[];
    float* Qs  = sm;
    float* KVs = sm + 64 * 260;
    float* Ps  = sm + 2 * 64 * 260;
    float* red = sm + 2 * 64 * 260 + 64 * 68;

    const int b = blockIdx.z;
    const int m0 = blockIdx.x * 64;
    const float* qb  = qt   + (long)b * NTT * 256;
    const float* kvb = rep2 + (long)b * NCC * 256;

    const int tid = threadIdx.x, wid = tid >> 5, lane = tid & 31;
    const int g = lane >> 2, t4 = lane & 3;
    const int wm = wid & 1, wn = wid >> 1;
    const int c4 = (tid & 63) * 4, r0 = tid >> 6;

#pragma unroll
    for (int p = 0; p < 16; p++) {
        int r = p * 4 + r0;
        float4 v = *(const float4*)(qb + (long)(m0 + r) * 256 + c4);
        *(float4*)&Qs[r * 260 + c4] = cvt4(v);
    }

    float4 rkv[16];
    auto loadKV = [&](int tk) {
#pragma unroll
        for (int p = 0; p < 16; p++) {
            int r = tk * 64 + p * 4 + r0;
            rkv[p] = *(const float4*)(kvb + (long)r * 256 + c4);
        }
    };
    auto stsKV = [&]() {
#pragma unroll
        for (int p = 0; p < 16; p++) {
            int r = p * 4 + r0;
            *(float4*)&KVs[r * 260 + c4] = cvt4(rkv[p]);
        }
    };

    float l_run[2][2], acc_o[2][8][4];
#pragma unroll
    for (int mi = 0; mi < 2; mi++)
#pragma unroll
        for (int hf = 0; hf < 2; hf++) l_run[mi][hf] = 0.f;
#pragma unroll
    for (int mi = 0; mi < 2; mi++)
#pragma unroll
        for (int ni = 0; ni < 8; ni++)
#pragma unroll
            for (int c = 0; c < 4; c++) acc_o[mi][ni][c] = 0.f;

    loadKV(0);

    for (int tk = 0; tk < 16; tk++) {
        __syncthreads();
        stsKV();
        __syncthreads();
        if (tk + 1 < 16) loadKV(tk + 1);

        // ---- S = Q KV^T (scale folded into exp) ----
        float s[2][2][4];
#pragma unroll
        for (int mi = 0; mi < 2; mi++)
#pragma unroll
            for (int ni = 0; ni < 2; ni++)
#pragma unroll
                for (int c = 0; c < 4; c++) s[mi][ni][c] = 0.f;
#pragma unroll
        for (int ks = 0; ks < 32; ks++) {
            int kb = ks * 8;
            float af[2][4], bf[2][2];
#pragma unroll
            for (int mi = 0; mi < 2; mi++) {
                int ma = wm * 32 + mi * 16 + g;
                af[mi][0] = Qs[ma * 260 + kb + t4];
                af[mi][1] = Qs[(ma + 8) * 260 + kb + t4];
                af[mi][2] = Qs[ma * 260 + kb + t4 + 4];
                af[mi][3] = Qs[(ma + 8) * 260 + kb + t4 + 4];
            }
#pragma unroll
            for (int ni = 0; ni < 2; ni++) {
                int nb = wn * 16 + ni * 8 + g;
                bf[ni][0] = KVs[nb * 260 + kb + t4];
                bf[ni][1] = KVs[nb * 260 + kb + t4 + 4];
            }
#pragma unroll
            for (int mi = 0; mi < 2; mi++)
#pragma unroll
                for (int ni = 0; ni < 2; ni++)
                    mma8(s[mi][ni], af[mi], bf[ni]);
        }

        // ---- p = exp(s/16); row-sum only ----
#pragma unroll
        for (int mi = 0; mi < 2; mi++)
#pragma unroll
            for (int hf = 0; hf < 2; hf++) {
                float ls = 0.f;
#pragma unroll
                for (int ni = 0; ni < 2; ni++) {
                    float p0 = __expf(s[mi][ni][hf * 2]     * 0.0625f);
                    float p1 = __expf(s[mi][ni][hf * 2 + 1] * 0.0625f);
                    s[mi][ni][hf * 2] = p0; s[mi][ni][hf * 2 + 1] = p1;
                    ls += p0 + p1;
                }
                ls += __shfl_xor_sync(0xffffffffu, ls, 1);
                ls += __shfl_xor_sync(0xffffffffu, ls, 2);
                if (t4 == 0) red[wn * 64 + wm * 32 + mi * 16 + hf * 8 + g] = ls;
            }
        __syncthreads();
#pragma unroll
        for (int mi = 0; mi < 2; mi++)
#pragma unroll
            for (int hf = 0; hf < 2; hf++) {
                int r = wm * 32 + mi * 16 + hf * 8 + g;
                l_run[mi][hf] += red[r] + red[64 + r] + red[128 + r] + red[192 + r];
            }
#pragma unroll
        for (int mi = 0; mi < 2; mi++) {
            int r = wm * 32 + mi * 16 + g;
#pragma unroll
            for (int ni = 0; ni < 2; ni++) {
                int c = wn * 16 + ni * 8 + t4 * 2;
                Ps[r * 68 + c]           = to_tf32(s[mi][ni][0]);
                Ps[r * 68 + c + 1]       = to_tf32(s[mi][ni][1]);
                Ps[(r + 8) * 68 + c]     = to_tf32(s[mi][ni][2]);
                Ps[(r + 8) * 68 + c + 1] = to_tf32(s[mi][ni][3]);
            }
        }
        __syncthreads();

        // ---- O += P KV ----
#pragma unroll
        for (int ks = 0; ks < 8; ks++) {
            int kb = ks * 8;
            float af[2][4], bf[8][2];
#pragma unroll
            for (int mi = 0; mi < 2; mi++) {
                int ma = wm * 32 + mi * 16 + g;
                af[mi][0] = Ps[ma * 68 + kb + t4];
                af[mi][1] = Ps[(ma + 8) * 68 + kb + t4];
                af[mi][2] = Ps[ma * 68 + kb + t4 + 4];
                af[mi][3] = Ps[(ma + 8) * 68 + kb + t4 + 4];
            }
#pragma unroll
            for (int ni = 0; ni < 8; ni++) {
                int nb = wn * 64 + ni * 8 + g;
                bf[ni][0] = KVs[(kb + t4) * 260 + nb];
                bf[ni][1] = KVs[(kb + t4 + 4) * 260 + nb];
            }
#pragma unroll
            for (int mi = 0; mi < 2; mi++)
#pragma unroll
                for (int ni = 0; ni < 8; ni++)
                    mma8(acc_o[mi][ni], af[mi], bf[ni]);
        }
    }

#pragma unroll
    for (int mi = 0; mi < 2; mi++) {
        int row = m0 + wm * 32 + mi * 16 + g;
        float inv0 = 1.f / l_run[mi][0], inv1 = 1.f / l_run[mi][1];
#pragma unroll
        for (int ni = 0; ni < 8; ni++) {
            int col = wn * 64 + ni * 8 + t4 * 2;
            long o0 = ((long)b * NTT + row) * 256 + col;
            long o1 = ((long)b * NTT + row + 8) * 256 + col;
            *(float2*)&det[o0] = make_float2(acc_o[mi][ni][0] * inv0, acc_o[mi][ni][1] * inv0);
            *(float2*)&det[o1] = make_float2(acc_o[mi][ni][2] * inv1, acc_o[mi][ni][3] * inv1);
        }
    }
}

// ===================== small kernels =====================

__global__ void mean1_k(const float* __restrict__ h, float* __restrict__ part)
{
    int b = blockIdx.x, ch = blockIdx.y, j = threadIdx.x * 4;
    const float* p = h + (long)b * NCC * RD + (long)ch * 32 * RD + j;
    float4 s = make_float4(0.f, 0.f, 0.f, 0.f);
#pragma unroll 4
    for (int n = 0; n < 32; n++) {
        float4 v = *(const float4*)(p + (long)n * RD);
        s.x += v.x; s.y += v.y; s.z += v.z; s.w += v.w;
    }
    *(float4*)&part[(long)(b * 32 + ch) * RD + j] = s;
}

__global__ void mean2_k(const float* __restrict__ part, float* __restrict__ out)
{
    int b = blockIdx.x, j = threadIdx.x;
    float s = 0.f;
#pragma unroll
    for (int c = 0; c < 32; c++) s += part[(long)(b * 32 + c) * RD + j];
    out[b * RD + j] = s * (1.f / NCC);
}

__global__ void latent_k(const float* __restrict__ hmean,
                         const float* __restrict__ pw, const float* __restrict__ pb,
                         const float* __restrict__ mw, const float* __restrict__ mb,
                         const float* __restrict__ sw, const float* __restrict__ sb,
                         const float* __restrict__ eps, float* __restrict__ z)
{
    __shared__ float h2[LHD];
    int b = blockIdx.x, tid = threadIdx.x;
    if (tid < LHD) {
        float s = pb[tid];
        const float* hm = hmean + b * RD;
        for (int k = 0; k < RD; k++) s += hm[k] * pw[k * LHD + tid];
        h2[tid] = s;
    }
    __syncthreads();
    float mu = mb[tid], ls = sb[tid];
    for (int k = 0; k < LHD; k++) {
        mu += h2[k] * mw[k * RD + tid];
        ls += h2[k] * sw[k * RD + tid];
    }
    float sig = 0.9f / (1.f + expf(-ls)) + 0.1f;
    z[b * RD + tid] = mu + sig * eps[b * RD + tid];
}

// residual + layernorm: one warp per 256-wide row, shfl-only reductions
__global__ void __launch_bounds__(256) ln_k(
    const float* __restrict__ x, const float* __restrict__ y,
    const float* __restrict__ g, const float* __restrict__ b,
    float* __restrict__ out)
{
    int w = threadIdx.x >> 5, lane = threadIdx.x & 31;
    long row = (long)blockIdx.x * 8 + w;
    const float4* xr = (const float4*)(x + row * RD);
    const float4* yr = (const float4*)(y + row * RD);
    float4 a0 = xr[lane], a1 = xr[lane + 32];
    float4 c0 = yr[lane], c1 = yr[lane + 32];
    a0.x += c0.x; a0.y += c0.y; a0.z += c0.z; a0.w += c0.w;
    a1.x += c1.x; a1.y += c1.y; a1.z += c1.z; a1.w += c1.w;

    float sum = a0.x + a0.y + a0.z + a0.w + a1.x + a1.y + a1.z + a1.w;
#pragma unroll
    for (int o = 16; o; o >>= 1) sum += __shfl_xor_sync(0xffffffffu, sum, o);
    float mean = sum * (1.f / RD);

    float d0x = a0.x - mean, d0y = a0.y - mean, d0z = a0.z - mean, d0w = a0.w - mean;
    float d1x = a1.x - mean, d1y = a1.y - mean, d1z = a1.z - mean, d1w = a1.w - mean;
    float vs = d0x * d0x + d0y * d0y + d0z * d0z + d0w * d0w
             + d1x * d1x + d1y * d1y + d1z * d1z + d1w * d1w;
#pragma unroll
    for (int o = 16; o; o >>= 1) vs += __shfl_xor_sync(0xffffffffu, vs, o);
    float inv = rsqrtf(vs * (1.f / RD) + 1e-5f);

    float4 g0 = ((const float4*)g)[lane], g1 = ((const float4*)g)[lane + 32];
    float4 b0 = ((const float4*)b)[lane], b1 = ((const float4*)b)[lane + 32];
    float4 o0 = make_float4(d0x * inv * g0.x + b0.x, d0y * inv * g0.y + b0.y,
                            d0z * inv * g0.z + b0.z, d0w * inv * g0.w + b0.w);
    float4 o1 = make_float4(d1x * inv * g1.x + b1.x, d1y * inv * g1.y + b1.y,
                            d1z * inv * g1.z + b1.z, d1w * inv * g1.w + b1.w);
    ((float4*)(out + row * RD))[lane] = o0;
    ((float4*)(out + row * RD))[lane + 32] = o1;
}

// dec2 (K=128, N=16) fused with mu/sigma epilogue, writes final out
__global__ void __launch_bounds__(256) dec2_k(
    const float* __restrict__ dh, const float* __restrict__ w2,
    const float* __restrict__ b2, float* __restrict__ out)
{
    __shared__ float w[128][17];
    __shared__ float a[16][132];
    int tid = threadIdx.x;
    for (int i = tid; i < 128 * 16; i += 256) { int k = i >> 4, c = i & 15; w[k][c] = w2[i]; }
    long row0 = (long)blockIdx.x * 16;
    for (int i = tid; i < 512; i += 256) {
        int r = i >> 5, c4 = (i & 31) * 4;
        *(float4*)&a[r][c4] = *(const float4*)&dh[(row0 + r) * 128 + c4];
    }
    __syncthreads();
    int r = tid >> 4, c = tid & 15;
    float s = b2[c];
#pragma unroll
    for (int k = 0; k < 128; k++) s += a[r][k] * w[k][c];
    long row = row0 + r;
    const long TOT = (long)BB * NTT * CTRLD;
    if (c < CTRLD) out[row * CTRLD + c] = s;
    else {
        float sp = fmaxf(s, 0.f) + log1pf(expf(-fabsf(s)));
        out[TOT + row * CTRLD + (c - CTRLD)] = 0.9f * sp + 0.1f;
    }
}

// ===================== host side =====================

static float* sym(const void* s) { void* p = nullptr; cudaGetSymbolAddress(&p, s); return (float*)p; }

extern "C" void kernel_launch(void* const* d_in, const int* in_sizes, int n_in,
                              void* d_out, int out_size)
{
    const float* context_x = (const float*)d_in[0];
    const float* context_y = (const float*)d_in[1];
    const float* target_x  = (const float*)d_in[2];
    const float* pred_ctrl = (const float*)d_in[3];
    const float* eps       = (const float*)d_in[4];
    const float* ce_w1 = (const float*)d_in[5];  const float* ce_b1 = (const float*)d_in[6];
    const float* ce_w2 = (const float*)d_in[7];  const float* ce_b2 = (const float*)d_in[8];
    const float* sa_in_w = (const float*)d_in[9];  const float* sa_in_b = (const float*)d_in[10];
    const float* sa_out_w = (const float*)d_in[11]; const float* sa_out_b = (const float*)d_in[12];
    const float* sa_ln_g = (const float*)d_in[13];  const float* sa_ln_b = (const float*)d_in[14];
    const float* qp_w = (const float*)d_in[15]; const float* qp_b = (const float*)d_in[16];
    const float* le_w1 = (const float*)d_in[17]; const float* le_b1 = (const float*)d_in[18];
    const float* le_w2 = (const float*)d_in[19]; const float* le_b2 = (const float*)d_in[20];
    const float* le_pw = (const float*)d_in[21]; const float* le_pb = (const float*)d_in[22];
    const float* le_mw = (const float*)d_in[23]; const float* le_mb = (const float*)d_in[24];
    const float* le_sw = (const float*)d_in[25]; const float* le_sb = (const float*)d_in[26];
    const float* dec_w1 = (const float*)d_in[27]; const float* dec_b1 = (const float*)d_in[28];
    const float* dec_w2 = (const float*)d_in[29]; const float* dec_b2 = (const float*)d_in[30];
    float* out = (float*)d_out;

    float* h12   = sym(g_h12);
    float* rep   = sym(g_rep);
    float* hle   = sym(g_hle);
    float* part  = sym(g_part);
    float* hmean = sym(g_hmean);
    float* z     = sym(g_z);
    float* qkv   = sym(g_qkv);
    float* attno = sym(g_attno);
    float* oproj = sym(g_oproj);
    float* rep2  = sym(g_rep2);
    float* qt    = sym(g_qt);
    float* det   = sym(g_det);
    float* dh    = sym(g_dh);

    const int MC = BB * NCC;   // 16384
    const int MT = BB * NTT;   // 32768

    static cudaStream_t s2 = nullptr;
    static cudaEvent_t evA = nullptr, evB = nullptr;
    if (!s2) {
        cudaStreamCreateWithFlags(&s2, cudaStreamNonBlocking);
        cudaEventCreateWithFlags(&evA, cudaEventDisableTiming);
        cudaEventCreateWithFlags(&evB, cudaEventDisableTiming);
    }

    cudaFuncSetAttribute(flash_self_k,  cudaFuncAttributeMaxDynamicSharedMemorySize, SELF_SMEM);
    cudaFuncSetAttribute(flash_cross_k, cudaFuncAttributeMaxDynamicSharedMemorySize, CROSS_SMEM);

    // --- merged MLP1 (le|ce), A gathered from concat(cy,cx), N = 256 ---
    mma_gemm<32, 1, 2, 1><<<dim3(MC / 128, 2, 1), 256>>>(nullptr, le_w1, le_b1, h12,
        MC, 2 * HIDD, CIN, CIN, HIDD, 2 * HIDD, 1.f, context_y, context_x, nullptr,
        ce_w1, ce_b1);

    // --- fork: latent path on s2 ---
    cudaEventRecord(evA, 0);
    cudaStreamWaitEvent(s2, evA, 0);
    mma_gemm<32, 0, 0, 0><<<dim3(MC / 128, 2, 1), 256, 0, s2>>>(h12, le_w2, le_b2, hle,
        MC, RD, HIDD, 2 * HIDD, RD, RD, 1.f, nullptr, nullptr, nullptr, nullptr, nullptr);
    mean1_k<<<dim3(BB, 32), 64, 0, s2>>>(hle, part);
    mean2_k<<<BB, 256, 0, s2>>>(part, hmean);
    latent_k<<<BB, 256, 0, s2>>>(hmean, le_pw, le_pb, le_mw, le_mb, le_sw, le_sb, eps, z);
    cudaEventRecord(evB, s2);

    // --- deterministic path on main stream ---
    mma_gemm<32, 0, 0, 0><<<dim3(MC / 128, 2, 1), 256>>>(h12 + HIDD, ce_w2, ce_b2, rep,
        MC, RD, HIDD, 2 * HIDD, RD, RD, 1.f, nullptr, nullptr, nullptr, nullptr, nullptr);

    mma_gemm<32, 0, 0, 0><<<dim3(MC / 128, 6, 1), 256>>>(rep, sa_in_w, sa_in_b, qkv,
        MC, 3 * RD, RD, RD, 3 * RD, 3 * RD, 1.f, nullptr, nullptr, nullptr, nullptr, nullptr);

    flash_self_k<<<dim3(NCC / 128, NHD, BB), 256, SELF_SMEM>>>(qkv, attno);

    mma_gemm<32, 0, 0, 0><<<dim3(MC / 128, 2, 1), 256>>>(attno, sa_out_w, sa_out_b, oproj,
        MC, RD, RD, RD, RD, RD, 1.f, nullptr, nullptr, nullptr, nullptr, nullptr);
    ln_k<<<MC / 8, 256>>>(rep, oproj, sa_ln_g, sa_ln_b, rep2);

    mma_gemm<32, 0, 0, 0><<<dim3(MT / 128, 2, 1), 256>>>(target_x, qp_w, qp_b, qt,
        MT, RD, GAPD, GAPD, RD, RD, 1.f, nullptr, nullptr, nullptr, nullptr, nullptr);
    flash_cross_k<<<dim3(NTT / 64, 1, BB), 256, CROSS_SMEM>>>(qt, rep2, det);

    // --- join latent path, then decoder ---
    cudaStreamWaitEvent(0, evB, 0);
    mma_gemm<32, 1, 1, 0><<<dim3(MT / 128, 1, 1), 256>>>(det, dec_w1, dec_b1, dh,
        MT, HIDD, DIN, DIN, HIDD, HIDD, 1.f, z, target_x, pred_ctrl, nullptr, nullptr);
    dec2_k<<<MT / 16, 256>>>(dh, dec_w2, dec_b2, out);
}

// round 8
// speedup vs baseline: 4.1899x; 1.0025x over previous
#include <cuda_runtime.h>
#include <math.h>

// ---- problem dims ----
#define BB 16
#define NCC 1024
#define NTT 2048
#define GAPD 128
#define CTRLD 8
#define RD 256
#define NHD 4
#define HDD 64
#define HIDD 128
#define LHD 192
#define CIN (CTRLD + GAPD)          // 136
#define DIN (2 * RD + GAPD + CTRLD) // 648

// ---- scratch ----
__device__ float g_h12  [BB * NCC * 2 * HIDD];   // [le-h1 | ce-h1]
__device__ float g_rep  [BB * NCC * RD];
__device__ float g_hle  [BB * NCC * RD];
__device__ float g_part [BB * 32 * RD];
__device__ float g_hmean[BB * RD];
__device__ float g_z    [BB * RD];
__device__ float g_qkv  [BB * NCC * 3 * RD];
__device__ float g_attno[BB * NCC * RD];
__device__ float g_oproj[BB * NCC * RD];
__device__ float g_rep2 [BB * NCC * RD];
__device__ float g_qt   [BB * NTT * RD];
__device__ float g_det  [BB * NTT * RD];
__device__ float g_dh   [BB * NTT * HIDD];

// ===================== common mma helpers =====================
__device__ __forceinline__ float to_tf32(float x) {
    float r; asm("cvt.rna.tf32.f32 %0, %1;" : "=f"(r) : "f"(x)); return r;
}
__device__ __forceinline__ float4 cvt4(float4 v) {
    return make_float4(to_tf32(v.x), to_tf32(v.y), to_tf32(v.z), to_tf32(v.w));
}
__device__ __forceinline__ void mma8(float* d, const float* a, const float* b) {
    asm volatile(
        "mma.sync.aligned.m16n8k8.row.col.f32.tf32.tf32.f32 "
        "{%0,%1,%2,%3},{%4,%5,%6,%7},{%8,%9},{%0,%1,%2,%3};\n"
        : "+f"(d[0]), "+f"(d[1]), "+f"(d[2]), "+f"(d[3])
        : "r"(__float_as_uint(a[0])), "r"(__float_as_uint(a[1])),
          "r"(__float_as_uint(a[2])), "r"(__float_as_uint(a[3])),
          "r"(__float_as_uint(b[0])), "r"(__float_as_uint(b[1])));
}
__device__ __forceinline__ float4 ld_guard(const float* src, int gk, int K) {
    if (gk + 4 <= K) return *(const float4*)src;
    float4 v = make_float4(0.f, 0.f, 0.f, 0.f);
    if (gk     < K) v.x = src[0];
    if (gk + 1 < K) v.y = src[1];
    if (gk + 2 < K) v.z = src[2];
    if (gk + 3 < K) v.w = src[3];
    return v;
}
// interleave within 8-col group: cols (t4, t4+4) -> adjacent (2t4, 2t4+1)
__device__ __forceinline__ int P8(int c) {
    return (c & ~7) | ((c & 3) << 1) | ((c >> 2) & 1);
}

// ===================== tf32 GEMM (reg-pipelined), B = [K,N] row-major ====
#define XBM 128
#define XBK 32

// MODE 0: plain A. MODE 1: A = [det | z | tx | pc], K=DIN. MODE 2: A = [cy | cx], K=CIN.
// BMODE 1: B cols [0,128) from B, [128,256) from B2; biases likewise.
template<int WNT, int ACT, int MODE, int BMODE>
__global__ void __launch_bounds__(256) mma_gemm(
    const float* __restrict__ A, const float* __restrict__ B,
    const float* __restrict__ bias, float* __restrict__ C,
    int M, int N, int K, int lda, int ldb, int ldc,
    float alpha,
    const float* __restrict__ zt, const float* __restrict__ txt,
    const float* __restrict__ pct,
    const float* __restrict__ B2, const float* __restrict__ bias2)
{
    constexpr int XBN_ = WNT * 4;
    constexpr int NI = WNT / 8;
    constexpr int AST = XBK + 4;
    constexpr int BST = XBN_ + 8;

    __shared__ float As[XBM][AST];
    __shared__ float Bs[XBK][BST];

    int tid = threadIdx.x;
    int wid = tid >> 5, lane = tid & 31;
    int g = lane >> 2, t4 = lane & 3;
    int wm = wid & 1, wn = wid >> 1;
    int m0 = blockIdx.x * XBM, n0 = blockIdx.y * XBN_;

    float acc[4][NI][4];
#pragma unroll
    for (int i = 0; i < 4; i++)
#pragma unroll
        for (int j = 0; j < NI; j++)
#pragma unroll
            for (int l = 0; l < 4; l++) acc[i][j][l] = 0.f;

    float4 ra[4], rb[4];
    constexpr int C4  = XBN_ / 4;
    constexpr int RPI = 256 / C4;
    constexpr int ITS = XBK / RPI;

    const int ac = (tid & 7) * 4;
    const int ar = tid >> 3;
    const int bc4 = tid % C4;
    const int brb = tid / C4;

    auto loadA = [&](int k0) {
        int gk = k0 + ac;
#pragma unroll
        for (int p = 0; p < 4; p++) {
            int gm = m0 + p * 32 + ar;
            if (MODE == 1) {
                const float* s;
                if (gk < RD)                 s = A   + (long)gm * RD   + gk;
                else if (gk < 2 * RD)        s = zt  + (long)(gm >> 11) * RD + (gk - RD);
                else if (gk < 2 * RD + GAPD) s = txt + (long)gm * GAPD + (gk - 2 * RD);
                else if (gk < DIN)           s = pct + (long)gm * CTRLD + (gk - 2 * RD - GAPD);
                else                         s = nullptr;
                ra[p] = s ? *(const float4*)s : make_float4(0.f, 0.f, 0.f, 0.f);
            } else if (MODE == 2) {
                const float* s;
                if (gk < CTRLD)    s = zt  + (long)gm * CTRLD + gk;
                else if (gk < CIN) s = txt + (long)gm * GAPD + (gk - CTRLD);
                else               s = nullptr;
                ra[p] = s ? *(const float4*)s : make_float4(0.f, 0.f, 0.f, 0.f);
            } else {
                ra[p] = ld_guard(A + (long)gm * lda + gk, gk, K);
            }
        }
    };
    auto loadB = [&](int k0) {
        int gn = n0 + bc4 * 4;
#pragma unroll
        for (int it = 0; it < ITS; it++) {
            int gk = k0 + it * RPI + brb;
            if (BMODE == 1) {
                const float* src = (gn < HIDD) ? (B  + (long)gk * ldb + gn)
                                               : (B2 + (long)gk * ldb + (gn - HIDD));
                rb[it] = (gk < K) ? *(const float4*)src : make_float4(0.f, 0.f, 0.f, 0.f);
            } else {
                rb[it] = (gk < K && gn + 3 < N) ? *(const float4*)(B + (long)gk * ldb + gn)
                                                : make_float4(0.f, 0.f, 0.f, 0.f);
            }
        }
    };
    auto stsAB = [&]() {
#pragma unroll
        for (int p = 0; p < 4; p++)
            *(float4*)&As[p * 32 + ar][ac] = cvt4(ra[p]);
#pragma unroll
        for (int it = 0; it < ITS; it++)
            *(float4*)&Bs[it * RPI + brb][bc4 * 4] = cvt4(rb[it]);
    };

    int kT = (K + XBK - 1) / XBK;
    loadA(0); loadB(0);

    for (int t = 0; t < kT; t++) {
        stsAB();
        __syncthreads();
        if (t + 1 < kT) { loadA((t + 1) * XBK); loadB((t + 1) * XBK); }
#pragma unroll
        for (int ks = 0; ks < 4; ks++) {
            int kb = ks * 8;
            float af[4][4], bf[NI][2];
#pragma unroll
            for (int mi = 0; mi < 4; mi++) {
                int ma = wm * 64 + mi * 16 + g;
                af[mi][0] = As[ma    ][kb + t4];
                af[mi][1] = As[ma + 8][kb + t4];
                af[mi][2] = As[ma    ][kb + t4 + 4];
                af[mi][3] = As[ma + 8][kb + t4 + 4];
            }
#pragma unroll
            for (int ni = 0; ni < NI; ni++) {
                int nb = wn * WNT + ni * 8 + g;
                bf[ni][0] = Bs[kb + t4    ][nb];
                bf[ni][1] = Bs[kb + t4 + 4][nb];
            }
#pragma unroll
            for (int mi = 0; mi < 4; mi++)
#pragma unroll
                for (int ni = 0; ni < NI; ni++)
                    mma8(acc[mi][ni], af[mi], bf[ni]);
        }
        __syncthreads();
    }

#pragma unroll
    for (int mi = 0; mi < 4; mi++) {
        int gm = m0 + wm * 64 + mi * 16 + g;
#pragma unroll
        for (int ni = 0; ni < NI; ni++) {
            int gn = n0 + wn * WNT + ni * 8 + t4 * 2;
            if (gn >= N) continue;
            float b0, b1;
            if (BMODE == 1) {
                const float* bp = (gn < HIDD) ? bias : bias2;
                int gq = (gn < HIDD) ? gn : gn - HIDD;
                b0 = bp[gq]; b1 = bp[gq + 1];
            } else {
                b0 = bias ? bias[gn] : 0.f;
                b1 = bias ? bias[gn + 1] : 0.f;
            }
            float v0 = acc[mi][ni][0] * alpha + b0;
            float v1 = acc[mi][ni][1] * alpha + b1;
            float v2 = acc[mi][ni][2] * alpha + b0;
            float v3 = acc[mi][ni][3] * alpha + b1;
            if (ACT == 1) {
                v0 = fmaxf(v0, 0.f); v1 = fmaxf(v1, 0.f);
                v2 = fmaxf(v2, 0.f); v3 = fmaxf(v3, 0.f);
            }
            *(float2*)&C[(long)gm * ldc + gn]       = make_float2(v0, v1);
            *(float2*)&C[(long)(gm + 8) * ldc + gn] = make_float2(v2, v3);
        }
    }
}

// ===================== flash self-attention =====================
// grid (8, 4, 16). Q tile 128x64, KV tiles 128x64.
// Qs/Ps stored k-interleaved (P8) -> A fragments via ld.shared.v2.
// Softmax scale folded into Q load (power of 2 -> bit-exact).
#define QST 72
#define PST 136
// floats: Qs 9216, Ks 8704, Vs 8704, Ps 17408, red 512 = 44544
#define SELF_SMEM (44544 * 4)

__global__ void __launch_bounds__(256) flash_self_k(
    const float* __restrict__ qkv, float* __restrict__ attno)
{
    extern __shared__ float sm[];
    float* Qs  = sm;
    float* Ks  = sm + 9216;
    float* Vs  = sm + 17920;
    float* Ps  = sm + 26624;
    float* red = sm + 44032;

    const int b = blockIdx.z, h = blockIdx.y;
    const int m0 = blockIdx.x * 128;
    const float* base = qkv + (long)b * NCC * 768;
    const float* qp = base + h * 64;
    const float* kp = base + 256 + h * 64;
    const float* vp = base + 512 + h * 64;

    const int tid = threadIdx.x, wid = tid >> 5, lane = tid & 31;
    const int g = lane >> 2, t4 = lane & 3;
    const int wm = wid & 1, wn = wid >> 1;
    const int c4 = (tid & 15) * 4, r0 = tid >> 4;

    // Q tile: scaled by 1/8 (exact), k-interleaved
#pragma unroll
    for (int p = 0; p < 8; p++) {
        int r = p * 16 + r0;
        float4 v = *(const float4*)(qp + (long)(m0 + r) * 768 + c4);
        float vv[4] = {v.x, v.y, v.z, v.w};
#pragma unroll
        for (int i = 0; i < 4; i++)
            Qs[r * QST + P8(c4 + i)] = to_tf32(0.125f * vv[i]);
    }

    float4 rk[8], rv[8];
    auto loadKV = [&](int tk) {
#pragma unroll
        for (int p = 0; p < 8; p++) {
            int r = tk * 128 + p * 16 + r0;
            rk[p] = *(const float4*)(kp + (long)r * 768 + c4);
            rv[p] = *(const float4*)(vp + (long)r * 768 + c4);
        }
    };
    auto stsKV = [&]() {
#pragma unroll
        for (int p = 0; p < 8; p++) {
            int r = p * 16 + r0;
            *(float4*)&Ks[r * 68 + c4] = cvt4(rk[p]);
            *(float4*)&Vs[r * 68 + c4] = cvt4(rv[p]);
        }
    };

    float l_run[4][2], acc_o[4][2][4];
#pragma unroll
    for (int mi = 0; mi < 4; mi++)
#pragma unroll
        for (int hf = 0; hf < 2; hf++) l_run[mi][hf] = 0.f;
#pragma unroll
    for (int mi = 0; mi < 4; mi++)
#pragma unroll
        for (int ni = 0; ni < 2; ni++)
#pragma unroll
            for (int c = 0; c < 4; c++) acc_o[mi][ni][c] = 0.f;

    loadKV(0);

    for (int tk = 0; tk < 8; tk++) {
        __syncthreads();
        stsKV();
        __syncthreads();
        if (tk + 1 < 8) loadKV(tk + 1);

        // ---- S = (Q/8) K^T ----
        float s[4][4][4];
#pragma unroll
        for (int mi = 0; mi < 4; mi++)
#pragma unroll
            for (int ni = 0; ni < 4; ni++)
#pragma unroll
                for (int c = 0; c < 4; c++) s[mi][ni][c] = 0.f;
#pragma unroll
        for (int ks = 0; ks < 8; ks++) {
            int kb = ks * 8;
            float af[4][4], bf[4][2];
#pragma unroll
            for (int mi = 0; mi < 4; mi++) {
                int ma = wm * 64 + mi * 16 + g;
                float2 u0 = *(const float2*)&Qs[ma * QST + kb + 2 * t4];
                float2 u1 = *(const float2*)&Qs[(ma + 8) * QST + kb + 2 * t4];
                af[mi][0] = u0.x; af[mi][1] = u1.x;
                af[mi][2] = u0.y; af[mi][3] = u1.y;
            }
#pragma unroll
            for (int ni = 0; ni < 4; ni++) {
                int nb = wn * 32 + ni * 8 + g;
                bf[ni][0] = Ks[nb * 68 + kb + t4];
                bf[ni][1] = Ks[nb * 68 + kb + t4 + 4];
            }
#pragma unroll
            for (int mi = 0; mi < 4; mi++)
#pragma unroll
                for (int ni = 0; ni < 4; ni++)
                    mma8(s[mi][ni], af[mi], bf[ni]);
        }

        // ---- p = exp(s); row-sum ----
#pragma unroll
        for (int mi = 0; mi < 4; mi++)
#pragma unroll
            for (int hf = 0; hf < 2; hf++) {
                float ls = 0.f;
#pragma unroll
                for (int ni = 0; ni < 4; ni++) {
                    float p0 = __expf(s[mi][ni][hf * 2]);
                    float p1 = __expf(s[mi][ni][hf * 2 + 1]);
                    s[mi][ni][hf * 2] = p0; s[mi][ni][hf * 2 + 1] = p1;
                    ls += p0 + p1;
                }
                ls += __shfl_xor_sync(0xffffffffu, ls, 1);
                ls += __shfl_xor_sync(0xffffffffu, ls, 2);
                if (t4 == 0) red[wn * 128 + wm * 64 + mi * 16 + hf * 8 + g] = ls;
            }
        __syncthreads();
#pragma unroll
        for (int mi = 0; mi < 4; mi++)
#pragma unroll
            for (int hf = 0; hf < 2; hf++) {
                int r = wm * 64 + mi * 16 + hf * 8 + g;
                l_run[mi][hf] += red[r] + red[128 + r] + red[256 + r] + red[384 + r];
            }
        // write P (tf32, k-interleaved cols)
#pragma unroll
        for (int mi = 0; mi < 4; mi++) {
            int r = wm * 64 + mi * 16 + g;
#pragma unroll
            for (int ni = 0; ni < 4; ni++) {
                int c = wn * 32 + ni * 8 + t4 * 2;
                int pc0 = P8(c), pc1 = P8(c + 1);
                Ps[r * PST + pc0]       = to_tf32(s[mi][ni][0]);
                Ps[r * PST + pc1]       = to_tf32(s[mi][ni][1]);
                Ps[(r + 8) * PST + pc0] = to_tf32(s[mi][ni][2]);
                Ps[(r + 8) * PST + pc1] = to_tf32(s[mi][ni][3]);
            }
        }
        __syncthreads();

        // ---- O += P V ----
#pragma unroll
        for (int ks = 0; ks < 16; ks++) {
            int kb = ks * 8;
            float af[4][4], bf[2][2];
#pragma unroll
            for (int mi = 0; mi < 4; mi++) {
                int ma = wm * 64 + mi * 16 + g;
                float2 u0 = *(const float2*)&Ps[ma * PST + kb + 2 * t4];
                float2 u1 = *(const float2*)&Ps[(ma + 8) * PST + kb + 2 * t4];
                af[mi][0] = u0.x; af[mi][1] = u1.x;
                af[mi][2] = u0.y; af[mi][3] = u1.y;
            }
#pragma unroll
            for (int ni = 0; ni < 2; ni++) {
                int nb = wn * 16 + ni * 8 + g;
                bf[ni][0] = Vs[(kb + t4) * 68 + nb];
                bf[ni][1] = Vs[(kb + t4 + 4) * 68 + nb];
            }
#pragma unroll
            for (int mi = 0; mi < 4; mi++)
#pragma unroll
                for (int ni = 0; ni < 2; ni++)
                    mma8(acc_o[mi][ni], af[mi], bf[ni]);
        }
    }

#pragma unroll
    for (int mi = 0; mi < 4; mi++) {
        int row = m0 + wm * 64 + mi * 16 + g;
        float inv0 = 1.f / l_run[mi][0], inv1 = 1.f / l_run[mi][1];
#pragma unroll
        for (int ni = 0; ni < 2; ni++) {
            int col = h * 64 + wn * 16 + ni * 8 + t4 * 2;
            long o0 = ((long)b * NCC + row) * 256 + col;
            long o1 = ((long)b * NCC + row + 8) * 256 + col;
            *(float2*)&attno[o0] = make_float2(acc_o[mi][ni][0] * inv0, acc_o[mi][ni][1] * inv0);
            *(float2*)&attno[o1] = make_float2(acc_o[mi][ni][2] * inv1, acc_o[mi][ni][3] * inv1);
        }
    }
}

// ===================== flash cross-attention =====================
// grid (32, 1, 16). Q tile 64x256, KV tiles 64x256 (K == V == rep2).
// Qs/Ps k-interleaved; scale 1/16 folded into Q load (exact).
#define QSTC 264
#define PSTC 72
// floats: Qs 16896, KVs 16640, Ps 4608, red 256 = 38400
#define CROSS_SMEM (38400 * 4)

__global__ void __launch_bounds__(256) flash_cross_k(
    const float* __restrict__ qt, const float* __restrict__ rep2,
    float* __restrict__ det)
{
    extern __shared__ float sm[];
    float* Qs  = sm;
    float* KVs = sm + 16896;
    float* Ps  = sm + 33536;
    float* red = sm + 38144;

    const int b = blockIdx.z;
    const int m0 = blockIdx.x * 64;
    const float* qb  = qt   + (long)b * NTT * 256;
    const float* kvb = rep2 + (long)b * NCC * 256;

    const int tid = threadIdx.x, wid = tid >> 5, lane = tid & 31;
    const int g = lane >> 2, t4 = lane & 3;
    const int wm = wid & 1, wn = wid >> 1;
    const int c4 = (tid & 63) * 4, r0 = tid >> 6;

#pragma unroll
    for (int p = 0; p < 16; p++) {
        int r = p * 4 + r0;
        float4 v = *(const float4*)(qb + (long)(m0 + r) * 256 + c4);
        float vv[4] = {v.x, v.y, v.z, v.w};
#pragma unroll
        for (int i = 0; i < 4; i++)
            Qs[r * QSTC + P8(c4 + i)] = to_tf32(0.0625f * vv[i]);
    }

    float4 rkv[16];
    auto loadKV = [&](int tk) {
#pragma unroll
        for (int p = 0; p < 16; p++) {
            int r = tk * 64 + p * 4 + r0;
            rkv[p] = *(const float4*)(kvb + (long)r * 256 + c4);
        }
    };
    auto stsKV = [&]() {
#pragma unroll
        for (int p = 0; p < 16; p++) {
            int r = p * 4 + r0;
            *(float4*)&KVs[r * 260 + c4] = cvt4(rkv[p]);
        }
    };

    float l_run[2][2], acc_o[2][8][4];
#pragma unroll
    for (int mi = 0; mi < 2; mi++)
#pragma unroll
        for (int hf = 0; hf < 2; hf++) l_run[mi][hf] = 0.f;
#pragma unroll
    for (int mi = 0; mi < 2; mi++)
#pragma unroll
        for (int ni = 0; ni < 8; ni++)
#pragma unroll
            for (int c = 0; c < 4; c++) acc_o[mi][ni][c] = 0.f;

    loadKV(0);

    for (int tk = 0; tk < 16; tk++) {
        __syncthreads();
        stsKV();
        __syncthreads();
        if (tk + 1 < 16) loadKV(tk + 1);

        // ---- S = (Q/16) KV^T ----
        float s[2][2][4];
#pragma unroll
        for (int mi = 0; mi < 2; mi++)
#pragma unroll
            for (int ni = 0; ni < 2; ni++)
#pragma unroll
                for (int c = 0; c < 4; c++) s[mi][ni][c] = 0.f;
#pragma unroll
        for (int ks = 0; ks < 32; ks++) {
            int kb = ks * 8;
            float af[2][4], bf[2][2];
#pragma unroll
            for (int mi = 0; mi < 2; mi++) {
                int ma = wm * 32 + mi * 16 + g;
                float2 u0 = *(const float2*)&Qs[ma * QSTC + kb + 2 * t4];
                float2 u1 = *(const float2*)&Qs[(ma + 8) * QSTC + kb + 2 * t4];
                af[mi][0] = u0.x; af[mi][1] = u1.x;
                af[mi][2] = u0.y; af[mi][3] = u1.y;
            }
#pragma unroll
            for (int ni = 0; ni < 2; ni++) {
                int nb = wn * 16 + ni * 8 + g;
                bf[ni][0] = KVs[nb * 260 + kb + t4];
                bf[ni][1] = KVs[nb * 260 + kb + t4 + 4];
            }
#pragma unroll
            for (int mi = 0; mi < 2; mi++)
#pragma unroll
                for (int ni = 0; ni < 2; ni++)
                    mma8(s[mi][ni], af[mi], bf[ni]);
        }

        // ---- p = exp(s); row-sum ----
#pragma unroll
        for (int mi = 0; mi < 2; mi++)
#pragma unroll
            for (int hf = 0; hf < 2; hf++) {
                float ls = 0.f;
#pragma unroll
                for (int ni = 0; ni < 2; ni++) {
                    float p0 = __expf(s[mi][ni][hf * 2]);
                    float p1 = __expf(s[mi][ni][hf * 2 + 1]);
                    s[mi][ni][hf * 2] = p0; s[mi][ni][hf * 2 + 1] = p1;
                    ls += p0 + p1;
                }
                ls += __shfl_xor_sync(0xffffffffu, ls, 1);
                ls += __shfl_xor_sync(0xffffffffu, ls, 2);
                if (t4 == 0) red[wn * 64 + wm * 32 + mi * 16 + hf * 8 + g] = ls;
            }
        __syncthreads();
#pragma unroll
        for (int mi = 0; mi < 2; mi++)
#pragma unroll
            for (int hf = 0; hf < 2; hf++) {
                int r = wm * 32 + mi * 16 + hf * 8 + g;
                l_run[mi][hf] += red[r] + red[64 + r] + red[128 + r] + red[192 + r];
            }
#pragma unroll
        for (int mi = 0; mi < 2; mi++) {
            int r = wm * 32 + mi * 16 + g;
#pragma unroll
            for (int ni = 0; ni < 2; ni++) {
                int c = wn * 16 + ni * 8 + t4 * 2;
                int pc0 = P8(c), pc1 = P8(c + 1);
                Ps[r * PSTC + pc0]       = to_tf32(s[mi][ni][0]);
                Ps[r * PSTC + pc1]       = to_tf32(s[mi][ni][1]);
                Ps[(r + 8) * PSTC + pc0] = to_tf32(s[mi][ni][2]);
                Ps[(r + 8) * PSTC + pc1] = to_tf32(s[mi][ni][3]);
            }
        }
        __syncthreads();

        // ---- O += P KV ----
#pragma unroll
        for (int ks = 0; ks < 8; ks++) {
            int kb = ks * 8;
            float af[2][4], bf[8][2];
#pragma unroll
            for (int mi = 0; mi < 2; mi++) {
                int ma = wm * 32 + mi * 16 + g;
                float2 u0 = *(const float2*)&Ps[ma * PSTC + kb + 2 * t4];
                float2 u1 = *(const float2*)&Ps[(ma + 8) * PSTC + kb + 2 * t4];
                af[mi][0] = u0.x; af[mi][1] = u1.x;
                af[mi][2] = u0.y; af[mi][3] = u1.y;
            }
#pragma unroll
            for (int ni = 0; ni < 8; ni++) {
                int nb = wn * 64 + ni * 8 + g;
                bf[ni][0] = KVs[(kb + t4) * 260 + nb];
                bf[ni][1] = KVs[(kb + t4 + 4) * 260 + nb];
            }
#pragma unroll
            for (int mi = 0; mi < 2; mi++)
#pragma unroll
                for (int ni = 0; ni < 8; ni++)
                    mma8(acc_o[mi][ni], af[mi], bf[ni]);
        }
    }

#pragma unroll
    for (int mi = 0; mi < 2; mi++) {
        int row = m0 + wm * 32 + mi * 16 + g;
        float inv0 = 1.f / l_run[mi][0], inv1 = 1.f / l_run[mi][1];
#pragma unroll
        for (int ni = 0; ni < 8; ni++) {
            int col = wn * 64 + ni * 8 + t4 * 2;
            long o0 = ((long)b * NTT + row) * 256 + col;
            long o1 = ((long)b * NTT + row + 8) * 256 + col;
            *(float2*)&det[o0] = make_float2(acc_o[mi][ni][0] * inv0, acc_o[mi][ni][1] * inv0);
            *(float2*)&det[o1] = make_float2(acc_o[mi][ni][2] * inv1, acc_o[mi][ni][3] * inv1);
        }
    }
}

// ===================== small kernels =====================

__global__ void mean1_k(const float* __restrict__ h, float* __restrict__ part)
{
    int b = blockIdx.x, ch = blockIdx.y, j = threadIdx.x * 4;
    const float* p = h + (long)b * NCC * RD + (long)ch * 32 * RD + j;
    float4 s = make_float4(0.f, 0.f, 0.f, 0.f);
#pragma unroll 4
    for (int n = 0; n < 32; n++) {
        float4 v = *(const float4*)(p + (long)n * RD);
        s.x += v.x; s.y += v.y; s.z += v.z; s.w += v.w;
    }
    *(float4*)&part[(long)(b * 32 + ch) * RD + j] = s;
}

__global__ void mean2_k(const float* __restrict__ part, float* __restrict__ out)
{
    int b = blockIdx.x, j = threadIdx.x;
    float s = 0.f;
#pragma unroll
    for (int c = 0; c < 32; c++) s += part[(long)(b * 32 + c) * RD + j];
    out[b * RD + j] = s * (1.f / NCC);
}

__global__ void latent_k(const float* __restrict__ hmean,
                         const float* __restrict__ pw, const float* __restrict__ pb,
                         const float* __restrict__ mw, const float* __restrict__ mb,
                         const float* __restrict__ sw, const float* __restrict__ sb,
                         const float* __restrict__ eps, float* __restrict__ z)
{
    __shared__ float h2[LHD];
    int b = blockIdx.x, tid = threadIdx.x;
    if (tid < LHD) {
        float s = pb[tid];
        const float* hm = hmean + b * RD;
        for (int k = 0; k < RD; k++) s += hm[k] * pw[k * LHD + tid];
        h2[tid] = s;
    }
    __syncthreads();
    float mu = mb[tid], ls = sb[tid];
    for (int k = 0; k < LHD; k++) {
        mu += h2[k] * mw[k * RD + tid];
        ls += h2[k] * sw[k * RD + tid];
    }
    float sig = 0.9f / (1.f + expf(-ls)) + 0.1f;
    z[b * RD + tid] = mu + sig * eps[b * RD + tid];
}

// residual + layernorm: one warp per 256-wide row
__global__ void __launch_bounds__(256) ln_k(
    const float* __restrict__ x, const float* __restrict__ y,
    const float* __restrict__ g, const float* __restrict__ b,
    float* __restrict__ out)
{
    int w = threadIdx.x >> 5, lane = threadIdx.x & 31;
    long row = (long)blockIdx.x * 8 + w;
    const float4* xr = (const float4*)(x + row * RD);
    const float4* yr = (const float4*)(y + row * RD);
    float4 a0 = xr[lane], a1 = xr[lane + 32];
    float4 c0 = yr[lane], c1 = yr[lane + 32];
    a0.x += c0.x; a0.y += c0.y; a0.z += c0.z; a0.w += c0.w;
    a1.x += c1.x; a1.y += c1.y; a1.z += c1.z; a1.w += c1.w;

    float sum = a0.x + a0.y + a0.z + a0.w + a1.x + a1.y + a1.z + a1.w;
#pragma unroll
    for (int o = 16; o; o >>= 1) sum += __shfl_xor_sync(0xffffffffu, sum, o);
    float mean = sum * (1.f / RD);

    float d0x = a0.x - mean, d0y = a0.y - mean, d0z = a0.z - mean, d0w = a0.w - mean;
    float d1x = a1.x - mean, d1y = a1.y - mean, d1z = a1.z - mean, d1w = a1.w - mean;
    float vs = d0x * d0x + d0y * d0y + d0z * d0z + d0w * d0w
             + d1x * d1x + d1y * d1y + d1z * d1z + d1w * d1w;
#pragma unroll
    for (int o = 16; o; o >>= 1) vs += __shfl_xor_sync(0xffffffffu, vs, o);
    float inv = rsqrtf(vs * (1.f / RD) + 1e-5f);

    float4 g0 = ((const float4*)g)[lane], g1 = ((const float4*)g)[lane + 32];
    float4 b0 = ((const float4*)b)[lane], b1 = ((const float4*)b)[lane + 32];
    float4 o0 = make_float4(d0x * inv * g0.x + b0.x, d0y * inv * g0.y + b0.y,
                            d0z * inv * g0.z + b0.z, d0w * inv * g0.w + b0.w);
    float4 o1 = make_float4(d1x * inv * g1.x + b1.x, d1y * inv * g1.y + b1.y,
                            d1z * inv * g1.z + b1.z, d1w * inv * g1.w + b1.w);
    ((float4*)(out + row * RD))[lane] = o0;
    ((float4*)(out + row * RD))[lane + 32] = o1;
}

// dec2 (K=128, N=16) fused with mu/sigma epilogue
__global__ void __launch_bounds__(256) dec2_k(
    const float* __restrict__ dh, const float* __restrict__ w2,
    const float* __restrict__ b2, float* __restrict__ out)
{
    __shared__ float w[128][17];
    __shared__ float a[16][132];
    int tid = threadIdx.x;
    for (int i = tid; i < 128 * 16; i += 256) { int k = i >> 4, c = i & 15; w[k][c] = w2[i]; }
    long row0 = (long)blockIdx.x * 16;
    for (int i = tid; i < 512; i += 256) {
        int r = i >> 5, c4 = (i & 31) * 4;
        *(float4*)&a[r][c4] = *(const float4*)&dh[(row0 + r) * 128 + c4];
    }
    __syncthreads();
    int r = tid >> 4, c = tid & 15;
    float s = b2[c];
#pragma unroll
    for (int k = 0; k < 128; k++) s += a[r][k] * w[k][c];
    long row = row0 + r;
    const long TOT = (long)BB * NTT * CTRLD;
    if (c < CTRLD) out[row * CTRLD + c] = s;
    else {
        float sp = fmaxf(s, 0.f) + log1pf(expf(-fabsf(s)));
        out[TOT + row * CTRLD + (c - CTRLD)] = 0.9f * sp + 0.1f;
    }
}

// ===================== host side =====================

static float* sym(const void* s) { void* p = nullptr; cudaGetSymbolAddress(&p, s); return (float*)p; }

extern "C" void kernel_launch(void* const* d_in, const int* in_sizes, int n_in,
                              void* d_out, int out_size)
{
    const float* context_x = (const float*)d_in[0];
    const float* context_y = (const float*)d_in[1];
    const float* target_x  = (const float*)d_in[2];
    const float* pred_ctrl = (const float*)d_in[3];
    const float* eps       = (const float*)d_in[4];
    const float* ce_w1 = (const float*)d_in[5];  const float* ce_b1 = (const float*)d_in[6];
    const float* ce_w2 = (const float*)d_in[7];  const float* ce_b2 = (const float*)d_in[8];
    const float* sa_in_w = (const float*)d_in[9];  const float* sa_in_b = (const float*)d_in[10];
    const float* sa_out_w = (const float*)d_in[11]; const float* sa_out_b = (const float*)d_in[12];
    const float* sa_ln_g = (const float*)d_in[13];  const float* sa_ln_b = (const float*)d_in[14];
    const float* qp_w = (const float*)d_in[15]; const float* qp_b = (const float*)d_in[16];
    const float* le_w1 = (const float*)d_in[17]; const float* le_b1 = (const float*)d_in[18];
    const float* le_w2 = (const float*)d_in[19]; const float* le_b2 = (const float*)d_in[20];
    const float* le_pw = (const float*)d_in[21]; const float* le_pb = (const float*)d_in[22];
    const float* le_mw = (const float*)d_in[23]; const float* le_mb = (const float*)d_in[24];
    const float* le_sw = (const float*)d_in[25]; const float* le_sb = (const float*)d_in[26];
    const float* dec_w1 = (const float*)d_in[27]; const float* dec_b1 = (const float*)d_in[28];
    const float* dec_w2 = (const float*)d_in[29]; const float* dec_b2 = (const float*)d_in[30];
    float* out = (float*)d_out;

    float* h12   = sym(g_h12);
    float* rep   = sym(g_rep);
    float* hle   = sym(g_hle);
    float* part  = sym(g_part);
    float* hmean = sym(g_hmean);
    float* z     = sym(g_z);
    float* qkv   = sym(g_qkv);
    float* attno = sym(g_attno);
    float* oproj = sym(g_oproj);
    float* rep2  = sym(g_rep2);
    float* qt    = sym(g_qt);
    float* det   = sym(g_det);
    float* dh    = sym(g_dh);

    const int MC = BB * NCC;   // 16384
    const int MT = BB * NTT;   // 32768

    static cudaStream_t s2 = nullptr;
    static cudaEvent_t ev0 = nullptr, evA = nullptr, evB = nullptr, evC = nullptr;
    if (!s2) {
        cudaStreamCreateWithFlags(&s2, cudaStreamNonBlocking);
        cudaEventCreateWithFlags(&ev0, cudaEventDisableTiming);
        cudaEventCreateWithFlags(&evA, cudaEventDisableTiming);
        cudaEventCreateWithFlags(&evB, cudaEventDisableTiming);
        cudaEventCreateWithFlags(&evC, cudaEventDisableTiming);
    }

    cudaFuncSetAttribute(flash_self_k,  cudaFuncAttributeMaxDynamicSharedMemorySize, SELF_SMEM);
    cudaFuncSetAttribute(flash_cross_k, cudaFuncAttributeMaxDynamicSharedMemorySize, CROSS_SMEM);

    // --- legal fork: ev0 recorded on capture stream BEFORE s2's first op ---
    cudaEventRecord(ev0, 0);
    cudaStreamWaitEvent(s2, ev0, 0);

    // --- qt on s2 (depends only on target_x) ---
    mma_gemm<32, 0, 0, 0><<<dim3(MT / 128, 2, 1), 256, 0, s2>>>(target_x, qp_w, qp_b, qt,
        MT, RD, GAPD, GAPD, RD, RD, 1.f, nullptr, nullptr, nullptr, nullptr, nullptr);
    cudaEventRecord(evC, s2);

    // --- merged MLP1 (le|ce), A gathered from concat(cy,cx), N = 256 ---
    mma_gemm<32, 1, 2, 1><<<dim3(MC / 128, 2, 1), 256>>>(nullptr, le_w1, le_b1, h12,
        MC, 2 * HIDD, CIN, CIN, HIDD, 2 * HIDD, 1.f, context_y, context_x, nullptr,
        ce_w1, ce_b1);

    // --- fork: latent path on s2 (after qt) ---
    cudaEventRecord(evA, 0);
    cudaStreamWaitEvent(s2, evA, 0);
    mma_gemm<32, 0, 0, 0><<<dim3(MC / 128, 2, 1), 256, 0, s2>>>(h12, le_w2, le_b2, hle,
        MC, RD, HIDD, 2 * HIDD, RD, RD, 1.f, nullptr, nullptr, nullptr, nullptr, nullptr);
    mean1_k<<<dim3(BB, 32), 64, 0, s2>>>(hle, part);
    mean2_k<<<BB, 256, 0, s2>>>(part, hmean);
    latent_k<<<BB, 256, 0, s2>>>(hmean, le_pw, le_pb, le_mw, le_mb, le_sw, le_sb, eps, z);
    cudaEventRecord(evB, s2);

    // --- deterministic path on main stream ---
    mma_gemm<32, 0, 0, 0><<<dim3(MC / 128, 2, 1), 256>>>(h12 + HIDD, ce_w2, ce_b2, rep,
        MC, RD, HIDD, 2 * HIDD, RD, RD, 1.f, nullptr, nullptr, nullptr, nullptr, nullptr);

    mma_gemm<32, 0, 0, 0><<<dim3(MC / 128, 6, 1), 256>>>(rep, sa_in_w, sa_in_b, qkv,
        MC, 3 * RD, RD, RD, 3 * RD, 3 * RD, 1.f, nullptr, nullptr, nullptr, nullptr, nullptr);

    flash_self_k<<<dim3(NCC / 128, NHD, BB), 256, SELF_SMEM>>>(qkv, attno);

    mma_gemm<32, 0, 0, 0><<<dim3(MC / 128, 2, 1), 256>>>(attno, sa_out_w, sa_out_b, oproj,
        MC, RD, RD, RD, RD, RD, 1.f, nullptr, nullptr, nullptr, nullptr, nullptr);
    ln_k<<<MC / 8, 256>>>(rep, oproj, sa_ln_g, sa_ln_b, rep2);

    // --- cross attention (join qt) ---
    cudaStreamWaitEvent(0, evC, 0);
    flash_cross_k<<<dim3(NTT / 64, 1, BB), 256, CROSS_SMEM>>>(qt, rep2, det);

    // --- join latent path, then decoder ---
    cudaStreamWaitEvent(0, evB, 0);
    mma_gemm<32, 1, 1, 0><<<dim3(MT / 128, 1, 1), 256>>>(det, dec_w1, dec_b1, dh,
        MT, HIDD, DIN, DIN, HIDD, HIDD, 1.f, z, target_x, pred_ctrl, nullptr, nullptr);
    dec2_k<<<MT / 16, 256>>>(dh, dec_w2, dec_b2, out);
}

// round 9
// speedup vs baseline: 7.0533x; 1.6834x over previous
#include <cuda_runtime.h>
#include <cuda_fp16.h>
#include <math.h>

// ---- problem dims ----
#define BB 16
#define NCC 1024
#define NTT 2048
#define GAPD 128
#define CTRLD 8
#define RD 256
#define NHD 4
#define HDD 64
#define HIDD 128
#define LHD 192
#define CIN (CTRLD + GAPD)          // 136
#define DIN (2 * RD + GAPD + CTRLD) // 648

// ---- scratch ----
__device__ float g_h12  [BB * NCC * 2 * HIDD];   // [le-h1 | ce-h1]
__device__ float g_rep  [BB * NCC * RD];
__device__ float g_hle  [BB * NCC * RD];
__device__ float g_part [BB * 32 * RD];
__device__ float g_hmean[BB * RD];
__device__ float g_z    [BB * RD];
__device__ float g_qkv  [BB * NCC * 3 * RD];
__device__ float g_attno[BB * NCC * RD];
__device__ float g_oproj[BB * NCC * RD];
__device__ float g_rep2 [BB * NCC * RD];
__device__ float g_qt   [BB * NTT * RD];
__device__ float g_det  [BB * NTT * RD];
__device__ float g_dh   [BB * NTT * HIDD];

// ===================== fp16 mma helpers =====================
__device__ __forceinline__ unsigned h2p(float a, float b) {
    __half2 h = __floats2half2_rn(a, b);
    return *reinterpret_cast<unsigned*>(&h);
}
// D += A(16x16) * B(16x8), fp16 inputs, fp32 accum
__device__ __forceinline__ void mma16(float* d, const unsigned* a, const unsigned* b) {
    asm volatile(
        "mma.sync.aligned.m16n8k16.row.col.f32.f16.f16.f32 "
        "{%0,%1,%2,%3},{%4,%5,%6,%7},{%8,%9},{%0,%1,%2,%3};\n"
        : "+f"(d[0]), "+f"(d[1]), "+f"(d[2]), "+f"(d[3])
        : "r"(a[0]), "r"(a[1]), "r"(a[2]), "r"(a[3]), "r"(b[0]), "r"(b[1]));
}
__device__ __forceinline__ float4 ld_guard(const float* src, int gk, int K) {
    if (gk + 4 <= K) return *(const float4*)src;
    float4 v = make_float4(0.f, 0.f, 0.f, 0.f);
    if (gk     < K) v.x = src[0];
    if (gk + 1 < K) v.y = src[1];
    if (gk + 2 < K) v.z = src[2];
    if (gk + 3 < K) v.w = src[3];
    return v;
}

// ===================== fp16 GEMM (reg-pipelined), B = [K,N] row-major ====
#define XBM 128
#define XBK 32

// MODE 0: plain A. MODE 1: A = [det | z | tx | pc], K=DIN. MODE 2: A = [cy | cx], K=CIN.
// BMODE 1: B cols [0,128) from B, [128,256) from B2; biases likewise.
template<int WNT, int ACT, int MODE, int BMODE>
__global__ void __launch_bounds__(256) mma_gemm(
    const float* __restrict__ A, const float* __restrict__ B,
    const float* __restrict__ bias, float* __restrict__ C,
    int M, int N, int K, int lda, int ldb, int ldc,
    float alpha,
    const float* __restrict__ zt, const float* __restrict__ txt,
    const float* __restrict__ pct,
    const float* __restrict__ B2, const float* __restrict__ bias2)
{
    constexpr int XBN_ = WNT * 4;
    constexpr int NI = WNT / 8;
    constexpr int AST2 = 20;          // 16 half2 cols + 4 pad (conflict-free: 20g+t)
    constexpr int BST2 = XBN_ + 8;    // 8t+g conflict-free

    __shared__ unsigned As2[XBM][AST2];
    __shared__ unsigned Bs2[XBK / 2][BST2];

    int tid = threadIdx.x;
    int wid = tid >> 5, lane = tid & 31;
    int g = lane >> 2, t4 = lane & 3;
    int wm = wid & 1, wn = wid >> 1;
    int m0 = blockIdx.x * XBM, n0 = blockIdx.y * XBN_;

    float acc[4][NI][4];
#pragma unroll
    for (int i = 0; i < 4; i++)
#pragma unroll
        for (int j = 0; j < NI; j++)
#pragma unroll
            for (int l = 0; l < 4; l++) acc[i][j][l] = 0.f;

    float4 ra[4], rbE[2], rbO[2];
    constexpr int C4  = XBN_ / 4;       // float4 cols
    constexpr int RP2 = 256 / C4;       // k-pair rows per pass
    constexpr int ITS2 = (XBK / 2) / RP2;

    const int ac = (tid & 7) * 4;       // A k-chunk (4 floats)
    const int ar = tid >> 3;
    const int bc4 = tid % C4;
    const int brb = tid / C4;

    auto loadA = [&](int k0) {
        int gk = k0 + ac;
#pragma unroll
        for (int p = 0; p < 4; p++) {
            int gm = m0 + p * 32 + ar;
            if (MODE == 1) {
                const float* s;
                if (gk < RD)                 s = A   + (long)gm * RD   + gk;
                else if (gk < 2 * RD)        s = zt  + (long)(gm >> 11) * RD + (gk - RD);
                else if (gk < 2 * RD + GAPD) s = txt + (long)gm * GAPD + (gk - 2 * RD);
                else if (gk < DIN)           s = pct + (long)gm * CTRLD + (gk - 2 * RD - GAPD);
                else                         s = nullptr;
                ra[p] = s ? *(const float4*)s : make_float4(0.f, 0.f, 0.f, 0.f);
            } else if (MODE == 2) {
                const float* s;
                if (gk < CTRLD)    s = zt  + (long)gm * CTRLD + gk;
                else if (gk < CIN) s = txt + (long)gm * GAPD + (gk - CTRLD);
                else               s = nullptr;
                ra[p] = s ? *(const float4*)s : make_float4(0.f, 0.f, 0.f, 0.f);
            } else {
                ra[p] = ld_guard(A + (long)gm * lda + gk, gk, K);
            }
        }
    };
    auto loadB = [&](int k0) {
        int gn = n0 + bc4 * 4;
#pragma unroll
        for (int it = 0; it < ITS2; it++) {
            int kp = k0 + (it * RP2 + brb) * 2;
            if (BMODE == 1) {
                const float* base0 = (gn < HIDD) ? B : B2;
                int gq = (gn < HIDD) ? gn : gn - HIDD;
                rbE[it] = (kp     < K) ? *(const float4*)(base0 + (long)kp * ldb + gq)
                                       : make_float4(0.f, 0.f, 0.f, 0.f);
                rbO[it] = (kp + 1 < K) ? *(const float4*)(base0 + (long)(kp + 1) * ldb + gq)
                                       : make_float4(0.f, 0.f, 0.f, 0.f);
            } else {
                bool okn = (gn + 3 < N);
                rbE[it] = (kp     < K && okn) ? *(const float4*)(B + (long)kp * ldb + gn)
                                              : make_float4(0.f, 0.f, 0.f, 0.f);
                rbO[it] = (kp + 1 < K && okn) ? *(const float4*)(B + (long)(kp + 1) * ldb + gn)
                                              : make_float4(0.f, 0.f, 0.f, 0.f);
            }
        }
    };
    auto stsAB = [&]() {
#pragma unroll
        for (int p = 0; p < 4; p++) {
            uint2 u = make_uint2(h2p(ra[p].x, ra[p].y), h2p(ra[p].z, ra[p].w));
            *(uint2*)&As2[p * 32 + ar][ac >> 1] = u;
        }
#pragma unroll
        for (int it = 0; it < ITS2; it++) {
            uint4 u = make_uint4(h2p(rbE[it].x, rbO[it].x), h2p(rbE[it].y, rbO[it].y),
                                 h2p(rbE[it].z, rbO[it].z), h2p(rbE[it].w, rbO[it].w));
            *(uint4*)&Bs2[it * RP2 + brb][bc4 * 4] = u;
        }
    };

    int kT = (K + XBK - 1) / XBK;
    loadA(0); loadB(0);

    for (int t = 0; t < kT; t++) {
        stsAB();
        __syncthreads();
        if (t + 1 < kT) { loadA((t + 1) * XBK); loadB((t + 1) * XBK); }
#pragma unroll
        for (int ks = 0; ks < 2; ks++) {          // two K=16 steps per 32-K tile
            int kb2 = ks * 8;
            unsigned af[4][4], bf[NI][2];
#pragma unroll
            for (int mi = 0; mi < 4; mi++) {
                int ma = wm * 64 + mi * 16 + g;
                af[mi][0] = As2[ma    ][kb2 + t4];
                af[mi][1] = As2[ma + 8][kb2 + t4];
                af[mi][2] = As2[ma    ][kb2 + t4 + 4];
                af[mi][3] = As2[ma + 8][kb2 + t4 + 4];
            }
#pragma unroll
            for (int ni = 0; ni < NI; ni++) {
                int nb = wn * WNT + ni * 8 + g;
                bf[ni][0] = Bs2[kb2 + t4    ][nb];
                bf[ni][1] = Bs2[kb2 + t4 + 4][nb];
            }
#pragma unroll
            for (int mi = 0; mi < 4; mi++)
#pragma unroll
                for (int ni = 0; ni < NI; ni++)
                    mma16(acc[mi][ni], af[mi], bf[ni]);
        }
        __syncthreads();
    }

#pragma unroll
    for (int mi = 0; mi < 4; mi++) {
        int gm = m0 + wm * 64 + mi * 16 + g;
#pragma unroll
        for (int ni = 0; ni < NI; ni++) {
            int gn = n0 + wn * WNT + ni * 8 + t4 * 2;
            if (gn >= N) continue;
            float b0, b1;
            if (BMODE == 1) {
                const float* bp = (gn < HIDD) ? bias : bias2;
                int gq = (gn < HIDD) ? gn : gn - HIDD;
                b0 = bp[gq]; b1 = bp[gq + 1];
            } else {
                b0 = bias ? bias[gn] : 0.f;
                b1 = bias ? bias[gn + 1] : 0.f;
            }
            float v0 = acc[mi][ni][0] * alpha + b0;
            float v1 = acc[mi][ni][1] * alpha + b1;
            float v2 = acc[mi][ni][2] * alpha + b0;
            float v3 = acc[mi][ni][3] * alpha + b1;
            if (ACT == 1) {
                v0 = fmaxf(v0, 0.f); v1 = fmaxf(v1, 0.f);
                v2 = fmaxf(v2, 0.f); v3 = fmaxf(v3, 0.f);
            }
            *(float2*)&C[(long)gm * ldc + gn]       = make_float2(v0, v1);
            *(float2*)&C[(long)(gm + 8) * ldc + gn] = make_float2(v2, v3);
        }
    }
}

// ===================== flash self-attention (fp16, 2 CTAs/SM) =====================
// grid (8, 4, 16). Q tile 128x64, KV tiles 128x64.
// Qs/Ks: half2 over headdim pairs, row-major. Vs: half2 over seq pairs.
// uint words: Qs 128*36=4608, Ks 4608, Vs 64*72=4608, Ps 128*68=8704, red 512
#define SELF_SMEM (23040 * 4)

__global__ void __launch_bounds__(256, 2) flash_self_k(
    const float* __restrict__ qkv, float* __restrict__ attno)
{
    extern __shared__ unsigned smu[];
    unsigned* Qs = smu;
    unsigned* Ks = smu + 4608;
    unsigned* Vs = smu + 9216;
    unsigned* Ps = smu + 13824;
    float*    red = (float*)(smu + 22528);

    const int b = blockIdx.z, h = blockIdx.y;
    const int m0 = blockIdx.x * 128;
    const float* base = qkv + (long)b * NCC * 768;
    const float* qp = base + h * 64;
    const float* kp = base + 256 + h * 64;
    const float* vp = base + 512 + h * 64;

    const int tid = threadIdx.x, wid = tid >> 5, lane = tid & 31;
    const int g = lane >> 2, t4 = lane & 3;
    const int wm = wid & 1, wn = wid >> 1;
    const int c4 = (tid & 15) * 4, r0 = tid >> 4;

    // Q tile, scaled by 1/8 (exact power of 2)
#pragma unroll
    for (int p = 0; p < 8; p++) {
        int r = p * 16 + r0;
        float4 v = *(const float4*)(qp + (long)(m0 + r) * 768 + c4);
        uint2 u = make_uint2(h2p(0.125f * v.x, 0.125f * v.y), h2p(0.125f * v.z, 0.125f * v.w));
        *(uint2*)&Qs[r * 36 + (c4 >> 1)] = u;
    }

    float l_run[4][2], acc_o[4][2][4];
#pragma unroll
    for (int mi = 0; mi < 4; mi++)
#pragma unroll
        for (int hf = 0; hf < 2; hf++) l_run[mi][hf] = 0.f;
#pragma unroll
    for (int mi = 0; mi < 4; mi++)
#pragma unroll
        for (int ni = 0; ni < 2; ni++)
#pragma unroll
            for (int c = 0; c < 4; c++) acc_o[mi][ni][c] = 0.f;

    for (int tk = 0; tk < 8; tk++) {
        __syncthreads();
        // K rows
#pragma unroll
        for (int p = 0; p < 8; p++) {
            int r = p * 16 + r0;
            float4 kv = *(const float4*)(kp + (long)(tk * 128 + r) * 768 + c4);
            *(uint2*)&Ks[r * 36 + (c4 >> 1)] =
                make_uint2(h2p(kv.x, kv.y), h2p(kv.z, kv.w));
        }
        // V seq-pairs
#pragma unroll
        for (int p = 0; p < 4; p++) {
            int q = p * 16 + r0;  // 0..63
            float4 e = *(const float4*)(vp + (long)(tk * 128 + 2 * q) * 768 + c4);
            float4 o = *(const float4*)(vp + (long)(tk * 128 + 2 * q + 1) * 768 + c4);
            *(uint4*)&Vs[q * 72 + c4] = make_uint4(
                h2p(e.x, o.x), h2p(e.y, o.y), h2p(e.z, o.z), h2p(e.w, o.w));
        }
        __syncthreads();

        // ---- S = (Q/8) K^T : 4 K=16 steps over hd ----
        float s[4][4][4];
#pragma unroll
        for (int mi = 0; mi < 4; mi++)
#pragma unroll
            for (int ni = 0; ni < 4; ni++)
#pragma unroll
                for (int c = 0; c < 4; c++) s[mi][ni][c] = 0.f;
#pragma unroll
        for (int ks = 0; ks < 4; ks++) {
            int kb2 = ks * 8;
            unsigned af[4][4], bf[4][2];
#pragma unroll
            for (int mi = 0; mi < 4; mi++) {
                int ma = wm * 64 + mi * 16 + g;
                af[mi][0] = Qs[ma * 36 + kb2 + t4];
                af[mi][1] = Qs[(ma + 8) * 36 + kb2 + t4];
                af[mi][2] = Qs[ma * 36 + kb2 + t4 + 4];
                af[mi][3] = Qs[(ma + 8) * 36 + kb2 + t4 + 4];
            }
#pragma unroll
            for (int ni = 0; ni < 4; ni++) {
                int nb = wn * 32 + ni * 8 + g;
                bf[ni][0] = Ks[nb * 36 + kb2 + t4];
                bf[ni][1] = Ks[nb * 36 + kb2 + t4 + 4];
            }
#pragma unroll
            for (int mi = 0; mi < 4; mi++)
#pragma unroll
                for (int ni = 0; ni < 4; ni++)
                    mma16(s[mi][ni], af[mi], bf[ni]);
        }

        // ---- p = exp(s); row-sum (max-free: scores tiny) ----
#pragma unroll
        for (int mi = 0; mi < 4; mi++)
#pragma unroll
            for (int hf = 0; hf < 2; hf++) {
                float ls = 0.f;
#pragma unroll
                for (int ni = 0; ni < 4; ni++) {
                    float p0 = __expf(s[mi][ni][hf * 2]);
                    float p1 = __expf(s[mi][ni][hf * 2 + 1]);
                    s[mi][ni][hf * 2] = p0; s[mi][ni][hf * 2 + 1] = p1;
                    ls += p0 + p1;
                }
                ls += __shfl_xor_sync(0xffffffffu, ls, 1);
                ls += __shfl_xor_sync(0xffffffffu, ls, 2);
                if (t4 == 0) red[wn * 128 + wm * 64 + mi * 16 + hf * 8 + g] = ls;
            }
        __syncthreads();
#pragma unroll
        for (int mi = 0; mi < 4; mi++)
#pragma unroll
            for (int hf = 0; hf < 2; hf++) {
                int r = wm * 64 + mi * 16 + hf * 8 + g;
                l_run[mi][hf] += red[r] + red[128 + r] + red[256 + r] + red[384 + r];
            }
        // write P: (c, c+1) adjacent -> single half2 STS
#pragma unroll
        for (int mi = 0; mi < 4; mi++) {
            int r = wm * 64 + mi * 16 + g;
#pragma unroll
            for (int ni = 0; ni < 4; ni++) {
                int c2 = wn * 16 + ni * 4 + t4;
                Ps[r * 68 + c2]       = h2p(s[mi][ni][0], s[mi][ni][1]);
                Ps[(r + 8) * 68 + c2] = h2p(s[mi][ni][2], s[mi][ni][3]);
            }
        }
        __syncthreads();

        // ---- O += P V : 8 K=16 steps over seq ----
#pragma unroll
        for (int ks = 0; ks < 8; ks++) {
            int kb2 = ks * 8;
            unsigned af[4][4], bf[2][2];
#pragma unroll
            for (int mi = 0; mi < 4; mi++) {
                int ma = wm * 64 + mi * 16 + g;
                af[mi][0] = Ps[ma * 68 + kb2 + t4];
                af[mi][1] = Ps[(ma + 8) * 68 + kb2 + t4];
                af[mi][2] = Ps[ma * 68 + kb2 + t4 + 4];
                af[mi][3] = Ps[(ma + 8) * 68 + kb2 + t4 + 4];
            }
#pragma unroll
            for (int ni = 0; ni < 2; ni++) {
                int nb = wn * 16 + ni * 8 + g;
                bf[ni][0] = Vs[(kb2 + t4) * 72 + nb];
                bf[ni][1] = Vs[(kb2 + t4 + 4) * 72 + nb];
            }
#pragma unroll
            for (int mi = 0; mi < 4; mi++)
#pragma unroll
                for (int ni = 0; ni < 2; ni++)
                    mma16(acc_o[mi][ni], af[mi], bf[ni]);
        }
    }

#pragma unroll
    for (int mi = 0; mi < 4; mi++) {
        int row = m0 + wm * 64 + mi * 16 + g;
        float inv0 = 1.f / l_run[mi][0], inv1 = 1.f / l_run[mi][1];
#pragma unroll
        for (int ni = 0; ni < 2; ni++) {
            int col = h * 64 + wn * 16 + ni * 8 + t4 * 2;
            long o0 = ((long)b * NCC + row) * 256 + col;
            long o1 = ((long)b * NCC + row + 8) * 256 + col;
            *(float2*)&attno[o0] = make_float2(acc_o[mi][ni][0] * inv0, acc_o[mi][ni][1] * inv0);
            *(float2*)&attno[o1] = make_float2(acc_o[mi][ni][2] * inv1, acc_o[mi][ni][3] * inv1);
        }
    }
}

// ===================== flash cross-attention (fp16, 2 CTAs/SM) =====================
// grid (32, 1, 16). Q tile 64x256, KV tiles 64x256 (K == V == rep2).
// Qs/KVs: half2 over hd pairs. Vsc: half2 over seq pairs. Psc: half2 over seq pairs.
// uint words: Qs 64*132=8448, KVs 8448, Vsc 32*264=8448, Psc 64*36=2304, red 256
#define CROSS_SMEM (27904 * 4)

__global__ void __launch_bounds__(256, 2) flash_cross_k(
    const float* __restrict__ qt, const float* __restrict__ rep2,
    float* __restrict__ det)
{
    extern __shared__ unsigned smu[];
    unsigned* Qs  = smu;
    unsigned* KVs = smu + 8448;
    unsigned* Vsc = smu + 16896;
    unsigned* Psc = smu + 25344;
    float*    red = (float*)(smu + 27648);

    const int b = blockIdx.z;
    const int m0 = blockIdx.x * 64;
    const float* qb  = qt   + (long)b * NTT * 256;
    const float* kvb = rep2 + (long)b * NCC * 256;

    const int tid = threadIdx.x, wid = tid >> 5, lane = tid & 31;
    const int g = lane >> 2, t4 = lane & 3;
    const int wm = wid & 1, wn = wid >> 1;
    const int c4 = (tid & 63) * 4, r0 = tid >> 6;

    // Q tile, scaled by 1/16 (exact)
#pragma unroll
    for (int p = 0; p < 16; p++) {
        int r = p * 4 + r0;
        float4 v = *(const float4*)(qb + (long)(m0 + r) * 256 + c4);
        *(uint2*)&Qs[r * 132 + (c4 >> 1)] =
            make_uint2(h2p(0.0625f * v.x, 0.0625f * v.y), h2p(0.0625f * v.z, 0.0625f * v.w));
    }

    float l_run[2][2], acc_o[2][8][4];
#pragma unroll
    for (int mi = 0; mi < 2; mi++)
#pragma unroll
        for (int hf = 0; hf < 2; hf++) l_run[mi][hf] = 0.f;
#pragma unroll
    for (int mi = 0; mi < 2; mi++)
#pragma unroll
        for (int ni = 0; ni < 8; ni++)
#pragma unroll
            for (int c = 0; c < 4; c++) acc_o[mi][ni][c] = 0.f;

    for (int tk = 0; tk < 16; tk++) {
        __syncthreads();
        // load KV tile once; write both layouts
#pragma unroll
        for (int p = 0; p < 8; p++) {
            int q = p * 4 + r0;  // 0..31
            float4 e = *(const float4*)(kvb + (long)(tk * 64 + 2 * q) * 256 + c4);
            float4 o = *(const float4*)(kvb + (long)(tk * 64 + 2 * q + 1) * 256 + c4);
            *(uint2*)&KVs[(2 * q) * 132 + (c4 >> 1)] =
                make_uint2(h2p(e.x, e.y), h2p(e.z, e.w));
            *(uint2*)&KVs[(2 * q + 1) * 132 + (c4 >> 1)] =
                make_uint2(h2p(o.x, o.y), h2p(o.z, o.w));
            *(uint4*)&Vsc[q * 264 + c4] = make_uint4(
                h2p(e.x, o.x), h2p(e.y, o.y), h2p(e.z, o.z), h2p(e.w, o.w));
        }
        __syncthreads();

        // ---- S = (Q/16) KV^T : 16 K=16 steps over hd ----
        float s[2][2][4];
#pragma unroll
        for (int mi = 0; mi < 2; mi++)
#pragma unroll
            for (int ni = 0; ni < 2; ni++)
#pragma unroll
                for (int c = 0; c < 4; c++) s[mi][ni][c] = 0.f;
#pragma unroll
        for (int ks = 0; ks < 16; ks++) {
            int kb2 = ks * 8;
            unsigned af[2][4], bf[2][2];
#pragma unroll
            for (int mi = 0; mi < 2; mi++) {
                int ma = wm * 32 + mi * 16 + g;
                af[mi][0] = Qs[ma * 132 + kb2 + t4];
                af[mi][1] = Qs[(ma + 8) * 132 + kb2 + t4];
                af[mi][2] = Qs[ma * 132 + kb2 + t4 + 4];
                af[mi][3] = Qs[(ma + 8) * 132 + kb2 + t4 + 4];
            }
#pragma unroll
            for (int ni = 0; ni < 2; ni++) {
                int nb = wn * 16 + ni * 8 + g;
                bf[ni][0] = KVs[nb * 132 + kb2 + t4];
                bf[ni][1] = KVs[nb * 132 + kb2 + t4 + 4];
            }
#pragma unroll
            for (int mi = 0; mi < 2; mi++)
#pragma unroll
                for (int ni = 0; ni < 2; ni++)
                    mma16(s[mi][ni], af[mi], bf[ni]);
        }

        // ---- p = exp(s); row-sum ----
#pragma unroll
        for (int mi = 0; mi < 2; mi++)
#pragma unroll
            for (int hf = 0; hf < 2; hf++) {
                float ls = 0.f;
#pragma unroll
                for (int ni = 0; ni < 2; ni++) {
                    float p0 = __expf(s[mi][ni][hf * 2]);
                    float p1 = __expf(s[mi][ni][hf * 2 + 1]);
                    s[mi][ni][hf * 2] = p0; s[mi][ni][hf * 2 + 1] = p1;
                    ls += p0 + p1;
                }
                ls += __shfl_xor_sync(0xffffffffu, ls, 1);
                ls += __shfl_xor_sync(0xffffffffu, ls, 2);
                if (t4 == 0) red[wn * 64 + wm * 32 + mi * 16 + hf * 8 + g] = ls;
            }
        __syncthreads();
#pragma unroll
        for (int mi = 0; mi < 2; mi++)
#pragma unroll
            for (int hf = 0; hf < 2; hf++) {
                int r = wm * 32 + mi * 16 + hf * 8 + g;
                l_run[mi][hf] += red[r] + red[64 + r] + red[128 + r] + red[192 + r];
            }
#pragma unroll
        for (int mi = 0; mi < 2; mi++) {
            int r = wm * 32 + mi * 16 + g;
#pragma unroll
            for (int ni = 0; ni < 2; ni++) {
                int c2 = wn * 8 + ni * 4 + t4;
                Psc[r * 36 + c2]       = h2p(s[mi][ni][0], s[mi][ni][1]);
                Psc[(r + 8) * 36 + c2] = h2p(s[mi][ni][2], s[mi][ni][3]);
            }
        }
        __syncthreads();

        // ---- O += P KV : 4 K=16 steps over seq ----
#pragma unroll
        for (int ks = 0; ks < 4; ks++) {
            int kb2 = ks * 8;
            unsigned af[2][4], bf[8][2];
#pragma unroll
            for (int mi = 0; mi < 2; mi++) {
                int ma = wm * 32 + mi * 16 + g;
                af[mi][0] = Psc[ma * 36 + kb2 + t4];
                af[mi][1] = Psc[(ma + 8) * 36 + kb2 + t4];
                af[mi][2] = Psc[ma * 36 + kb2 + t4 + 4];
                af[mi][3] = Psc[(ma + 8) * 36 + kb2 + t4 + 4];
            }
#pragma unroll
            for (int ni = 0; ni < 8; ni++) {
                int nb = wn * 64 + ni * 8 + g;
                bf[ni][0] = Vsc[(kb2 + t4) * 264 + nb];
                bf[ni][1] = Vsc[(kb2 + t4 + 4) * 264 + nb];
            }
#pragma unroll
            for (int mi = 0; mi < 2; mi++)
#pragma unroll
                for (int ni = 0; ni < 8; ni++)
                    mma16(acc_o[mi][ni], af[mi], bf[ni]);
        }
    }

#pragma unroll
    for (int mi = 0; mi < 2; mi++) {
        int row = m0 + wm * 32 + mi * 16 + g;
        float inv0 = 1.f / l_run[mi][0], inv1 = 1.f / l_run[mi][1];
#pragma unroll
        for (int ni = 0; ni < 8; ni++) {
            int col = wn * 64 + ni * 8 + t4 * 2;
            long o0 = ((long)b * NTT + row) * 256 + col;
            long o1 = ((long)b * NTT + row + 8) * 256 + col;
            *(float2*)&det[o0] = make_float2(acc_o[mi][ni][0] * inv0, acc_o[mi][ni][1] * inv0);
            *(float2*)&det[o1] = make_float2(acc_o[mi][ni][2] * inv1, acc_o[mi][ni][3] * inv1);
        }
    }
}

// ===================== small kernels =====================

__global__ void mean1_k(const float* __restrict__ h, float* __restrict__ part)
{
    int b = blockIdx.x, ch = blockIdx.y, j = threadIdx.x * 4;
    const float* p = h + (long)b * NCC * RD + (long)ch * 32 * RD + j;
    float4 s = make_float4(0.f, 0.f, 0.f, 0.f);
#pragma unroll 4
    for (int n = 0; n < 32; n++) {
        float4 v = *(const float4*)(p + (long)n * RD);
        s.x += v.x; s.y += v.y; s.z += v.z; s.w += v.w;
    }
    *(float4*)&part[(long)(b * 32 + ch) * RD + j] = s;
}

__global__ void mean2_k(const float* __restrict__ part, float* __restrict__ out)
{
    int b = blockIdx.x, j = threadIdx.x;
    float s = 0.f;
#pragma unroll
    for (int c = 0; c < 32; c++) s += part[(long)(b * 32 + c) * RD + j];
    out[b * RD + j] = s * (1.f / NCC);
}

__global__ void latent_k(const float* __restrict__ hmean,
                         const float* __restrict__ pw, const float* __restrict__ pb,
                         const float* __restrict__ mw, const float* __restrict__ mb,
                         const float* __restrict__ sw, const float* __restrict__ sb,
                         const float* __restrict__ eps, float* __restrict__ z)
{
    __shared__ float h2s[LHD];
    int b = blockIdx.x, tid = threadIdx.x;
    if (tid < LHD) {
        float s = pb[tid];
        const float* hm = hmean + b * RD;
        for (int k = 0; k < RD; k++) s += hm[k] * pw[k * LHD + tid];
        h2s[tid] = s;
    }
    __syncthreads();
    float mu = mb[tid], ls = sb[tid];
    for (int k = 0; k < LHD; k++) {
        mu += h2s[k] * mw[k * RD + tid];
        ls += h2s[k] * sw[k * RD + tid];
    }
    float sig = 0.9f / (1.f + expf(-ls)) + 0.1f;
    z[b * RD + tid] = mu + sig * eps[b * RD + tid];
}

// residual + layernorm: one warp per 256-wide row
__global__ void __launch_bounds__(256) ln_k(
    const float* __restrict__ x, const float* __restrict__ y,
    const float* __restrict__ g, const float* __restrict__ b,
    float* __restrict__ out)
{
    int w = threadIdx.x >> 5, lane = threadIdx.x & 31;
    long row = (long)blockIdx.x * 8 + w;
    const float4* xr = (const float4*)(x + row * RD);
    const float4* yr = (const float4*)(y + row * RD);
    float4 a0 = xr[lane], a1 = xr[lane + 32];
    float4 c0 = yr[lane], c1 = yr[lane + 32];
    a0.x += c0.x; a0.y += c0.y; a0.z += c0.z; a0.w += c0.w;
    a1.x += c1.x; a1.y += c1.y; a1.z += c1.z; a1.w += c1.w;

    float sum = a0.x + a0.y + a0.z + a0.w + a1.x + a1.y + a1.z + a1.w;
#pragma unroll
    for (int o = 16; o; o >>= 1) sum += __shfl_xor_sync(0xffffffffu, sum, o);
    float mean = sum * (1.f / RD);

    float d0x = a0.x - mean, d0y = a0.y - mean, d0z = a0.z - mean, d0w = a0.w - mean;
    float d1x = a1.x - mean, d1y = a1.y - mean, d1z = a1.z - mean, d1w = a1.w - mean;
    float vs = d0x * d0x + d0y * d0y + d0z * d0z + d0w * d0w
             + d1x * d1x + d1y * d1y + d1z * d1z + d1w * d1w;
#pragma unroll
    for (int o = 16; o; o >>= 1) vs += __shfl_xor_sync(0xffffffffu, vs, o);
    float inv = rsqrtf(vs * (1.f / RD) + 1e-5f);

    float4 g0 = ((const float4*)g)[lane], g1 = ((const float4*)g)[lane + 32];
    float4 b0 = ((const float4*)b)[lane], b1 = ((const float4*)b)[lane + 32];
    float4 o0 = make_float4(d0x * inv * g0.x + b0.x, d0y * inv * g0.y + b0.y,
                            d0z * inv * g0.z + b0.z, d0w * inv * g0.w + b0.w);
    float4 o1 = make_float4(d1x * inv * g1.x + b1.x, d1y * inv * g1.y + b1.y,
                            d1z * inv * g1.z + b1.z, d1w * inv * g1.w + b1.w);
    ((float4*)(out + row * RD))[lane] = o0;
    ((float4*)(out + row * RD))[lane + 32] = o1;
}

// dec2 (K=128, N=16) fused with mu/sigma epilogue
__global__ void __launch_bounds__(256) dec2_k(
    const float* __restrict__ dh, const float* __restrict__ w2,
    const float* __restrict__ b2, float* __restrict__ out)
{
    __shared__ float w[128][17];
    __shared__ float a[16][132];
    int tid = threadIdx.x;
    for (int i = tid; i < 128 * 16; i += 256) { int k = i >> 4, c = i & 15; w[k][c] = w2[i]; }
    long row0 = (long)blockIdx.x * 16;
    for (int i = tid; i < 512; i += 256) {
        int r = i >> 5, c4 = (i & 31) * 4;
        *(float4*)&a[r][c4] = *(const float4*)&dh[(row0 + r) * 128 + c4];
    }
    __syncthreads();
    int r = tid >> 4, c = tid & 15;
    float s = b2[c];
#pragma unroll
    for (int k = 0; k < 128; k++) s += a[r][k] * w[k][c];
    long row = row0 + r;
    const long TOT = (long)BB * NTT * CTRLD;
    if (c < CTRLD) out[row * CTRLD + c] = s;
    else {
        float sp = fmaxf(s, 0.f) + log1pf(expf(-fabsf(s)));
        out[TOT + row * CTRLD + (c - CTRLD)] = 0.9f * sp + 0.1f;
    }
}

// ===================== host side =====================

static float* sym(const void* s) { void* p = nullptr; cudaGetSymbolAddress(&p, s); return (float*)p; }

extern "C" void kernel_launch(void* const* d_in, const int* in_sizes, int n_in,
                              void* d_out, int out_size)
{
    const float* context_x = (const float*)d_in[0];
    const float* context_y = (const float*)d_in[1];
    const float* target_x  = (const float*)d_in[2];
    const float* pred_ctrl = (const float*)d_in[3];
    const float* eps       = (const float*)d_in[4];
    const float* ce_w1 = (const float*)d_in[5];  const float* ce_b1 = (const float*)d_in[6];
    const float* ce_w2 = (const float*)d_in[7];  const float* ce_b2 = (const float*)d_in[8];
    const float* sa_in_w = (const float*)d_in[9];  const float* sa_in_b = (const float*)d_in[10];
    const float* sa_out_w = (const float*)d_in[11]; const float* sa_out_b = (const float*)d_in[12];
    const float* sa_ln_g = (const float*)d_in[13];  const float* sa_ln_b = (const float*)d_in[14];
    const float* qp_w = (const float*)d_in[15]; const float* qp_b = (const float*)d_in[16];
    const float* le_w1 = (const float*)d_in[17]; const float* le_b1 = (const float*)d_in[18];
    const float* le_w2 = (const float*)d_in[19]; const float* le_b2 = (const float*)d_in[20];
    const float* le_pw = (const float*)d_in[21]; const float* le_pb = (const float*)d_in[22];
    const float* le_mw = (const float*)d_in[23]; const float* le_mb = (const float*)d_in[24];
    const float* le_sw = (const float*)d_in[25]; const float* le_sb = (const float*)d_in[26];
    const float* dec_w1 = (const float*)d_in[27]; const float* dec_b1 = (const float*)d_in[28];
    const float* dec_w2 = (const float*)d_in[29]; const float* dec_b2 = (const float*)d_in[30];
    float* out = (float*)d_out;

    float* h12   = sym(g_h12);
    float* rep   = sym(g_rep);
    float* hle   = sym(g_hle);
    float* part  = sym(g_part);
    float* hmean = sym(g_hmean);
    float* z     = sym(g_z);
    float* qkv   = sym(g_qkv);
    float* attno = sym(g_attno);
    float* oproj = sym(g_oproj);
    float* rep2  = sym(g_rep2);
    float* qt    = sym(g_qt);
    float* det   = sym(g_det);
    float* dh    = sym(g_dh);

    const int MC = BB * NCC;   // 16384
    const int MT = BB * NTT;   // 32768

    static cudaStream_t s2 = nullptr;
    static cudaEvent_t ev0 = nullptr, evA = nullptr, evB = nullptr, evC = nullptr;
    if (!s2) {
        cudaStreamCreateWithFlags(&s2, cudaStreamNonBlocking);
        cudaEventCreateWithFlags(&ev0, cudaEventDisableTiming);
        cudaEventCreateWithFlags(&evA, cudaEventDisableTiming);
        cudaEventCreateWithFlags(&evB, cudaEventDisableTiming);
        cudaEventCreateWithFlags(&evC, cudaEventDisableTiming);
    }

    cudaFuncSetAttribute(flash_self_k,  cudaFuncAttributeMaxDynamicSharedMemorySize, SELF_SMEM);
    cudaFuncSetAttribute(flash_cross_k, cudaFuncAttributeMaxDynamicSharedMemorySize, CROSS_SMEM);

    // --- legal fork: ev0 on capture stream BEFORE s2's first op ---
    cudaEventRecord(ev0, 0);
    cudaStreamWaitEvent(s2, ev0, 0);

    // --- qt on s2 (depends only on target_x) ---
    mma_gemm<32, 0, 0, 0><<<dim3(MT / 128, 2, 1), 256, 0, s2>>>(target_x, qp_w, qp_b, qt,
        MT, RD, GAPD, GAPD, RD, RD, 1.f, nullptr, nullptr, nullptr, nullptr, nullptr);
    cudaEventRecord(evC, s2);

    // --- merged MLP1 (le|ce), A gathered from concat(cy,cx), N = 256 ---
    mma_gemm<32, 1, 2, 1><<<dim3(MC / 128, 2, 1), 256>>>(nullptr, le_w1, le_b1, h12,
        MC, 2 * HIDD, CIN, CIN, HIDD, 2 * HIDD, 1.f, context_y, context_x, nullptr,
        ce_w1, ce_b1);

    // --- fork: latent path on s2 (after qt) ---
    cudaEventRecord(evA, 0);
    cudaStreamWaitEvent(s2, evA, 0);
    mma_gemm<32, 0, 0, 0><<<dim3(MC / 128, 2, 1), 256, 0, s2>>>(h12, le_w2, le_b2, hle,
        MC, RD, HIDD, 2 * HIDD, RD, RD, 1.f, nullptr, nullptr, nullptr, nullptr, nullptr);
    mean1_k<<<dim3(BB, 32), 64, 0, s2>>>(hle, part);
    mean2_k<<<BB, 256, 0, s2>>>(part, hmean);
    latent_k<<<BB, 256, 0, s2>>>(hmean, le_pw, le_pb, le_mw, le_mb, le_sw, le_sb, eps, z);
    cudaEventRecord(evB, s2);

    // --- deterministic path on main stream ---
    mma_gemm<32, 0, 0, 0><<<dim3(MC / 128, 2, 1), 256>>>(h12 + HIDD, ce_w2, ce_b2, rep,
        MC, RD, HIDD, 2 * HIDD, RD, RD, 1.f, nullptr, nullptr, nullptr, nullptr, nullptr);

    mma_gemm<32, 0, 0, 0><<<dim3(MC / 128, 6, 1), 256>>>(rep, sa_in_w, sa_in_b, qkv,
        MC, 3 * RD, RD, RD, 3 * RD, 3 * RD, 1.f, nullptr, nullptr, nullptr, nullptr, nullptr);

    flash_self_k<<<dim3(NCC / 128, NHD, BB), 256, SELF_SMEM>>>(qkv, attno);

    mma_gemm<32, 0, 0, 0><<<dim3(MC / 128, 2, 1), 256>>>(attno, sa_out_w, sa_out_b, oproj,
        MC, RD, RD, RD, RD, RD, 1.f, nullptr, nullptr, nullptr, nullptr, nullptr);
    ln_k<<<MC / 8, 256>>>(rep, oproj, sa_ln_g, sa_ln_b, rep2);

    // --- cross attention (join qt) ---
    cudaStreamWaitEvent(0, evC, 0);
    flash_cross_k<<<dim3(NTT / 64, 1, BB), 256, CROSS_SMEM>>>(qt, rep2, det);

    // --- join latent path, then decoder ---
    cudaStreamWaitEvent(0, evB, 0);
    mma_gemm<32, 1, 1, 0><<<dim3(MT / 128, 1, 1), 256>>>(det, dec_w1, dec_b1, dh,
        MT, HIDD, DIN, DIN, HIDD, HIDD, 1.f, z, target_x, pred_ctrl, nullptr, nullptr);
    dec2_k<<<MT / 16, 256>>>(dh, dec_w2, dec_b2, out);
}

// round 10
// speedup vs baseline: 7.4929x; 1.0623x over previous
#include <cuda_runtime.h>
#include <cuda_fp16.h>
#include <math.h>

// ---- problem dims ----
#define BB 16
#define NCC 1024
#define NTT 2048
#define GAPD 128
#define CTRLD 8
#define RD 256
#define NHD 4
#define HDD 64
#define HIDD 128
#define LHD 192
#define CIN (CTRLD + GAPD)          // 136
#define DIN (2 * RD + GAPD + CTRLD) // 648

// ---- scratch ----
__device__ float g_h12  [BB * NCC * 2 * HIDD];
__device__ float g_rep  [BB * NCC * RD];
__device__ float g_hle  [BB * NCC * RD];
__device__ float g_part [BB * 32 * RD];
__device__ float g_hmean[BB * RD];
__device__ float g_z    [BB * RD];
__device__ unsigned short g_qkvh [BB * NCC * 3 * RD];
__device__ float g_attno[BB * NCC * RD];
__device__ float g_oproj[BB * NCC * RD];
__device__ unsigned short g_rep2h[BB * NCC * RD];
__device__ unsigned short g_qth  [(size_t)BB * NTT * RD];
__device__ float g_det  [BB * NTT * RD];
__device__ float g_dh   [BB * NTT * HIDD];

// ===================== fp16 mma helpers =====================
__device__ __forceinline__ unsigned h2p(float a, float b) {
    __half2 h = __floats2half2_rn(a, b);
    return *reinterpret_cast<unsigned*>(&h);
}
__device__ __forceinline__ void mma16(float* d, const unsigned* a, const unsigned* b) {
    asm volatile(
        "mma.sync.aligned.m16n8k16.row.col.f32.f16.f16.f32 "
        "{%0,%1,%2,%3},{%4,%5,%6,%7},{%8,%9},{%0,%1,%2,%3};\n"
        : "+f"(d[0]), "+f"(d[1]), "+f"(d[2]), "+f"(d[3])
        : "r"(a[0]), "r"(a[1]), "r"(a[2]), "r"(a[3]), "r"(b[0]), "r"(b[1]));
}
__device__ __forceinline__ float4 ld_guard(const float* src, int gk, int K) {
    if (gk + 4 <= K) return *(const float4*)src;
    float4 v = make_float4(0.f, 0.f, 0.f, 0.f);
    if (gk     < K) v.x = src[0];
    if (gk + 1 < K) v.y = src[1];
    if (gk + 2 < K) v.z = src[2];
    if (gk + 3 < K) v.w = src[3];
    return v;
}
__device__ __forceinline__ unsigned ilo(unsigned a, unsigned b) { return __byte_perm(a, b, 0x5410); }
__device__ __forceinline__ unsigned ihi(unsigned a, unsigned b) { return __byte_perm(a, b, 0x7632); }

// ===================== fp16 GEMM (reg-pipelined), B = [K,N] row-major ====
#define XBM 128
#define XBK 32

template<int WNT, int ACT, int MODE, int BMODE, int OUTH>
__global__ void __launch_bounds__(256) mma_gemm(
    const float* __restrict__ A, const float* __restrict__ B,
    const float* __restrict__ bias, float* __restrict__ C,
    int M, int N, int K, int lda, int ldb, int ldc,
    float alpha,
    const float* __restrict__ zt, const float* __restrict__ txt,
    const float* __restrict__ pct,
    const float* __restrict__ B2, const float* __restrict__ bias2)
{
    constexpr int XBN_ = WNT * 4;
    constexpr int NI = WNT / 8;
    constexpr int AST2 = 20;
    constexpr int BST2 = XBN_ + 8;

    __shared__ unsigned As2[XBM][AST2];
    __shared__ unsigned Bs2[XBK / 2][BST2];

    int tid = threadIdx.x;
    int wid = tid >> 5, lane = tid & 31;
    int g = lane >> 2, t4 = lane & 3;
    int wm = wid & 1, wn = wid >> 1;
    int m0 = blockIdx.x * XBM, n0 = blockIdx.y * XBN_;

    float acc[4][NI][4];
#pragma unroll
    for (int i = 0; i < 4; i++)
#pragma unroll
        for (int j = 0; j < NI; j++)
#pragma unroll
            for (int l = 0; l < 4; l++) acc[i][j][l] = 0.f;

    float4 ra[4], rbE[2], rbO[2];
    constexpr int C4  = XBN_ / 4;
    constexpr int RP2 = 256 / C4;
    constexpr int ITS2 = (XBK / 2) / RP2;

    const int ac = (tid & 7) * 4;
    const int ar = tid >> 3;
    const int bc4 = tid % C4;
    const int brb = tid / C4;

    auto loadA = [&](int k0) {
        int gk = k0 + ac;
#pragma unroll
        for (int p = 0; p < 4; p++) {
            int gm = m0 + p * 32 + ar;
            if (MODE == 1) {
                const float* s;
                if (gk < RD)                 s = A   + (long)gm * RD   + gk;
                else if (gk < 2 * RD)        s = zt  + (long)(gm >> 11) * RD + (gk - RD);
                else if (gk < 2 * RD + GAPD) s = txt + (long)gm * GAPD + (gk - 2 * RD);
                else if (gk < DIN)           s = pct + (long)gm * CTRLD + (gk - 2 * RD - GAPD);
                else                         s = nullptr;
                ra[p] = s ? *(const float4*)s : make_float4(0.f, 0.f, 0.f, 0.f);
            } else if (MODE == 2) {
                const float* s;
                if (gk < CTRLD)    s = zt  + (long)gm * CTRLD + gk;
                else if (gk < CIN) s = txt + (long)gm * GAPD + (gk - CTRLD);
                else               s = nullptr;
                ra[p] = s ? *(const float4*)s : make_float4(0.f, 0.f, 0.f, 0.f);
            } else {
                ra[p] = ld_guard(A + (long)gm * lda + gk, gk, K);
            }
        }
    };
    auto loadB = [&](int k0) {
        int gn = n0 + bc4 * 4;
#pragma unroll
        for (int it = 0; it < ITS2; it++) {
            int kp = k0 + (it * RP2 + brb) * 2;
            if (BMODE == 1) {
                const float* base0 = (gn < HIDD) ? B : B2;
                int gq = (gn < HIDD) ? gn : gn - HIDD;
                rbE[it] = (kp     < K) ? *(const float4*)(base0 + (long)kp * ldb + gq)
                                       : make_float4(0.f, 0.f, 0.f, 0.f);
                rbO[it] = (kp + 1 < K) ? *(const float4*)(base0 + (long)(kp + 1) * ldb + gq)
                                       : make_float4(0.f, 0.f, 0.f, 0.f);
            } else {
                bool okn = (gn + 3 < N);
                rbE[it] = (kp     < K && okn) ? *(const float4*)(B + (long)kp * ldb + gn)
                                              : make_float4(0.f, 0.f, 0.f, 0.f);
                rbO[it] = (kp + 1 < K && okn) ? *(const float4*)(B + (long)(kp + 1) * ldb + gn)
                                              : make_float4(0.f, 0.f, 0.f, 0.f);
            }
        }
    };
    auto stsAB = [&]() {
#pragma unroll
        for (int p = 0; p < 4; p++) {
            uint2 u = make_uint2(h2p(ra[p].x, ra[p].y), h2p(ra[p].z, ra[p].w));
            *(uint2*)&As2[p * 32 + ar][ac >> 1] = u;
        }
#pragma unroll
        for (int it = 0; it < ITS2; it++) {
            uint4 u = make_uint4(h2p(rbE[it].x, rbO[it].x), h2p(rbE[it].y, rbO[it].y),
                                 h2p(rbE[it].z, rbO[it].z), h2p(rbE[it].w, rbO[it].w));
            *(uint4*)&Bs2[it * RP2 + brb][bc4 * 4] = u;
        }
    };

    int kT = (K + XBK - 1) / XBK;
    loadA(0); loadB(0);

    for (int t = 0; t < kT; t++) {
        stsAB();
        __syncthreads();
        if (t + 1 < kT) { loadA((t + 1) * XBK); loadB((t + 1) * XBK); }
#pragma unroll
        for (int ks = 0; ks < 2; ks++) {
            int kb2 = ks * 8;
            unsigned af[4][4], bf[NI][2];
#pragma unroll
            for (int mi = 0; mi < 4; mi++) {
                int ma = wm * 64 + mi * 16 + g;
                af[mi][0] = As2[ma    ][kb2 + t4];
                af[mi][1] = As2[ma + 8][kb2 + t4];
                af[mi][2] = As2[ma    ][kb2 + t4 + 4];
                af[mi][3] = As2[ma + 8][kb2 + t4 + 4];
            }
#pragma unroll
            for (int ni = 0; ni < NI; ni++) {
                int nb = wn * WNT + ni * 8 + g;
                bf[ni][0] = Bs2[kb2 + t4    ][nb];
                bf[ni][1] = Bs2[kb2 + t4 + 4][nb];
            }
#pragma unroll
            for (int mi = 0; mi < 4; mi++)
#pragma unroll
                for (int ni = 0; ni < NI; ni++)
                    mma16(acc[mi][ni], af[mi], bf[ni]);
        }
        __syncthreads();
    }

#pragma unroll
    for (int mi = 0; mi < 4; mi++) {
        int gm = m0 + wm * 64 + mi * 16 + g;
#pragma unroll
        for (int ni = 0; ni < NI; ni++) {
            int gn = n0 + wn * WNT + ni * 8 + t4 * 2;
            if (gn >= N) continue;
            float b0, b1;
            if (BMODE == 1) {
                const float* bp = (gn < HIDD) ? bias : bias2;
                int gq = (gn < HIDD) ? gn : gn - HIDD;
                b0 = bp[gq]; b1 = bp[gq + 1];
            } else {
                b0 = bias ? bias[gn] : 0.f;
                b1 = bias ? bias[gn + 1] : 0.f;
            }
            float v0 = acc[mi][ni][0] * alpha + b0;
            float v1 = acc[mi][ni][1] * alpha + b1;
            float v2 = acc[mi][ni][2] * alpha + b0;
            float v3 = acc[mi][ni][3] * alpha + b1;
            if (ACT == 1) {
                v0 = fmaxf(v0, 0.f); v1 = fmaxf(v1, 0.f);
                v2 = fmaxf(v2, 0.f); v3 = fmaxf(v3, 0.f);
            }
            if (OUTH) {
                unsigned short* Ch = (unsigned short*)C;
                *(unsigned*)&Ch[(long)gm * ldc + gn]       = h2p(v0, v1);
                *(unsigned*)&Ch[(long)(gm + 8) * ldc + gn] = h2p(v2, v3);
            } else {
                *(float2*)&C[(long)gm * ldc + gn]       = make_float2(v0, v1);
                *(float2*)&C[(long)(gm + 8) * ldc + gn] = make_float2(v2, v3);
            }
        }
    }
}

// ===================== flash self-attention (fp16 I/O, 2 CTAs/SM) =====================
#define SELF_SMEM (23040 * 4)

__global__ void __launch_bounds__(256, 2) flash_self_k(
    const unsigned short* __restrict__ qkvh, float* __restrict__ attno)
{
    extern __shared__ unsigned smu[];
    unsigned* Qs = smu;
    unsigned* Ks = smu + 4608;
    unsigned* Vs = smu + 9216;
    unsigned* Ps = smu + 13824;
    float*    red = (float*)(smu + 22528);

    const int b = blockIdx.z, h = blockIdx.y;
    const int m0 = blockIdx.x * 128;
    const unsigned short* base = qkvh + (long)b * NCC * 768;
    const unsigned short* qp = base + h * 64;
    const unsigned short* kp = base + 256 + h * 64;
    const unsigned short* vp = base + 512 + h * 64;

    const int tid = threadIdx.x, wid = tid >> 5, lane = tid & 31;
    const int g = lane >> 2, t4 = lane & 3;
    const int wm = wid & 1, wn = wid >> 1;
    const int c4h = (tid & 15) * 4, r0 = tid >> 4;

    const __half2 sc8 = __floats2half2_rn(0.125f, 0.125f);
#pragma unroll
    for (int p = 0; p < 8; p++) {
        int r = p * 16 + r0;
        uint2 u = *(const uint2*)(qp + (long)(m0 + r) * 768 + c4h);
        __half2 ha = __hmul2(*(__half2*)&u.x, sc8);
        __half2 hb = __hmul2(*(__half2*)&u.y, sc8);
        *(uint2*)&Qs[r * 36 + (c4h >> 1)] = make_uint2(*(unsigned*)&ha, *(unsigned*)&hb);
    }

    float l_run[4][2], acc_o[4][2][4];
#pragma unroll
    for (int mi = 0; mi < 4; mi++)
#pragma unroll
        for (int hf = 0; hf < 2; hf++) l_run[mi][hf] = 0.f;
#pragma unroll
    for (int mi = 0; mi < 4; mi++)
#pragma unroll
        for (int ni = 0; ni < 2; ni++)
#pragma unroll
            for (int c = 0; c < 4; c++) acc_o[mi][ni][c] = 0.f;

    for (int tk = 0; tk < 8; tk++) {
        __syncthreads();
#pragma unroll
        for (int p = 0; p < 8; p++) {
            int r = p * 16 + r0;
            *(uint2*)&Ks[r * 36 + (c4h >> 1)] =
                *(const uint2*)(kp + (long)(tk * 128 + r) * 768 + c4h);
        }
#pragma unroll
        for (int p = 0; p < 4; p++) {
            int q = p * 16 + r0;
            uint2 e = *(const uint2*)(vp + (long)(tk * 128 + 2 * q) * 768 + c4h);
            uint2 o = *(const uint2*)(vp + (long)(tk * 128 + 2 * q + 1) * 768 + c4h);
            *(uint4*)&Vs[q * 72 + c4h] = make_uint4(
                ilo(e.x, o.x), ihi(e.x, o.x), ilo(e.y, o.y), ihi(e.y, o.y));
        }
        __syncthreads();

        float s[4][4][4];
#pragma unroll
        for (int mi = 0; mi < 4; mi++)
#pragma unroll
            for (int ni = 0; ni < 4; ni++)
#pragma unroll
                for (int c = 0; c < 4; c++) s[mi][ni][c] = 0.f;
#pragma unroll
        for (int ks = 0; ks < 4; ks++) {
            int kb2 = ks * 8;
            unsigned af[4][4], bf[4][2];
#pragma unroll
            for (int mi = 0; mi < 4; mi++) {
                int ma = wm * 64 + mi * 16 + g;
                af[mi][0] = Qs[ma * 36 + kb2 + t4];
                af[mi][1] = Qs[(ma + 8) * 36 + kb2 + t4];
                af[mi][2] = Qs[ma * 36 + kb2 + t4 + 4];
                af[mi][3] = Qs[(ma + 8) * 36 + kb2 + t4 + 4];
            }
#pragma unroll
            for (int ni = 0; ni < 4; ni++) {
                int nb = wn * 32 + ni * 8 + g;
                bf[ni][0] = Ks[nb * 36 + kb2 + t4];
                bf[ni][1] = Ks[nb * 36 + kb2 + t4 + 4];
            }
#pragma unroll
            for (int mi = 0; mi < 4; mi++)
#pragma unroll
                for (int ni = 0; ni < 4; ni++)
                    mma16(s[mi][ni], af[mi], bf[ni]);
        }

#pragma unroll
        for (int mi = 0; mi < 4; mi++)
#pragma unroll
            for (int hf = 0; hf < 2; hf++) {
                float ls = 0.f;
#pragma unroll
                for (int ni = 0; ni < 4; ni++) {
                    float p0 = __expf(s[mi][ni][hf * 2]);
                    float p1 = __expf(s[mi][ni][hf * 2 + 1]);
                    s[mi][ni][hf * 2] = p0; s[mi][ni][hf * 2 + 1] = p1;
                    ls += p0 + p1;
                }
                ls += __shfl_xor_sync(0xffffffffu, ls, 1);
                ls += __shfl_xor_sync(0xffffffffu, ls, 2);
                if (t4 == 0) red[wn * 128 + wm * 64 + mi * 16 + hf * 8 + g] = ls;
            }
        __syncthreads();
#pragma unroll
        for (int mi = 0; mi < 4; mi++)
#pragma unroll
            for (int hf = 0; hf < 2; hf++) {
                int r = wm * 64 + mi * 16 + hf * 8 + g;
                l_run[mi][hf] += red[r] + red[128 + r] + red[256 + r] + red[384 + r];
            }
#pragma unroll
        for (int mi = 0; mi < 4; mi++) {
            int r = wm * 64 + mi * 16 + g;
#pragma unroll
            for (int ni = 0; ni < 4; ni++) {
                int c2 = wn * 16 + ni * 4 + t4;
                Ps[r * 68 + c2]       = h2p(s[mi][ni][0], s[mi][ni][1]);
                Ps[(r + 8) * 68 + c2] = h2p(s[mi][ni][2], s[mi][ni][3]);
            }
        }
        __syncthreads();

#pragma unroll
        for (int ks = 0; ks < 8; ks++) {
            int kb2 = ks * 8;
            unsigned af[4][4], bf[2][2];
#pragma unroll
            for (int mi = 0; mi < 4; mi++) {
                int ma = wm * 64 + mi * 16 + g;
                af[mi][0] = Ps[ma * 68 + kb2 + t4];
                af[mi][1] = Ps[(ma + 8) * 68 + kb2 + t4];
                af[mi][2] = Ps[ma * 68 + kb2 + t4 + 4];
                af[mi][3] = Ps[(ma + 8) * 68 + kb2 + t4 + 4];
            }
#pragma unroll
            for (int ni = 0; ni < 2; ni++) {
                int nb = wn * 16 + ni * 8 + g;
                bf[ni][0] = Vs[(kb2 + t4) * 72 + nb];
                bf[ni][1] = Vs[(kb2 + t4 + 4) * 72 + nb];
            }
#pragma unroll
            for (int mi = 0; mi < 4; mi++)
#pragma unroll
                for (int ni = 0; ni < 2; ni++)
                    mma16(acc_o[mi][ni], af[mi], bf[ni]);
        }
    }

#pragma unroll
    for (int mi = 0; mi < 4; mi++) {
        int row = m0 + wm * 64 + mi * 16 + g;
        float inv0 = 1.f / l_run[mi][0], inv1 = 1.f / l_run[mi][1];
#pragma unroll
        for (int ni = 0; ni < 2; ni++) {
            int col = h * 64 + wn * 16 + ni * 8 + t4 * 2;
            long o0 = ((long)b * NCC + row) * 256 + col;
            long o1 = ((long)b * NCC + row + 8) * 256 + col;
            *(float2*)&attno[o0] = make_float2(acc_o[mi][ni][0] * inv0, acc_o[mi][ni][1] * inv0);
            *(float2*)&attno[o1] = make_float2(acc_o[mi][ni][2] * inv1, acc_o[mi][ni][3] * inv1);
        }
    }
}

// ===================== flash cross-attention (fp16 I/O, 2 CTAs/SM) =====================
#define CROSS_SMEM (27904 * 4)

__global__ void __launch_bounds__(256, 2) flash_cross_k(
    const unsigned short* __restrict__ qth, const unsigned short* __restrict__ rep2h,
    float* __restrict__ det)
{
    extern __shared__ unsigned smu[];
    unsigned* Qs  = smu;
    unsigned* KVs = smu + 8448;
    unsigned* Vsc = smu + 16896;
    unsigned* Psc = smu + 25344;
    float*    red = (float*)(smu + 27648);

    const int b = blockIdx.z;
    const int m0 = blockIdx.x * 64;
    const unsigned short* qb  = qth   + (long)b * NTT * 256;
    const unsigned short* kvb = rep2h + (long)b * NCC * 256;

    const int tid = threadIdx.x, wid = tid >> 5, lane = tid & 31;
    const int g = lane >> 2, t4 = lane & 3;
    const int wm = wid & 1, wn = wid >> 1;
    const int c4h = (tid & 63) * 4, r0 = tid >> 6;

    const __half2 sc16 = __floats2half2_rn(0.0625f, 0.0625f);
#pragma unroll
    for (int p = 0; p < 16; p++) {
        int r = p * 4 + r0;
        uint2 u = *(const uint2*)(qb + (long)(m0 + r) * 256 + c4h);
        __half2 ha = __hmul2(*(__half2*)&u.x, sc16);
        __half2 hb = __hmul2(*(__half2*)&u.y, sc16);
        *(uint2*)&Qs[r * 132 + (c4h >> 1)] = make_uint2(*(unsigned*)&ha, *(unsigned*)&hb);
    }

    float l_run[2][2], acc_o[2][8][4];
#pragma unroll
    for (int mi = 0; mi < 2; mi++)
#pragma unroll
        for (int hf = 0; hf < 2; hf++) l_run[mi][hf] = 0.f;
#pragma unroll
    for (int mi = 0; mi < 2; mi++)
#pragma unroll
        for (int ni = 0; ni < 8; ni++)
#pragma unroll
            for (int c = 0; c < 4; c++) acc_o[mi][ni][c] = 0.f;

    for (int tk = 0; tk < 16; tk++) {
        __syncthreads();
#pragma unroll
        for (int p = 0; p < 8; p++) {
            int q = p * 4 + r0;
            uint2 e = *(const uint2*)(kvb + (long)(tk * 64 + 2 * q) * 256 + c4h);
            uint2 o = *(const uint2*)(kvb + (long)(tk * 64 + 2 * q + 1) * 256 + c4h);
            *(uint2*)&KVs[(2 * q) * 132 + (c4h >> 1)]     = e;
            *(uint2*)&KVs[(2 * q + 1) * 132 + (c4h >> 1)] = o;
            *(uint4*)&Vsc[q * 264 + c4h] = make_uint4(
                ilo(e.x, o.x), ihi(e.x, o.x), ilo(e.y, o.y), ihi(e.y, o.y));
        }
        __syncthreads();

        float s[2][2][4];
#pragma unroll
        for (int mi = 0; mi < 2; mi++)
#pragma unroll
            for (int ni = 0; ni < 2; ni++)
#pragma unroll
                for (int c = 0; c < 4; c++) s[mi][ni][c] = 0.f;
#pragma unroll
        for (int ks = 0; ks < 16; ks++) {
            int kb2 = ks * 8;
            unsigned af[2][4], bf[2][2];
#pragma unroll
            for (int mi = 0; mi < 2; mi++) {
                int ma = wm * 32 + mi * 16 + g;
                af[mi][0] = Qs[ma * 132 + kb2 + t4];
                af[mi][1] = Qs[(ma + 8) * 132 + kb2 + t4];
                af[mi][2] = Qs[ma * 132 + kb2 + t4 + 4];
                af[mi][3] = Qs[(ma + 8) * 132 + kb2 + t4 + 4];
            }
#pragma unroll
            for (int ni = 0; ni < 2; ni++) {
                int nb = wn * 16 + ni * 8 + g;
                bf[ni][0] = KVs[nb * 132 + kb2 + t4];
                bf[ni][1] = KVs[nb * 132 + kb2 + t4 + 4];
            }
#pragma unroll
            for (int mi = 0; mi < 2; mi++)
#pragma unroll
                for (int ni = 0; ni < 2; ni++)
                    mma16(s[mi][ni], af[mi], bf[ni]);
        }

#pragma unroll
        for (int mi = 0; mi < 2; mi++)
#pragma unroll
            for (int hf = 0; hf < 2; hf++) {
                float ls = 0.f;
#pragma unroll
                for (int ni = 0; ni < 2; ni++) {
                    float p0 = __expf(s[mi][ni][hf * 2]);
                    float p1 = __expf(s[mi][ni][hf * 2 + 1]);
                    s[mi][ni][hf * 2] = p0; s[mi][ni][hf * 2 + 1] = p1;
                    ls += p0 + p1;
                }
                ls += __shfl_xor_sync(0xffffffffu, ls, 1);
                ls += __shfl_xor_sync(0xffffffffu, ls, 2);
                if (t4 == 0) red[wn * 64 + wm * 32 + mi * 16 + hf * 8 + g] = ls;
            }
        __syncthreads();
#pragma unroll
        for (int mi = 0; mi < 2; mi++)
#pragma unroll
            for (int hf = 0; hf < 2; hf++) {
                int r = wm * 32 + mi * 16 + hf * 8 + g;
                l_run[mi][hf] += red[r] + red[64 + r] + red[128 + r] + red[192 + r];
            }
#pragma unroll
        for (int mi = 0; mi < 2; mi++) {
            int r = wm * 32 + mi * 16 + g;
#pragma unroll
            for (int ni = 0; ni < 2; ni++) {
                int c2 = wn * 8 + ni * 4 + t4;
                Psc[r * 36 + c2]       = h2p(s[mi][ni][0], s[mi][ni][1]);
                Psc[(r + 8) * 36 + c2] = h2p(s[mi][ni][2], s[mi][ni][3]);
            }
        }
        __syncthreads();

#pragma unroll
        for (int ks = 0; ks < 4; ks++) {
            int kb2 = ks * 8;
            unsigned af[2][4], bf[8][2];
#pragma unroll
            for (int mi = 0; mi < 2; mi++) {
                int ma = wm * 32 + mi * 16 + g;
                af[mi][0] = Psc[ma * 36 + kb2 + t4];
                af[mi][1] = Psc[(ma + 8) * 36 + kb2 + t4];
                af[mi][2] = Psc[ma * 36 + kb2 + t4 + 4];
                af[mi][3] = Psc[(ma + 8) * 36 + kb2 + t4 + 4];
            }
#pragma unroll
            for (int ni = 0; ni < 8; ni++) {
                int nb = wn * 64 + ni * 8 + g;
                bf[ni][0] = Vsc[(kb2 + t4) * 264 + nb];
                bf[ni][1] = Vsc[(kb2 + t4 + 4) * 264 + nb];
            }
#pragma unroll
            for (int mi = 0; mi < 2; mi++)
#pragma unroll
                for (int ni = 0; ni < 8; ni++)
                    mma16(acc_o[mi][ni], af[mi], bf[ni]);
        }
    }

#pragma unroll
    for (int mi = 0; mi < 2; mi++) {
        int row = m0 + wm * 32 + mi * 16 + g;
        float inv0 = 1.f / l_run[mi][0], inv1 = 1.f / l_run[mi][1];
#pragma unroll
        for (int ni = 0; ni < 8; ni++) {
            int col = wn * 64 + ni * 8 + t4 * 2;
            long o0 = ((long)b * NTT + row) * 256 + col;
            long o1 = ((long)b * NTT + row + 8) * 256 + col;
            *(float2*)&det[o0] = make_float2(acc_o[mi][ni][0] * inv0, acc_o[mi][ni][1] * inv0);
            *(float2*)&det[o1] = make_float2(acc_o[mi][ni][2] * inv1, acc_o[mi][ni][3] * inv1);
        }
    }
}

// ===================== small kernels =====================

__global__ void mean1_k(const float* __restrict__ h, float* __restrict__ part)
{
    int b = blockIdx.x, ch = blockIdx.y, j = threadIdx.x * 4;
    const float* p = h + (long)b * NCC * RD + (long)ch * 32 * RD + j;
    float4 s = make_float4(0.f, 0.f, 0.f, 0.f);
#pragma unroll 4
    for (int n = 0; n < 32; n++) {
        float4 v = *(const float4*)(p + (long)n * RD);
        s.x += v.x; s.y += v.y; s.z += v.z; s.w += v.w;
    }
    *(float4*)&part[(long)(b * 32 + ch) * RD + j] = s;
}

__global__ void mean2_k(const float* __restrict__ part, float* __restrict__ out)
{
    int b = blockIdx.x, j = threadIdx.x;
    float s = 0.f;
#pragma unroll
    for (int c = 0; c < 32; c++) s += part[(long)(b * 32 + c) * RD + j];
    out[b * RD + j] = s * (1.f / NCC);
}

__global__ void latent_k(const float* __restrict__ hmean,
                         const float* __restrict__ pw, const float* __restrict__ pb,
                         const float* __restrict__ mw, const float* __restrict__ mb,
                         const float* __restrict__ sw, const float* __restrict__ sb,
                         const float* __restrict__ eps, float* __restrict__ z)
{
    __shared__ float h2s[LHD];
    int b = blockIdx.x, tid = threadIdx.x;
    if (tid < LHD) {
        float s = pb[tid];
        const float* hm = hmean + b * RD;
        for (int k = 0; k < RD; k++) s += hm[k] * pw[k * LHD + tid];
        h2s[tid] = s;
    }
    __syncthreads();
    float mu = mb[tid], ls = sb[tid];
    for (int k = 0; k < LHD; k++) {
        mu += h2s[k] * mw[k * RD + tid];
        ls += h2s[k] * sw[k * RD + tid];
    }
    float sig = 0.9f / (1.f + expf(-ls)) + 0.1f;
    z[b * RD + tid] = mu + sig * eps[b * RD + tid];
}

// residual + layernorm -> half output
__global__ void __launch_bounds__(256) ln_k(
    const float* __restrict__ x, const float* __restrict__ y,
    const float* __restrict__ g, const float* __restrict__ b,
    unsigned short* __restrict__ outh)
{
    int w = threadIdx.x >> 5, lane = threadIdx.x & 31;
    long row = (long)blockIdx.x * 8 + w;
    const float4* xr = (const float4*)(x + row * RD);
    const float4* yr = (const float4*)(y + row * RD);
    float4 a0 = xr[lane], a1 = xr[lane + 32];
    float4 c0 = yr[lane], c1 = yr[lane + 32];
    a0.x += c0.x; a0.y += c0.y; a0.z += c0.z; a0.w += c0.w;
    a1.x += c1.x; a1.y += c1.y; a1.z += c1.z; a1.w += c1.w;

    float sum = a0.x + a0.y + a0.z + a0.w + a1.x + a1.y + a1.z + a1.w;
#pragma unroll
    for (int o = 16; o; o >>= 1) sum += __shfl_xor_sync(0xffffffffu, sum, o);
    float mean = sum * (1.f / RD);

    float d0x = a0.x - mean, d0y = a0.y - mean, d0z = a0.z - mean, d0w = a0.w - mean;
    float d1x = a1.x - mean, d1y = a1.y - mean, d1z = a1.z - mean, d1w = a1.w - mean;
    float vs = d0x * d0x + d0y * d0y + d0z * d0z + d0w * d0w
             + d1x * d1x + d1y * d1y + d1z * d1z + d1w * d1w;
#pragma unroll
    for (int o = 16; o; o >>= 1) vs += __shfl_xor_sync(0xffffffffu, vs, o);
    float inv = rsqrtf(vs * (1.f / RD) + 1e-5f);

    float4 g0 = ((const float4*)g)[lane], g1 = ((const float4*)g)[lane + 32];
    float4 b0 = ((const float4*)b)[lane], b1 = ((const float4*)b)[lane + 32];
    uint2 u0 = make_uint2(h2p(d0x * inv * g0.x + b0.x, d0y * inv * g0.y + b0.y),
                          h2p(d0z * inv * g0.z + b0.z, d0w * inv * g0.w + b0.w));
    uint2 u1 = make_uint2(h2p(d1x * inv * g1.x + b1.x, d1y * inv * g1.y + b1.y),
                          h2p(d1z * inv * g1.z + b1.z, d1w * inv * g1.w + b1.w));
    ((uint2*)(outh + row * RD))[lane] = u0;
    ((uint2*)(outh + row * RD))[lane + 32] = u1;
}

// dec2 (K=128, N=16) fused with mu/sigma epilogue
__global__ void __launch_bounds__(256) dec2_k(
    const float* __restrict__ dh, const float* __restrict__ w2,
    const float* __restrict__ b2, float* __restrict__ out)
{
    __shared__ float w[128][17];
    __shared__ float a[16][132];
    int tid = threadIdx.x;
    for (int i = tid; i < 128 * 16; i += 256) { int k = i >> 4, c = i & 15; w[k][c] = w2[i]; }
    long row0 = (long)blockIdx.x * 16;
    for (int i = tid; i < 512; i += 256) {
        int r = i >> 5, c4 = (i & 31) * 4;
        *(float4*)&a[r][c4] = *(const float4*)&dh[(row0 + r) * 128 + c4];
    }
    __syncthreads();
    int r = tid >> 4, c = tid & 15;
    float s = b2[c];
#pragma unroll
    for (int k = 0; k < 128; k++) s += a[r][k] * w[k][c];
    long row = row0 + r;
    const long TOT = (long)BB * NTT * CTRLD;
    if (c < CTRLD) out[row * CTRLD + c] = s;
    else {
        float sp = fmaxf(s, 0.f) + log1pf(expf(-fabsf(s)));
        out[TOT + row * CTRLD + (c - CTRLD)] = 0.9f * sp + 0.1f;
    }
}

// ===================== host side =====================

static void* symv(const void* s) { void* p = nullptr; cudaGetSymbolAddress(&p, s); return p; }

extern "C" void kernel_launch(void* const* d_in, const int* in_sizes, int n_in,
                              void* d_out, int out_size)
{
    const float* context_x = (const float*)d_in[0];
    const float* context_y = (const float*)d_in[1];
    const float* target_x  = (const float*)d_in[2];
    const float* pred_ctrl = (const float*)d_in[3];
    const float* eps       = (const float*)d_in[4];
    const float* ce_w1 = (const float*)d_in[5];  const float* ce_b1 = (const float*)d_in[6];
    const float* ce_w2 = (const float*)d_in[7];  const float* ce_b2 = (const float*)d_in[8];
    const float* sa_in_w = (const float*)d_in[9];  const float* sa_in_b = (const float*)d_in[10];
    const float* sa_out_w = (const float*)d_in[11]; const float* sa_out_b = (const float*)d_in[12];
    const float* sa_ln_g = (const float*)d_in[13];  const float* sa_ln_b = (const float*)d_in[14];
    const float* qp_w = (const float*)d_in[15]; const float* qp_b = (const float*)d_in[16];
    const float* le_w1 = (const float*)d_in[17]; const float* le_b1 = (const float*)d_in[18];
    const float* le_w2 = (const float*)d_in[19]; const float* le_b2 = (const float*)d_in[20];
    const float* le_pw = (const float*)d_in[21]; const float* le_pb = (const float*)d_in[22];
    const float* le_mw = (const float*)d_in[23]; const float* le_mb = (const float*)d_in[24];
    const float* le_sw = (const float*)d_in[25]; const float* le_sb = (const float*)d_in[26];
    const float* dec_w1 = (const float*)d_in[27]; const float* dec_b1 = (const float*)d_in[28];
    const float* dec_w2 = (const float*)d_in[29]; const float* dec_b2 = (const float*)d_in[30];
    float* out = (float*)d_out;

    float* h12   = (float*)symv(g_h12);
    float* rep   = (float*)symv(g_rep);
    float* hle   = (float*)symv(g_hle);
    float* part  = (float*)symv(g_part);
    float* hmean = (float*)symv(g_hmean);
    float* z     = (float*)symv(g_z);
    unsigned short* qkvh  = (unsigned short*)symv(g_qkvh);
    float* attno = (float*)symv(g_attno);
    float* oproj = (float*)symv(g_oproj);
    unsigned short* rep2h = (unsigned short*)symv(g_rep2h);
    unsigned short* qth   = (unsigned short*)symv(g_qth);
    float* det   = (float*)symv(g_det);
    float* dh    = (float*)symv(g_dh);

    const int MC = BB * NCC;   // 16384
    const int MT = BB * NTT;   // 32768

    static cudaStream_t s2 = nullptr;
    static cudaEvent_t ev0 = nullptr, evA = nullptr, evB = nullptr, evC = nullptr;
    if (!s2) {
        cudaStreamCreateWithFlags(&s2, cudaStreamNonBlocking);
        cudaEventCreateWithFlags(&ev0, cudaEventDisableTiming);
        cudaEventCreateWithFlags(&evA, cudaEventDisableTiming);
        cudaEventCreateWithFlags(&evB, cudaEventDisableTiming);
        cudaEventCreateWithFlags(&evC, cudaEventDisableTiming);
    }

    cudaFuncSetAttribute(flash_self_k,  cudaFuncAttributeMaxDynamicSharedMemorySize, SELF_SMEM);
    cudaFuncSetAttribute(flash_cross_k, cudaFuncAttributeMaxDynamicSharedMemorySize, CROSS_SMEM);

    // legal fork: ev0 on capture stream BEFORE s2's first op
    cudaEventRecord(ev0, 0);
    cudaStreamWaitEvent(s2, ev0, 0);

    // qt (half out) on s2
    mma_gemm<32, 0, 0, 0, 1><<<dim3(MT / 128, 2, 1), 256, 0, s2>>>(target_x, qp_w, qp_b, (float*)qth,
        MT, RD, GAPD, GAPD, RD, RD, 1.f, nullptr, nullptr, nullptr, nullptr, nullptr);
    cudaEventRecord(evC, s2);

    // merged MLP1 (le|ce)
    mma_gemm<32, 1, 2, 1, 0><<<dim3(MC / 128, 2, 1), 256>>>(nullptr, le_w1, le_b1, h12,
        MC, 2 * HIDD, CIN, CIN, HIDD, 2 * HIDD, 1.f, context_y, context_x, nullptr,
        ce_w1, ce_b1);

    // fork: latent path on s2
    cudaEventRecord(evA, 0);
    cudaStreamWaitEvent(s2, evA, 0);
    mma_gemm<32, 0, 0, 0, 0><<<dim3(MC / 128, 2, 1), 256, 0, s2>>>(h12, le_w2, le_b2, hle,
        MC, RD, HIDD, 2 * HIDD, RD, RD, 1.f, nullptr, nullptr, nullptr, nullptr, nullptr);
    mean1_k<<<dim3(BB, 32), 64, 0, s2>>>(hle, part);
    mean2_k<<<BB, 256, 0, s2>>>(part, hmean);
    latent_k<<<BB, 256, 0, s2>>>(hmean, le_pw, le_pb, le_mw, le_mb, le_sw, le_sb, eps, z);
    cudaEventRecord(evB, s2);

    // deterministic path
    mma_gemm<32, 0, 0, 0, 0><<<dim3(MC / 128, 2, 1), 256>>>(h12 + HIDD, ce_w2, ce_b2, rep,
        MC, RD, HIDD, 2 * HIDD, RD, RD, 1.f, nullptr, nullptr, nullptr, nullptr, nullptr);

    mma_gemm<32, 0, 0, 0, 1><<<dim3(MC / 128, 6, 1), 256>>>(rep, sa_in_w, sa_in_b, (float*)qkvh,
        MC, 3 * RD, RD, RD, 3 * RD, 3 * RD, 1.f, nullptr, nullptr, nullptr, nullptr, nullptr);

    flash_self_k<<<dim3(NCC / 128, NHD, BB), 256, SELF_SMEM>>>(qkvh, attno);

    mma_gemm<32, 0, 0, 0, 0><<<dim3(MC / 128, 2, 1), 256>>>(attno, sa_out_w, sa_out_b, oproj,
        MC, RD, RD, RD, RD, RD, 1.f, nullptr, nullptr, nullptr, nullptr, nullptr);
    ln_k<<<MC / 8, 256>>>(rep, oproj, sa_ln_g, sa_ln_b, rep2h);

    // cross attention (join qt)
    cudaStreamWaitEvent(0, evC, 0);
    flash_cross_k<<<dim3(NTT / 64, 1, BB), 256, CROSS_SMEM>>>(qth, rep2h, det);

    // join latent path, then decoder
    cudaStreamWaitEvent(0, evB, 0);
    mma_gemm<32, 1, 1, 0, 0><<<dim3(MT / 128, 1, 1), 256>>>(det, dec_w1, dec_b1, dh,
        MT, HIDD, DIN, DIN, HIDD, HIDD, 1.f, z, target_x, pred_ctrl, nullptr, nullptr);
    dec2_k<<<MT / 16, 256>>>(dh, dec_w2, dec_b2, out);
}